// round 2
// baseline (speedup 1.0000x reference)
#include <cuda_runtime.h>
#include <math.h>
#include <stdint.h>

#define BB 128
#define LL 64
#define VV 8192
#define EE 128
#define HH 128
#define RR (BB*LL)     /* 8192 rows */
#define G4 512
#define NSTEPS 10
#define MAXBIN 512

/* ------------------------------ scratch ------------------------------ */
__device__ float d_Wt[VV*EE];        /* W_visit transposed [V][E] */
__device__ float d_v[RR*EE];
__device__ float d_xg[RR*G4];
__device__ float d_h[RR*HH];
__device__ float d_hp[RR*EE];
__device__ float d_z[RR*EE];
__device__ float d_ep[RR*EE];
__device__ float d_tmp[RR*EE];
__device__ float d_gcat[RR*2*EE];
__device__ float d_ff1[RR*EE];
__device__ float d_hsyn[RR*HH];
__device__ float d_bias[G4];
__device__ int   d_len[BB];
__device__ float d_scal[2];          /* [0]=denom, [1]=loss accum */

struct ABCoef { float ab[NSTEPS]; };

__device__ __forceinline__ float sigm(float x) { return 1.f / (1.f + expf(-x)); }

/* ------------------------- W_visit transpose ------------------------- */
__global__ void __launch_bounds__(256)
transpose_kernel(const float* __restrict__ W) {
    __shared__ float t[32][33];
    int j0 = blockIdx.x * 32, e0 = blockIdx.y * 32;
    for (int i = threadIdx.y; i < 32; i += 8)
        t[i][threadIdx.x] = W[(size_t)(e0 + i) * VV + j0 + threadIdx.x];
    __syncthreads();
    for (int i = threadIdx.y; i < 32; i += 8)
        d_Wt[(size_t)(j0 + i) * EE + e0 + threadIdx.x] = t[threadIdx.x][i];
}

/* ------------------- lengths, denom, loss reset ---------------------- */
__global__ void __launch_bounds__(128)
prep_kernel(const float* __restrict__ mask) {
    int b = threadIdx.x;                       /* 128 threads */
    float s = 0.f;
    for (int l = 0; l < LL; ++l) s += mask[b * LL + l];
    int len = (int)(s + 0.5f);
    if (len < 1) len = 1;
    d_len[b] = len;
    __shared__ float red[128];
    red[b] = s;
    __syncthreads();
    for (int o = 64; o > 0; o >>= 1) { if (b < o) red[b] += red[b + o]; __syncthreads(); }
    if (b == 0) {
        float dn = red[0];
        if (dn < 1.f) dn = 1.f;
        d_scal[0] = dn;
        d_scal[1] = 0.f;
    }
}

__global__ void __launch_bounds__(512)
bias_kernel(const float* __restrict__ bih, const float* __restrict__ bhh) {
    int i = threadIdx.x;                       /* 512 threads */
    d_bias[i] = bih[i] + bhh[i];
}

/* --------------------- sparse visit embedding ------------------------ */
__global__ void __launch_bounds__(128)
compute_v_kernel(const float* __restrict__ x,
                 const int* __restrict__ bins,
                 const float* __restrict__ mask,
                 const float* __restrict__ bin_embed) {
    int row = blockIdx.x;
    int tid = threadIdx.x;                     /* 128 threads */
    int l = row & (LL - 1);
    float m = mask[row];
    if (m == 0.f) { d_v[(size_t)row * EE + tid] = 0.f; return; }

    int dlt = 0;
    if (l > 0) {
        dlt = bins[row] - bins[row - 1];
        if (dlt < 0) dlt = 0;
        if (dlt > MAXBIN + 1) dlt = MAXBIN + 1;
    }
    float acc = bin_embed[dlt * EE + tid];

    __shared__ int   s_idx[2048];
    __shared__ float s_val[2048];
    __shared__ int   s_cnt;
    const float* xr = x + (size_t)row * VV;

    for (int c0 = 0; c0 < VV; c0 += 2048) {
        if (tid == 0) s_cnt = 0;
        __syncthreads();
#pragma unroll
        for (int i = 0; i < 16; ++i) {
            int j = c0 + i * EE + tid;
            float xv = xr[j];
            if (xv != 0.f) {
                int p = atomicAdd(&s_cnt, 1);
                s_idx[p] = j;
                s_val[p] = xv;
            }
        }
        __syncthreads();
        int n = s_cnt;
        for (int p = 0; p < n; ++p)
            acc += s_val[p] * d_Wt[(size_t)s_idx[p] * EE + tid];
        __syncthreads();
    }
    d_v[(size_t)row * EE + tid] = acc * m;
}

/* ------------------------ generic tiled GEMM -------------------------
   C[M,N] = A[M,K] * W[N,K]^T (+bias) (+relu).  M%64==0, N%64==0, K%32==0 */
__global__ void __launch_bounds__(256)
gemm_kernel(const float* __restrict__ A, const float* __restrict__ W,
            const float* __restrict__ bias, float* __restrict__ C,
            int M, int N, int K, int relu, int has_bias) {
    __shared__ float As[64][33];
    __shared__ float Bs[64][33];
    int bm = blockIdx.x * 64, bn = blockIdx.y * 64;
    int tid = threadIdx.x;                     /* 256 threads */
    int tx = tid & 15, ty = tid >> 4;
    float acc[4][4] = {};

    for (int k0 = 0; k0 < K; k0 += 32) {
#pragma unroll
        for (int i = 0; i < 8; ++i) {
            int idx = tid + i * 256;
            int mm = idx >> 5, kk = idx & 31;
            As[mm][kk] = A[(size_t)(bm + mm) * K + k0 + kk];
            Bs[mm][kk] = W[(size_t)(bn + mm) * K + k0 + kk];
        }
        __syncthreads();
#pragma unroll
        for (int kk = 0; kk < 32; ++kk) {
            float a[4], b[4];
#pragma unroll
            for (int i = 0; i < 4; ++i) a[i] = As[ty * 4 + i][kk];
#pragma unroll
            for (int j = 0; j < 4; ++j) b[j] = Bs[tx * 4 + j][kk];
#pragma unroll
            for (int i = 0; i < 4; ++i)
#pragma unroll
                for (int j = 0; j < 4; ++j)
                    acc[i][j] += a[i] * b[j];
        }
        __syncthreads();
    }
#pragma unroll
    for (int i = 0; i < 4; ++i)
#pragma unroll
        for (int j = 0; j < 4; ++j) {
            int mm = bm + ty * 4 + i, nn = bn + tx * 4 + j;
            float vv = acc[i][j];
            if (has_bias) vv += bias[nn];
            if (relu && vv < 0.f) vv = 0.f;
            C[(size_t)mm * N + nn] = vv;
        }
}

/* ------------------------------ LSTM --------------------------------- */
__global__ void __launch_bounds__(512)
lstm_kernel(const float* __restrict__ xg, const float* __restrict__ Whh,
            const float* __restrict__ mask, float* __restrict__ hout) {
    int j = threadIdx.x;                       /* 512 threads = 512 gates */
    int b0 = blockIdx.x * 2;                   /* 2 batches / block */
    __shared__ __align__(16) float h_sh[2][HH];
    __shared__ float c_sh[2][HH];
    __shared__ float g_sh[2][G4];
    if (j < 128) {
        h_sh[0][j] = 0.f; h_sh[1][j] = 0.f;
        c_sh[0][j] = 0.f; c_sh[1][j] = 0.f;
    }
    __syncthreads();
    const float4* wrow = reinterpret_cast<const float4*>(Whh + (size_t)j * HH);

    for (int l = 0; l < LL; ++l) {
        float g0 = xg[((size_t)b0 * LL + l) * G4 + j];
        float g1 = xg[((size_t)(b0 + 1) * LL + l) * G4 + j];
        const float4* h0 = reinterpret_cast<const float4*>(h_sh[0]);
        const float4* h1 = reinterpret_cast<const float4*>(h_sh[1]);
#pragma unroll 8
        for (int e = 0; e < 32; ++e) {
            float4 wv = wrow[e];
            float4 a = h0[e];
            float4 b = h1[e];
            g0 += wv.x * a.x + wv.y * a.y + wv.z * a.z + wv.w * a.w;
            g1 += wv.x * b.x + wv.y * b.y + wv.z * b.z + wv.w * b.w;
        }
        g_sh[0][j] = g0;
        g_sh[1][j] = g1;
        __syncthreads();
        if (j < 256) {
            int bb = j >> 7, idx = j & 127;
            float gi = g_sh[bb][idx];
            float gf = g_sh[bb][128 + idx];
            float gg = g_sh[bb][256 + idx];
            float go = g_sh[bb][384 + idx];
            float c = sigm(gf) * c_sh[bb][idx] + sigm(gi) * tanhf(gg);
            float h = sigm(go) * tanhf(c);
            c_sh[bb][idx] = c;
            h_sh[bb][idx] = h;
            int row = (b0 + bb) * LL + l;
            hout[(size_t)row * HH + idx] = h * mask[row];
        }
        __syncthreads();
    }
}

/* ------------------------------ logits ------------------------------- */
__global__ void __launch_bounds__(128)
logits_kernel(const float* __restrict__ h, const float* __restrict__ Wcls,
              const float* __restrict__ bcls, float* __restrict__ out) {
    int b = blockIdx.x, tid = threadIdx.x;     /* 128 threads */
    int l = d_len[b] - 1;
    float p = h[((size_t)b * LL + l) * HH + tid] * Wcls[tid];
    __shared__ float red[128];
    red[tid] = p;
    __syncthreads();
    for (int o = 64; o > 0; o >>= 1) { if (tid < o) red[tid] += red[tid + o]; __syncthreads(); }
    if (tid == 0) out[b] = red[0] + bcls[0];
}

/* --------------------------- shift h by 1 ---------------------------- */
__global__ void __launch_bounds__(128)
shift_kernel() {
    int row = blockIdx.x, tid = threadIdx.x;
    int l = row & (LL - 1);
    d_tmp[(size_t)row * EE + tid] = (l == 0) ? 0.f : d_h[(size_t)(row - 1) * EE + tid];
}

/* ------------------------------- z_t --------------------------------- */
__global__ void __launch_bounds__(128)
zt_kernel(const float* __restrict__ eps, const float* __restrict__ mask,
          const int* __restrict__ tdiff, ABCoef cf) {
    int row = blockIdx.x, tid = threadIdx.x;
    size_t idx = (size_t)row * EE + tid;
    float m = mask[row];
    if (m == 0.f) { d_z[idx] = 0.f; return; }
    int t = tdiff[row / LL];
    float ab = cf.ab[t - 1];
    d_z[idx] = sqrtf(ab) * d_v[idx] + sqrtf(1.f - ab) * eps[idx];
}

/* --------------------------- fuse gate ------------------------------- */
__global__ void __launch_bounds__(128)
fuse_gate_kernel(const float* __restrict__ Wf, const float* __restrict__ bf,
                 const float* __restrict__ temb, const int* __restrict__ tdiff,
                 const float* __restrict__ mask, int kk) {
    int row = blockIdx.x, tid = threadIdx.x;   /* 128 threads */
    float m = mask[row];
    int t = (kk == 0) ? ((m > 0.f) ? tdiff[row / LL] : 1)
                      : ((m > 0.f) ? kk : 1);
    float zv = d_z[(size_t)row * EE + tid];
    float hv = d_hp[(size_t)row * EE + tid];
    float p0 = zv * Wf[tid] + hv * Wf[128 + tid];
    float p1 = zv * Wf[256 + tid] + hv * Wf[384 + tid];
    __shared__ float r0[128], r1[128];
    r0[tid] = p0; r1[tid] = p1;
    __syncthreads();
    for (int o = 64; o > 0; o >>= 1) {
        if (tid < o) { r0[tid] += r0[tid + o]; r1[tid] += r1[tid + o]; }
        __syncthreads();
    }
    float s0 = r0[0] + bf[0], s1 = r1[0] + bf[1];
    float a0 = 1.f / (1.f + expf(s1 - s0));
    d_gcat[(size_t)row * 256 + tid]       = a0 * zv + (1.f - a0) * hv;
    d_gcat[(size_t)row * 256 + 128 + tid] = temb[t * EE + tid];
}

/* ------------------------------ loss --------------------------------- */
__global__ void __launch_bounds__(256)
loss_kernel(const float* __restrict__ eps, const float* __restrict__ mask) {
    int idx = blockIdx.x * blockDim.x + threadIdx.x;   /* RR*EE exact */
    int row = idx >> 7;
    float m = mask[row];
    float dlt = d_ep[idx] - eps[idx];
    float val = dlt * dlt * m;
    __shared__ float red[256];
    red[threadIdx.x] = val;
    __syncthreads();
    for (int o = 128; o > 0; o >>= 1) {
        if (threadIdx.x < o) red[threadIdx.x] += red[threadIdx.x + o];
        __syncthreads();
    }
    if (threadIdx.x == 0) atomicAdd(&d_scal[1], red[0]);
}

/* ------------------------- sampling update --------------------------- */
__global__ void __launch_bounds__(256)
update_kernel(const float* __restrict__ noise, const float* __restrict__ mask,
              float c1, float inva, float sb, int addnoise) {
    int idx = blockIdx.x * blockDim.x + threadIdx.x;
    int row = idx >> 7;
    float m = mask[row];
    float mean = (d_z[idx] - c1 * d_ep[idx]) * inva;
    float z = addnoise ? (mean + sb * noise[idx]) : mean;
    d_z[idx] = z * m;
}

__global__ void __launch_bounds__(1)
final_kernel(float* __restrict__ out) {
    out[256] = d_scal[1] / d_scal[0];
}

/* ============================== host ================================= */
extern "C" void kernel_launch(void* const* d_in, const int* in_sizes, int n_in,
                              void* d_out, int out_size) {
    const float* padded_x   = (const float*)d_in[0];
    const float* visit_mask = (const float*)d_in[1];
    const int*   padded_bins= (const int*)  d_in[2];
    const int*   t_diff     = (const int*)  d_in[3];
    const float* eps        = (const float*)d_in[4];
    const float* z0         = (const float*)d_in[5];
    const float* noise      = (const float*)d_in[6];
    const float* W_visit    = (const float*)d_in[7];
    const float* bin_embed  = (const float*)d_in[8];
    const float* W_ih       = (const float*)d_in[9];
    const float* W_hh       = (const float*)d_in[10];
    const float* b_ih       = (const float*)d_in[11];
    const float* b_hh       = (const float*)d_in[12];
    const float* W_cls      = (const float*)d_in[13];
    const float* b_cls      = (const float*)d_in[14];
    const float* W_proj     = (const float*)d_in[15];
    const float* time_embed = (const float*)d_in[16];
    const float* W_fuse     = (const float*)d_in[17];
    const float* b_fuse     = (const float*)d_in[18];
    const float* W_e1       = (const float*)d_in[19];
    const float* b_e1       = (const float*)d_in[20];
    const float* W_e2       = (const float*)d_in[21];
    const float* b_e2       = (const float*)d_in[22];
    float* out = (float*)d_out;
    (void)in_sizes; (void)n_in; (void)out_size;

    float *v, *xg, *h, *hp, *z, *ep, *tmp, *gcat, *ff1, *hsyn, *bias;
    cudaGetSymbolAddress((void**)&v,    d_v);
    cudaGetSymbolAddress((void**)&xg,   d_xg);
    cudaGetSymbolAddress((void**)&h,    d_h);
    cudaGetSymbolAddress((void**)&hp,   d_hp);
    cudaGetSymbolAddress((void**)&z,    d_z);
    cudaGetSymbolAddress((void**)&ep,   d_ep);
    cudaGetSymbolAddress((void**)&tmp,  d_tmp);
    cudaGetSymbolAddress((void**)&gcat, d_gcat);
    cudaGetSymbolAddress((void**)&ff1,  d_ff1);
    cudaGetSymbolAddress((void**)&hsyn, d_hsyn);
    cudaGetSymbolAddress((void**)&bias, d_bias);

    /* diffusion schedule (host, fp64) */
    double betas[NSTEPS], alphas[NSTEPS], abars[NSTEPS];
    double prod = 1.0;
    for (int i = 0; i < NSTEPS; ++i) {
        betas[i] = 1e-4 + (double)i * (2e-2 - 1e-4) / (double)(NSTEPS - 1);
        alphas[i] = 1.0 - betas[i];
        prod *= alphas[i];
        abars[i] = prod;
    }
    ABCoef cf;
    for (int i = 0; i < NSTEPS; ++i) cf.ab[i] = (float)abars[i];

    /* ---- pipeline ---- */
    transpose_kernel<<<dim3(VV / 32, EE / 32), dim3(32, 8)>>>(W_visit);
    prep_kernel<<<1, 128>>>(visit_mask);
    bias_kernel<<<1, 512>>>(b_ih, b_hh);
    compute_v_kernel<<<RR, 128>>>(padded_x, padded_bins, visit_mask, bin_embed);

    /* encoder LSTM on real data */
    gemm_kernel<<<dim3(RR / 64, G4 / 64), 256>>>(v, W_ih, bias, xg, RR, G4, EE, 0, 1);
    lstm_kernel<<<BB / 2, 512>>>(xg, W_hh, visit_mask, h);
    logits_kernel<<<BB, 128>>>(h, W_cls, b_cls, out);            /* out[0..127] */

    /* hp = shift(h) @ W_proj^T */
    shift_kernel<<<RR, 128>>>();
    gemm_kernel<<<dim3(RR / 64, EE / 64), 256>>>(tmp, W_proj, (const float*)0, hp, RR, EE, HH, 0, 0);

    /* diffusion loss path */
    zt_kernel<<<RR, 128>>>(eps, visit_mask, t_diff, cf);
    fuse_gate_kernel<<<RR, 128>>>(W_fuse, b_fuse, time_embed, t_diff, visit_mask, 0);
    gemm_kernel<<<dim3(RR / 64, EE / 64), 256>>>(gcat, W_e1, b_e1, ff1, RR, EE, 2 * EE, 1, 1);
    gemm_kernel<<<dim3(RR / 64, EE / 64), 256>>>(ff1, W_e2, b_e2, ep, RR, EE, EE, 0, 1);
    loss_kernel<<<RR * EE / 256, 256>>>(eps, visit_mask);

    /* reverse diffusion sampling */
    cudaMemcpyAsync(z, z0, (size_t)RR * EE * sizeof(float), cudaMemcpyDeviceToDevice);
    for (int kk = NSTEPS; kk >= 1; --kk) {
        fuse_gate_kernel<<<RR, 128>>>(W_fuse, b_fuse, time_embed, t_diff, visit_mask, kk);
        gemm_kernel<<<dim3(RR / 64, EE / 64), 256>>>(gcat, W_e1, b_e1, ff1, RR, EE, 2 * EE, 1, 1);
        gemm_kernel<<<dim3(RR / 64, EE / 64), 256>>>(ff1, W_e2, b_e2, ep, RR, EE, EE, 0, 1);
        double beta = betas[kk - 1];
        float c1   = (float)(beta / sqrt(1.0 - abars[kk - 1]));
        float inva = (float)(1.0 / sqrt(alphas[kk - 1]));
        float sb   = (float)sqrt(beta);
        update_kernel<<<RR * EE / 256, 256>>>(noise + (size_t)(NSTEPS - kk) * RR * EE,
                                              visit_mask, c1, inva, sb, (kk > 1) ? 1 : 0);
    }

    /* encoder LSTM on synthetic data */
    gemm_kernel<<<dim3(RR / 64, G4 / 64), 256>>>(z, W_ih, bias, xg, RR, G4, EE, 0, 1);
    lstm_kernel<<<BB / 2, 512>>>(xg, W_hh, visit_mask, hsyn);
    logits_kernel<<<BB, 128>>>(hsyn, W_cls, b_cls, out + 128);   /* out[128..255] */

    final_kernel<<<1, 1>>>(out);                                 /* out[256] */
}

// round 3
// speedup vs baseline: 1.4641x; 1.4641x over previous
#include <cuda_runtime.h>
#include <math.h>
#include <stdint.h>

#define BB 128
#define LL 64
#define VV 8192
#define EE 128
#define HH 128
#define RR (BB*LL)     /* 8192 rows */
#define G4 512
#define NSTEPS 10
#define MAXBIN 512

typedef unsigned long long ull;

/* ------------------------------ scratch ------------------------------ */
__device__ float d_Wt[VV*EE];          /* W_visit transposed [V][E] */
__device__ float d_Wq[G4*HH];          /* W_hh packed: [e2][j] float2 */
__device__ float d_v[RR*EE];
__device__ float d_xg[RR*G4];
__device__ float d_h[RR*HH];
__device__ float d_hp[RR*EE];
__device__ float d_z[RR*EE];
__device__ float d_ep[RR*EE];
__device__ float d_g[RR*EE];
__device__ float d_ff1[RR*EE];
__device__ float d_hsyn[RR*HH];
__device__ float d_bias[G4];
__device__ float d_TT[(NSTEPS+1)*EE];  /* temb@W_e1b^T + b_e1 per t */
__device__ int   d_trow[RR];
__device__ int   d_len[BB];
__device__ float d_scal[2];            /* [0]=denom, [1]=loss accum */

struct ABCoef { float ab[NSTEPS]; };

__device__ __forceinline__ float sigm(float x) { return 1.f / (1.f + expf(-x)); }
__device__ __forceinline__ void fma2(ull& c, ull a, ull b) {
    asm("fma.rn.f32x2 %0, %1, %2, %0;" : "+l"(c) : "l"(a), "l"(b));
}
union F2U { ull u; float2 f; };

/* ------------------------- W_visit transpose ------------------------- */
__global__ void __launch_bounds__(256)
transpose_kernel(const float* __restrict__ W) {
    __shared__ float t[32][33];
    int j0 = blockIdx.x * 32, e0 = blockIdx.y * 32;
    for (int i = threadIdx.y; i < 32; i += 8)
        t[i][threadIdx.x] = W[(size_t)(e0 + i) * VV + j0 + threadIdx.x];
    __syncthreads();
    for (int i = threadIdx.y; i < 32; i += 8)
        d_Wt[(size_t)(j0 + i) * EE + e0 + threadIdx.x] = t[threadIdx.x][i];
}

/* --------------------- W_hh pack: [e2][j] float2 --------------------- */
__global__ void __launch_bounds__(256)
wqprep_kernel(const float* __restrict__ Whh) {
    int idx = blockIdx.x * 256 + threadIdx.x;   /* 64*512 = 32768 */
    if (idx < 64 * G4) {
        int e2 = idx >> 9, j = idx & 511;
        d_Wq[(e2 * G4 + j) * 2 + 0] = Whh[(size_t)j * HH + e2 * 2 + 0];
        d_Wq[(e2 * G4 + j) * 2 + 1] = Whh[(size_t)j * HH + e2 * 2 + 1];
    }
}

/* ------------------ bias sum + TT table precompute ------------------- */
__global__ void __launch_bounds__(512)
biastt_kernel(const float* __restrict__ bih, const float* __restrict__ bhh,
              const float* __restrict__ temb, const float* __restrict__ We1,
              const float* __restrict__ be1) {
    int j = threadIdx.x;
    d_bias[j] = bih[j] + bhh[j];
    if (j < EE) {
        for (int t = 0; t <= NSTEPS; ++t) {
            float s = be1[j];
            for (int k = 0; k < EE; ++k)
                s += temb[t * EE + k] * We1[(size_t)j * (2 * EE) + EE + k];
            d_TT[t * EE + j] = s;
        }
    }
}

/* ------------------- lengths, denom, loss reset ---------------------- */
__global__ void __launch_bounds__(128)
prep_kernel(const float* __restrict__ mask) {
    int b = threadIdx.x;
    float s = 0.f;
    for (int l = 0; l < LL; ++l) s += mask[b * LL + l];
    int len = (int)(s + 0.5f);
    if (len < 1) len = 1;
    d_len[b] = len;
    __shared__ float red[128];
    red[b] = s;
    __syncthreads();
    for (int o = 64; o > 0; o >>= 1) { if (b < o) red[b] += red[b + o]; __syncthreads(); }
    if (b == 0) {
        float dn = red[0];
        if (dn < 1.f) dn = 1.f;
        d_scal[0] = dn;
        d_scal[1] = 0.f;
    }
}

/* --------------------- sparse visit embedding ------------------------ */
__global__ void __launch_bounds__(128)
compute_v_kernel(const float* __restrict__ x,
                 const int* __restrict__ bins,
                 const float* __restrict__ mask,
                 const float* __restrict__ bin_embed) {
    int row = blockIdx.x;
    int tid = threadIdx.x;
    int l = row & (LL - 1);
    float m = mask[row];
    if (m == 0.f) { d_v[(size_t)row * EE + tid] = 0.f; return; }

    int dlt = 0;
    if (l > 0) {
        dlt = bins[row] - bins[row - 1];
        if (dlt < 0) dlt = 0;
        if (dlt > MAXBIN + 1) dlt = MAXBIN + 1;
    }
    float acc = bin_embed[dlt * EE + tid];

    __shared__ int   s_idx[2048];
    __shared__ float s_val[2048];
    __shared__ int   s_cnt;
    const float4* xr4 = reinterpret_cast<const float4*>(x + (size_t)row * VV);

    for (int c0 = 0; c0 < VV; c0 += 2048) {
        if (tid == 0) s_cnt = 0;
        __syncthreads();
#pragma unroll
        for (int i = 0; i < 4; ++i) {
            int j4 = (c0 >> 2) + i * 128 + tid;
            float4 xv = xr4[j4];
            if (xv.x != 0.f) { int p = atomicAdd(&s_cnt, 1); s_idx[p] = 4*j4+0; s_val[p] = xv.x; }
            if (xv.y != 0.f) { int p = atomicAdd(&s_cnt, 1); s_idx[p] = 4*j4+1; s_val[p] = xv.y; }
            if (xv.z != 0.f) { int p = atomicAdd(&s_cnt, 1); s_idx[p] = 4*j4+2; s_val[p] = xv.z; }
            if (xv.w != 0.f) { int p = atomicAdd(&s_cnt, 1); s_idx[p] = 4*j4+3; s_val[p] = xv.w; }
        }
        __syncthreads();
        int n = s_cnt;
        for (int p = 0; p < n; ++p)
            acc += s_val[p] * d_Wt[(size_t)s_idx[p] * EE + tid];
        __syncthreads();
    }
    d_v[(size_t)row * EE + tid] = acc * m;
}

/* ------------------------ f32x2 tiled GEMM ---------------------------
   C[M,N] = A[M,K] * W[N,K(ldb)]^T; BM=BN=64, BK=16, 256 threads, 4x4/thr.
   flags: 1=bias, 2=relu, 4=shiftA(by one row within LL-batch), 8=loss, 16=rowbias(TT) */
__global__ void __launch_bounds__(256)
gemm_kernel(const float* __restrict__ A, const float* __restrict__ W,
            const float* __restrict__ bias, float* __restrict__ C,
            int M, int N, int K, int ldb, int flags,
            const float* __restrict__ eps, const float* __restrict__ mask)
{
    __shared__ float As[64 * 18];
    __shared__ float Bs[64 * 18];
    int tid = threadIdx.x;
    int bm = blockIdx.x * 64, bn = blockIdx.y * 64;
    int tx = tid & 15, ty = tid >> 4;
    int lrow = tid >> 2, lseg = tid & 3;

    ull acc[4][4];
#pragma unroll
    for (int i = 0; i < 4; ++i)
#pragma unroll
        for (int j = 0; j < 4; ++j) acc[i][j] = 0ull;

    /* prefetch first tile */
    float4 pa, pb;
    {
        int r = bm + lrow;
        if (flags & 4) {
            if ((r & (LL - 1)) == 0) pa = make_float4(0.f, 0.f, 0.f, 0.f);
            else pa = *(const float4*)&A[(size_t)(r - 1) * K + lseg * 4];
        } else {
            pa = *(const float4*)&A[(size_t)r * K + lseg * 4];
        }
        pb = *(const float4*)&W[(size_t)(bn + lrow) * ldb + lseg * 4];
    }

    for (int kt = 0; kt < K; kt += 16) {
        float* as = &As[lrow * 18 + lseg * 4];
        as[0] = pa.x; as[1] = pa.y; as[2] = pa.z; as[3] = pa.w;
        float* bs = &Bs[lrow * 18 + lseg * 4];
        bs[0] = pb.x; bs[1] = pb.y; bs[2] = pb.z; bs[3] = pb.w;
        __syncthreads();

        if (kt + 16 < K) {
            int k0 = kt + 16 + lseg * 4;
            int r = bm + lrow;
            if (flags & 4) {
                if ((r & (LL - 1)) == 0) pa = make_float4(0.f, 0.f, 0.f, 0.f);
                else pa = *(const float4*)&A[(size_t)(r - 1) * K + k0];
            } else {
                pa = *(const float4*)&A[(size_t)r * K + k0];
            }
            pb = *(const float4*)&W[(size_t)(bn + lrow) * ldb + k0];
        }

#pragma unroll
        for (int k2 = 0; k2 < 8; ++k2) {
            ull a2[4], b2[4];
#pragma unroll
            for (int i = 0; i < 4; ++i)
                a2[i] = *(const ull*)&As[(ty * 4 + i) * 18 + k2 * 2];
#pragma unroll
            for (int j = 0; j < 4; ++j)
                b2[j] = *(const ull*)&Bs[(tx * 4 + j) * 18 + k2 * 2];
#pragma unroll
            for (int i = 0; i < 4; ++i)
#pragma unroll
                for (int j = 0; j < 4; ++j)
                    fma2(acc[i][j], a2[i], b2[j]);
        }
        __syncthreads();
    }

    float mrow[4];
    int trows[4];
    if (flags & 8) {
#pragma unroll
        for (int i = 0; i < 4; ++i) mrow[i] = mask[bm + ty * 4 + i];
    }
    if (flags & 16) {
#pragma unroll
        for (int i = 0; i < 4; ++i) trows[i] = d_trow[bm + ty * 4 + i];
    }
    float lsum = 0.f;
#pragma unroll
    for (int i = 0; i < 4; ++i) {
        int mm = bm + ty * 4 + i;
        float cv[4];
#pragma unroll
        for (int j = 0; j < 4; ++j) {
            F2U u; u.u = acc[i][j];
            float vv = u.f.x + u.f.y;
            int nn = bn + tx * 4 + j;
            if (flags & 1)  vv += bias[nn];
            if (flags & 16) vv += d_TT[trows[i] * EE + nn];
            if (flags & 2)  vv = fmaxf(vv, 0.f);
            if (flags & 8) {
                float d = vv - eps[(size_t)mm * N + nn];
                lsum += d * d * mrow[i];
            }
            cv[j] = vv;
        }
        *(float4*)&C[(size_t)mm * N + bn + tx * 4] = make_float4(cv[0], cv[1], cv[2], cv[3]);
    }
    if (flags & 8) {
#pragma unroll
        for (int o = 16; o > 0; o >>= 1) lsum += __shfl_xor_sync(0xffffffffu, lsum, o);
        __shared__ float lred[8];
        int wid = tid >> 5, lane = tid & 31;
        if (lane == 0) lred[wid] = lsum;
        __syncthreads();
        if (tid == 0) {
            float s = 0.f;
            for (int w2 = 0; w2 < 8; ++w2) s += lred[w2];
            atomicAdd(&d_scal[1], s);
        }
    }
}

/* ------------------------------ LSTM (4 batches/block) --------------- */
__global__ void __launch_bounds__(512)
lstm_kernel(const float* __restrict__ xg, const float* __restrict__ mask,
            float* __restrict__ hout) {
    int j = threadIdx.x;                       /* 512 gates */
    int b0 = blockIdx.x * 4;                   /* 32 blocks */
    __shared__ __align__(16) float h_sh[4][HH];
    __shared__ float c_sh[4][HH];
    __shared__ float g_sh[4][G4];
    {
        int bb = j >> 7, ii = j & 127;
        h_sh[bb][ii] = 0.f; c_sh[bb][ii] = 0.f;
    }
    __syncthreads();
    const ull* wq = (const ull*)d_Wq;          /* [e2*512 + j] */

    for (int l = 0; l < LL; ++l) {
        ull g2[4] = {0ull, 0ull, 0ull, 0ull};
#pragma unroll 8
        for (int e2 = 0; e2 < 64; ++e2) {
            ull w2 = wq[e2 * G4 + j];
            fma2(g2[0], w2, *(const ull*)&h_sh[0][e2 * 2]);
            fma2(g2[1], w2, *(const ull*)&h_sh[1][e2 * 2]);
            fma2(g2[2], w2, *(const ull*)&h_sh[2][e2 * 2]);
            fma2(g2[3], w2, *(const ull*)&h_sh[3][e2 * 2]);
        }
#pragma unroll
        for (int bb = 0; bb < 4; ++bb) {
            F2U u; u.u = g2[bb];
            g_sh[bb][j] = u.f.x + u.f.y + xg[((size_t)(b0 + bb) * LL + l) * G4 + j];
        }
        __syncthreads();
        {
            int bb = j >> 7, idx = j & 127;
            float gi = g_sh[bb][idx];
            float gf = g_sh[bb][128 + idx];
            float gg = g_sh[bb][256 + idx];
            float go = g_sh[bb][384 + idx];
            float c = sigm(gf) * c_sh[bb][idx] + sigm(gi) * tanhf(gg);
            float h = sigm(go) * tanhf(c);
            c_sh[bb][idx] = c;
            h_sh[bb][idx] = h;
            int row = (b0 + bb) * LL + l;
            hout[(size_t)row * HH + idx] = h * mask[row];
        }
        __syncthreads();
    }
}

/* ------------------------------ logits ------------------------------- */
__global__ void __launch_bounds__(128)
logits_kernel(const float* __restrict__ h, const float* __restrict__ Wcls,
              const float* __restrict__ bcls, float* __restrict__ out) {
    int b = blockIdx.x, tid = threadIdx.x;
    int l = d_len[b] - 1;
    float p = h[((size_t)b * LL + l) * HH + tid] * Wcls[tid];
    __shared__ float red[128];
    red[tid] = p;
    __syncthreads();
    for (int o = 64; o > 0; o >>= 1) { if (tid < o) red[tid] += red[tid + o]; __syncthreads(); }
    if (tid == 0) out[b] = red[0] + bcls[0];
}

/* ------------------ zt + fuse gate (loss path) ----------------------- */
__global__ void __launch_bounds__(256)
ztgate_kernel(const float* __restrict__ eps, const float* __restrict__ mask,
              const int* __restrict__ tdiff, const float* __restrict__ Wf,
              const float* __restrict__ bf, ABCoef cf) {
    int w = threadIdx.x >> 5, lane = threadIdx.x & 31;
    int row = blockIdx.x * 8 + w;
    float m = mask[row];
    int t = (m > 0.f) ? tdiff[row >> 6] : 1;
    size_t base = (size_t)row * EE + lane * 4;
    float ab = cf.ab[t - 1];
    float sa = sqrtf(ab) * m, sb = sqrtf(1.f - ab) * m;
    float4 vv = *(const float4*)&d_v[base];
    float4 ee = *(const float4*)&eps[base];
    float4 z;
    z.x = sa * vv.x + sb * ee.x;
    z.y = sa * vv.y + sb * ee.y;
    z.z = sa * vv.z + sb * ee.z;
    z.w = sa * vv.w + sb * ee.w;
    float4 hp = *(const float4*)&d_hp[base];
    float4 w0 = *(const float4*)&Wf[lane * 4];
    float4 w1 = *(const float4*)&Wf[128 + lane * 4];
    float4 w2 = *(const float4*)&Wf[256 + lane * 4];
    float4 w3 = *(const float4*)&Wf[384 + lane * 4];
    float p0 = z.x*w0.x + z.y*w0.y + z.z*w0.z + z.w*w0.w
             + hp.x*w1.x + hp.y*w1.y + hp.z*w1.z + hp.w*w1.w;
    float p1 = z.x*w2.x + z.y*w2.y + z.z*w2.z + z.w*w2.w
             + hp.x*w3.x + hp.y*w3.y + hp.z*w3.z + hp.w*w3.w;
#pragma unroll
    for (int o = 16; o > 0; o >>= 1) {
        p0 += __shfl_xor_sync(0xffffffffu, p0, o);
        p1 += __shfl_xor_sync(0xffffffffu, p1, o);
    }
    float a0 = 1.f / (1.f + expf((p1 + bf[1]) - (p0 + bf[0])));
    float4 g;
    g.x = a0 * z.x + (1.f - a0) * hp.x;
    g.y = a0 * z.y + (1.f - a0) * hp.y;
    g.z = a0 * z.z + (1.f - a0) * hp.z;
    g.w = a0 * z.w + (1.f - a0) * hp.w;
    *(float4*)&d_g[base] = g;
    if (lane == 0) d_trow[row] = t;
}

/* ------------- sampling: (apply prev update) + fuse gate ------------- */
__global__ void __launch_bounds__(256)
stepgate_kernel(const float* __restrict__ zsrc, const float* __restrict__ noise,
                const float* __restrict__ mask, const float* __restrict__ Wf,
                const float* __restrict__ bf,
                float c1, float inva, float sbeta, int addnoise, int dofirst, int kk) {
    int w = threadIdx.x >> 5, lane = threadIdx.x & 31;
    int row = blockIdx.x * 8 + w;
    float m = mask[row];
    size_t base = (size_t)row * EE + lane * 4;
    float4 z = *(const float4*)&zsrc[base];
    if (!dofirst) {
        float4 e = *(const float4*)&d_ep[base];
        z.x = (z.x - c1 * e.x) * inva;
        z.y = (z.y - c1 * e.y) * inva;
        z.z = (z.z - c1 * e.z) * inva;
        z.w = (z.w - c1 * e.w) * inva;
        if (addnoise) {
            float4 nz = *(const float4*)&noise[base];
            z.x += sbeta * nz.x; z.y += sbeta * nz.y;
            z.z += sbeta * nz.z; z.w += sbeta * nz.w;
        }
        z.x *= m; z.y *= m; z.z *= m; z.w *= m;
        *(float4*)&d_z[base] = z;
    }
    int t = (m > 0.f) ? kk : 1;
    float4 hp = *(const float4*)&d_hp[base];
    float4 w0 = *(const float4*)&Wf[lane * 4];
    float4 w1 = *(const float4*)&Wf[128 + lane * 4];
    float4 w2 = *(const float4*)&Wf[256 + lane * 4];
    float4 w3 = *(const float4*)&Wf[384 + lane * 4];
    float p0 = z.x*w0.x + z.y*w0.y + z.z*w0.z + z.w*w0.w
             + hp.x*w1.x + hp.y*w1.y + hp.z*w1.z + hp.w*w1.w;
    float p1 = z.x*w2.x + z.y*w2.y + z.z*w2.z + z.w*w2.w
             + hp.x*w3.x + hp.y*w3.y + hp.z*w3.z + hp.w*w3.w;
#pragma unroll
    for (int o = 16; o > 0; o >>= 1) {
        p0 += __shfl_xor_sync(0xffffffffu, p0, o);
        p1 += __shfl_xor_sync(0xffffffffu, p1, o);
    }
    float a0 = 1.f / (1.f + expf((p1 + bf[1]) - (p0 + bf[0])));
    float4 g;
    g.x = a0 * z.x + (1.f - a0) * hp.x;
    g.y = a0 * z.y + (1.f - a0) * hp.y;
    g.z = a0 * z.z + (1.f - a0) * hp.z;
    g.w = a0 * z.w + (1.f - a0) * hp.w;
    *(float4*)&d_g[base] = g;
    if (lane == 0) d_trow[row] = t;
}

/* ----------------------- final sampling update ----------------------- */
__global__ void __launch_bounds__(256)
finalupd_kernel(const float* __restrict__ mask, float c1, float inva) {
    int i4 = blockIdx.x * 256 + threadIdx.x;     /* RR*EE/4 */
    int row = i4 >> 5;
    float m = mask[row];
    size_t base = (size_t)i4 * 4;
    float4 z = *(const float4*)&d_z[base];
    float4 e = *(const float4*)&d_ep[base];
    z.x = (z.x - c1 * e.x) * inva * m;
    z.y = (z.y - c1 * e.y) * inva * m;
    z.z = (z.z - c1 * e.z) * inva * m;
    z.w = (z.w - c1 * e.w) * inva * m;
    *(float4*)&d_z[base] = z;
}

__global__ void __launch_bounds__(1)
final_kernel(float* __restrict__ out) {
    out[256] = d_scal[1] / d_scal[0];
}

/* ============================== host ================================= */
extern "C" void kernel_launch(void* const* d_in, const int* in_sizes, int n_in,
                              void* d_out, int out_size) {
    const float* padded_x   = (const float*)d_in[0];
    const float* visit_mask = (const float*)d_in[1];
    const int*   padded_bins= (const int*)  d_in[2];
    const int*   t_diff     = (const int*)  d_in[3];
    const float* eps        = (const float*)d_in[4];
    const float* z0         = (const float*)d_in[5];
    const float* noise      = (const float*)d_in[6];
    const float* W_visit    = (const float*)d_in[7];
    const float* bin_embed  = (const float*)d_in[8];
    const float* W_ih       = (const float*)d_in[9];
    const float* W_hh       = (const float*)d_in[10];
    const float* b_ih       = (const float*)d_in[11];
    const float* b_hh       = (const float*)d_in[12];
    const float* W_cls      = (const float*)d_in[13];
    const float* b_cls      = (const float*)d_in[14];
    const float* W_proj     = (const float*)d_in[15];
    const float* time_embed = (const float*)d_in[16];
    const float* W_fuse     = (const float*)d_in[17];
    const float* b_fuse     = (const float*)d_in[18];
    const float* W_e1       = (const float*)d_in[19];
    const float* b_e1       = (const float*)d_in[20];
    const float* W_e2       = (const float*)d_in[21];
    const float* b_e2       = (const float*)d_in[22];
    float* out = (float*)d_out;
    (void)in_sizes; (void)n_in; (void)out_size;

    float *v, *xg, *h, *hp, *z, *ep, *g, *ff1, *hsyn, *bias;
    cudaGetSymbolAddress((void**)&v,    d_v);
    cudaGetSymbolAddress((void**)&xg,   d_xg);
    cudaGetSymbolAddress((void**)&h,    d_h);
    cudaGetSymbolAddress((void**)&hp,   d_hp);
    cudaGetSymbolAddress((void**)&z,    d_z);
    cudaGetSymbolAddress((void**)&ep,   d_ep);
    cudaGetSymbolAddress((void**)&g,    d_g);
    cudaGetSymbolAddress((void**)&ff1,  d_ff1);
    cudaGetSymbolAddress((void**)&hsyn, d_hsyn);
    cudaGetSymbolAddress((void**)&bias, d_bias);

    /* diffusion schedule (host, fp64) */
    double betas[NSTEPS], alphas[NSTEPS], abars[NSTEPS];
    double prod = 1.0;
    for (int i = 0; i < NSTEPS; ++i) {
        betas[i] = 1e-4 + (double)i * (2e-2 - 1e-4) / (double)(NSTEPS - 1);
        alphas[i] = 1.0 - betas[i];
        prod *= alphas[i];
        abars[i] = prod;
    }
    ABCoef cf;
    for (int i = 0; i < NSTEPS; ++i) cf.ab[i] = (float)abars[i];

    /* ---- pipeline (lstm is launch index 5 for ncu -s 5 -c 1) ---- */
    transpose_kernel<<<dim3(VV / 32, EE / 32), dim3(32, 8)>>>(W_visit);            /* 0 */
    wqprep_kernel<<<128, 256>>>(W_hh);                                             /* 1 */
    biastt_kernel<<<1, 512>>>(b_ih, b_hh, time_embed, W_e1, b_e1);                 /* 2 */
    compute_v_kernel<<<RR, 128>>>(padded_x, padded_bins, visit_mask, bin_embed);   /* 3 */

    gemm_kernel<<<dim3(RR / 64, G4 / 64), 256>>>(v, W_ih, bias, xg,
                RR, G4, EE, EE, 1, 0, 0);                                          /* 4 */
    lstm_kernel<<<BB / 4, 512>>>(xg, visit_mask, h);                               /* 5 */
    prep_kernel<<<1, 128>>>(visit_mask);                                           /* 6 */
    logits_kernel<<<BB, 128>>>(h, W_cls, b_cls, out);                              /* 7 */

    /* hp = shift(h) @ W_proj^T  (shift fused into A load, flag 4) */
    gemm_kernel<<<dim3(RR / 64, EE / 64), 256>>>(h, W_proj, 0, hp,
                RR, EE, HH, HH, 4, 0, 0);                                          /* 8 */

    /* diffusion loss path */
    ztgate_kernel<<<RR / 8, 256>>>(eps, visit_mask, t_diff, W_fuse, b_fuse, cf);   /* 9 */
    gemm_kernel<<<dim3(RR / 64, EE / 64), 256>>>(g, W_e1, 0, ff1,
                RR, EE, EE, 2 * EE, 2 | 16, 0, 0);                                 /* 10 */
    gemm_kernel<<<dim3(RR / 64, EE / 64), 256>>>(ff1, W_e2, b_e2, ep,
                RR, EE, EE, EE, 1 | 8, eps, visit_mask);                           /* 11 */

    /* reverse diffusion sampling */
    for (int kk = NSTEPS; kk >= 1; --kk) {
        int s = kk + 1;  /* pending update from previous iteration's step */
        float c1 = 0.f, inva = 1.f, sb = 0.f;
        const float* zsrc = z;
        const float* np = noise;
        int dofirst = (kk == NSTEPS);
        if (!dofirst) {
            c1   = (float)(betas[s - 1] / sqrt(1.0 - abars[s - 1]));
            inva = (float)(1.0 / sqrt(alphas[s - 1]));
            sb   = (float)sqrt(betas[s - 1]);
            np   = noise + (size_t)(NSTEPS - s) * RR * EE;
            zsrc = (s == NSTEPS) ? z0 : z;
        }
        stepgate_kernel<<<RR / 8, 256>>>(dofirst ? z0 : zsrc, np, visit_mask,
                                         W_fuse, b_fuse, c1, inva, sb,
                                         1 /* s>=2 always here */, dofirst, kk);
        gemm_kernel<<<dim3(RR / 64, EE / 64), 256>>>(g, W_e1, 0, ff1,
                    RR, EE, EE, 2 * EE, 2 | 16, 0, 0);
        gemm_kernel<<<dim3(RR / 64, EE / 64), 256>>>(ff1, W_e2, b_e2, ep,
                    RR, EE, EE, EE, 1, 0, 0);
    }
    /* final update for step kk=1 (no noise). z source: step-1 input.
       For NSTEPS>=2 that z was written by stepgate(kk=1)'s update of step 2. */
    {
        float c1   = (float)(betas[0] / sqrt(1.0 - abars[0]));
        float inva = (float)(1.0 / sqrt(alphas[0]));
        finalupd_kernel<<<RR * EE / 1024, 256>>>(visit_mask, c1, inva);
    }

    /* encoder LSTM on synthetic data */
    gemm_kernel<<<dim3(RR / 64, G4 / 64), 256>>>(z, W_ih, bias, xg,
                RR, G4, EE, EE, 1, 0, 0);
    lstm_kernel<<<BB / 4, 512>>>(xg, visit_mask, hsyn);
    logits_kernel<<<BB, 128>>>(hsyn, W_cls, b_cls, out + 128);

    final_kernel<<<1, 1>>>(out);
}

// round 5
// speedup vs baseline: 1.6006x; 1.0932x over previous
#include <cuda_runtime.h>
#include <cuda_bf16.h>
#include <math.h>
#include <stdint.h>

#define BB 128
#define LL 64
#define VV 8192
#define EE 128
#define HH 128
#define RR (BB*LL)     /* 8192 rows */
#define G4 512
#define NSTEPS 10
#define MAXBIN 512
#define KP 136         /* padded K stride in bf16 elems */
#define ROWB 272       /* KP*2 bytes per tile row */

typedef unsigned long long ull;
typedef unsigned int u32;

/* ------------------------------ scratch ------------------------------ */
__device__ float d_Wt[VV*EE];          /* W_visit transposed [V][E] */
__device__ float d_Wq[G4*HH];          /* W_hh packed: [e4][j] float4 */
__device__ float d_v[RR*EE];
__device__ float d_xg[RR*G4];
__device__ float d_h[RR*HH];
__device__ float d_hp[RR*EE];
__device__ float d_z[RR*EE];
__device__ float d_ep[RR*EE];
__device__ float d_hsyn[RR*HH];
__device__ float d_bias[G4];
__device__ float d_TT[(NSTEPS+1)*EE];  /* temb@W_e1b^T + b_e1 per t */
__device__ int   d_len[BB];
__device__ float d_scal[2];            /* [0]=denom, [1]=loss accum */

/* bf16 hi/lo padded weight images: [hi plane Nrows*KP][lo plane Nrows*KP] */
__device__ __nv_bfloat16 d_wih_img[2*512*KP];
__device__ __nv_bfloat16 d_wproj_img[2*128*KP];
__device__ __nv_bfloat16 d_we1_img[2*128*KP];
__device__ __nv_bfloat16 d_we2_img[2*128*KP];

struct ABCoef { float ab[NSTEPS]; };

__device__ __forceinline__ float sigm(float x) { return 1.f / (1.f + expf(-x)); }
__device__ __forceinline__ void fma2(ull& c, ull a, ull b) {
    asm("fma.rn.f32x2 %0, %1, %2, %0;" : "+l"(c) : "l"(a), "l"(b));
}
union F2U { ull u; float2 f; };
union F4U { float4 f; ull u[2]; };

/* split pair of fp32 into (hi bf16x2, lo bf16x2) register images */
__device__ __forceinline__ uint2 split2(float x, float y) {
    __nv_bfloat162 h = __floats2bfloat162_rn(x, y);
    float2 hf = __bfloat1622float2(h);
    __nv_bfloat162 l = __floats2bfloat162_rn(x - hf.x, y - hf.y);
    uint2 r;
    r.x = *(u32*)&h;
    r.y = *(u32*)&l;
    return r;
}

#define MMA(c, a, b) \
    asm volatile("mma.sync.aligned.m16n8k16.row.col.f32.bf16.bf16.f32 " \
        "{%0,%1,%2,%3},{%4,%5,%6,%7},{%8,%9},{%0,%1,%2,%3};" \
        : "+f"((c)[0]), "+f"((c)[1]), "+f"((c)[2]), "+f"((c)[3]) \
        : "r"((a)[0]), "r"((a)[1]), "r"((a)[2]), "r"((a)[3]), "r"((b)[0]), "r"((b)[1]))

/* shared 128x128x128 split-bf16 mma mainloop: acc += A*W^T (3-term split) */
__device__ __forceinline__ void mma_block(const char* sAh, const char* sAl,
                                          const char* sWh, const char* sWl,
                                          float acc[2][8][4], int m0, int n0,
                                          int gr, int gc) {
#pragma unroll 2
    for (int k0 = 0; k0 < 128; k0 += 16) {
        u32 ah[2][4], al[2][4];
        int cA = (k0 + gc * 2) * 2;
#pragma unroll
        for (int mt = 0; mt < 2; ++mt) {
            int r = m0 + mt * 16 + gr;
            ah[mt][0] = *(const u32*)(sAh + r * ROWB + cA);
            ah[mt][1] = *(const u32*)(sAh + (r + 8) * ROWB + cA);
            ah[mt][2] = *(const u32*)(sAh + r * ROWB + cA + 16);
            ah[mt][3] = *(const u32*)(sAh + (r + 8) * ROWB + cA + 16);
            al[mt][0] = *(const u32*)(sAl + r * ROWB + cA);
            al[mt][1] = *(const u32*)(sAl + (r + 8) * ROWB + cA);
            al[mt][2] = *(const u32*)(sAl + r * ROWB + cA + 16);
            al[mt][3] = *(const u32*)(sAl + (r + 8) * ROWB + cA + 16);
        }
#pragma unroll
        for (int nh = 0; nh < 2; ++nh) {
            u32 bh[4][2], bl[4][2];
#pragma unroll
            for (int nt = 0; nt < 4; ++nt) {
                int n = n0 + nh * 32 + nt * 8 + gr;
                bh[nt][0] = *(const u32*)(sWh + n * ROWB + cA);
                bh[nt][1] = *(const u32*)(sWh + n * ROWB + cA + 16);
                bl[nt][0] = *(const u32*)(sWl + n * ROWB + cA);
                bl[nt][1] = *(const u32*)(sWl + n * ROWB + cA + 16);
            }
#pragma unroll
            for (int mt = 0; mt < 2; ++mt)
#pragma unroll
                for (int nt = 0; nt < 4; ++nt) {
                    float* c = acc[mt][nh * 4 + nt];
                    MMA(c, ah[mt], bh[nt]);
                    MMA(c, ah[mt], bl[nt]);
                    MMA(c, al[mt], bh[nt]);
                }
        }
    }
}

/* ------------------------- W_visit transpose ------------------------- */
__global__ void __launch_bounds__(256)
transpose_kernel(const float* __restrict__ W) {
    __shared__ float t[32][33];
    int j0 = blockIdx.x * 32, e0 = blockIdx.y * 32;
    for (int i = threadIdx.y; i < 32; i += 8)
        t[i][threadIdx.x] = W[(size_t)(e0 + i) * VV + j0 + threadIdx.x];
    __syncthreads();
    for (int i = threadIdx.y; i < 32; i += 8)
        d_Wt[(size_t)(j0 + i) * EE + e0 + threadIdx.x] = t[threadIdx.x][i];
}

/* --------------------- W_hh pack: [e4][j] float4 --------------------- */
__global__ void __launch_bounds__(256)
wqprep_kernel(const float* __restrict__ Whh) {
    int idx = blockIdx.x * 256 + threadIdx.x;     /* 32*512 quads */
    if (idx < 32 * G4) {
        int e4 = idx >> 9, j = idx & 511;
#pragma unroll
        for (int c = 0; c < 4; ++c)
            d_Wq[(e4 * G4 + j) * 4 + c] = Whh[(size_t)j * HH + e4 * 4 + c];
    }
}

/* ---------- weight rows -> bf16 hi/lo padded row-major images -------- */
__global__ void __launch_bounds__(128)
wconv_kernel(const float* __restrict__ Wih, const float* __restrict__ Wproj,
             const float* __restrict__ We1, const float* __restrict__ We2) {
    int rb = blockIdx.x, k = threadIdx.x;
    const float* src; int nrow, nrows; __nv_bfloat16* img; int ld = 128;
    if (rb < 512)      { src = Wih;  nrow = rb;       nrows = 512; img = d_wih_img; }
    else if (rb < 640) { src = Wproj; nrow = rb - 512; nrows = 128; img = d_wproj_img; }
    else if (rb < 768) { src = We1;  nrow = rb - 640; nrows = 128; img = d_we1_img; ld = 256; }
    else               { src = We2;  nrow = rb - 768; nrows = 128; img = d_we2_img; }
    float a = src[(size_t)nrow * ld + k];
    __nv_bfloat16 hi = __float2bfloat16(a);
    __nv_bfloat16 lo = __float2bfloat16(a - __bfloat162float(hi));
    img[(size_t)nrow * KP + k] = hi;
    img[(size_t)nrows * KP + (size_t)nrow * KP + k] = lo;
}

/* ------------------ bias sum + TT table precompute ------------------- */
__global__ void __launch_bounds__(512)
biastt_kernel(const float* __restrict__ bih, const float* __restrict__ bhh,
              const float* __restrict__ temb, const float* __restrict__ We1,
              const float* __restrict__ be1) {
    int j = threadIdx.x;
    d_bias[j] = bih[j] + bhh[j];
    if (j < EE) {
        for (int t = 0; t <= NSTEPS; ++t) {
            float s = be1[j];
            for (int k = 0; k < EE; ++k)
                s += temb[t * EE + k] * We1[(size_t)j * (2 * EE) + EE + k];
            d_TT[t * EE + j] = s;
        }
    }
}

/* ------------------- lengths, denom, loss reset ---------------------- */
__global__ void __launch_bounds__(128)
prep_kernel(const float* __restrict__ mask) {
    int b = threadIdx.x;
    float s = 0.f;
    for (int l = 0; l < LL; ++l) s += mask[b * LL + l];
    int len = (int)(s + 0.5f);
    if (len < 1) len = 1;
    d_len[b] = len;
    __shared__ float red[128];
    red[b] = s;
    __syncthreads();
    for (int o = 64; o > 0; o >>= 1) { if (b < o) red[b] += red[b + o]; __syncthreads(); }
    if (b == 0) {
        float dn = red[0];
        if (dn < 1.f) dn = 1.f;
        d_scal[0] = dn;
        d_scal[1] = 0.f;
    }
}

/* --------------------- sparse visit embedding ------------------------ */
__global__ void __launch_bounds__(128)
compute_v_kernel(const float* __restrict__ x,
                 const int* __restrict__ bins,
                 const float* __restrict__ mask,
                 const float* __restrict__ bin_embed) {
    int row = blockIdx.x;
    int tid = threadIdx.x;
    int l = row & (LL - 1);
    float m = mask[row];
    if (m == 0.f) { d_v[(size_t)row * EE + tid] = 0.f; return; }

    int dlt = 0;
    if (l > 0) {
        dlt = bins[row] - bins[row - 1];
        if (dlt < 0) dlt = 0;
        if (dlt > MAXBIN + 1) dlt = MAXBIN + 1;
    }
    float acc = bin_embed[dlt * EE + tid];

    __shared__ int   s_idx[2048];
    __shared__ float s_val[2048];
    __shared__ int   s_cnt;
    const float4* xr4 = reinterpret_cast<const float4*>(x + (size_t)row * VV);

    for (int c0 = 0; c0 < VV; c0 += 2048) {
        if (tid == 0) s_cnt = 0;
        __syncthreads();
#pragma unroll
        for (int i = 0; i < 4; ++i) {
            int j4 = (c0 >> 2) + i * 128 + tid;
            float4 xv = xr4[j4];
            if (xv.x != 0.f) { int p = atomicAdd(&s_cnt, 1); s_idx[p] = 4*j4+0; s_val[p] = xv.x; }
            if (xv.y != 0.f) { int p = atomicAdd(&s_cnt, 1); s_idx[p] = 4*j4+1; s_val[p] = xv.y; }
            if (xv.z != 0.f) { int p = atomicAdd(&s_cnt, 1); s_idx[p] = 4*j4+2; s_val[p] = xv.z; }
            if (xv.w != 0.f) { int p = atomicAdd(&s_cnt, 1); s_idx[p] = 4*j4+3; s_val[p] = xv.w; }
        }
        __syncthreads();
        int n = s_cnt;
        for (int p = 0; p < n; ++p)
            acc += s_val[p] * d_Wt[(size_t)s_idx[p] * EE + tid];
        __syncthreads();
    }
    d_v[(size_t)row * EE + tid] = acc * m;
}

/* ------------------- generic split-bf16 HMMA GEMM --------------------
   C[bm:+128, bn:+128] = A[.,128] @ Wimg[bn:+128]^T (+bias)  (opt shiftA) */
__global__ void __launch_bounds__(256)
hmma_gemm(const float* __restrict__ A, const __nv_bfloat16* __restrict__ Wimg,
          int wlo, const float* __restrict__ bias, float* __restrict__ C,
          int N, int shift) {
    extern __shared__ char sm[];
    char* sAh = sm;
    char* sAl = sm + 34816;
    char* sWh = sm + 69632;
    char* sWl = sm + 104448;
    int tid = threadIdx.x;
    int bm = blockIdx.x * 128, bn = blockIdx.y * 128;

    /* stage W tile */
    {
        const float4* srcH = (const float4*)(Wimg + (size_t)bn * KP);
        const float4* srcL = (const float4*)(Wimg + (size_t)wlo + (size_t)bn * KP);
        float4* dh = (float4*)sWh; float4* dl = (float4*)sWl;
        for (int i = tid; i < 2176; i += 256) { dh[i] = srcH[i]; dl[i] = srcL[i]; }
    }
    /* stage A tile (fp32 -> hi/lo bf16) */
    {
        int r = tid >> 1, c0 = (tid & 1) * 64;
        int g = bm + r;
        bool zr = shift && ((g & (LL - 1)) == 0);
        const float4* row = (const float4*)(A + (size_t)(shift ? (g > 0 ? g - 1 : 0) : g) * EE);
#pragma unroll 4
        for (int k4 = 0; k4 < 16; ++k4) {
            int c = c0 + k4 * 4;
            float4 f = zr ? make_float4(0.f, 0.f, 0.f, 0.f) : row[c >> 2];
            uint2 s01 = split2(f.x, f.y), s23 = split2(f.z, f.w);
            *(u32*)(sAh + r * ROWB + c * 2)     = s01.x;
            *(u32*)(sAl + r * ROWB + c * 2)     = s01.y;
            *(u32*)(sAh + r * ROWB + c * 2 + 4) = s23.x;
            *(u32*)(sAl + r * ROWB + c * 2 + 4) = s23.y;
        }
    }
    __syncthreads();

    int lane = tid & 31, w = tid >> 5;
    int m0 = (w & 3) * 32, n0 = (w >> 2) * 64;
    int gr = lane >> 2, gc = lane & 3;
    float acc[2][8][4];
#pragma unroll
    for (int i = 0; i < 2; ++i)
#pragma unroll
        for (int j = 0; j < 8; ++j)
#pragma unroll
            for (int q = 0; q < 4; ++q) acc[i][j][q] = 0.f;

    mma_block(sAh, sAl, sWh, sWl, acc, m0, n0, gr, gc);

#pragma unroll
    for (int mt = 0; mt < 2; ++mt)
#pragma unroll
        for (int nt = 0; nt < 8; ++nt) {
            int col = n0 + nt * 8 + gc * 2;
            float b0 = 0.f, b1 = 0.f;
            if (bias) { b0 = bias[bn + col]; b1 = bias[bn + col + 1]; }
            int r0 = bm + m0 + mt * 16 + gr;
            float2 v0 = make_float2(acc[mt][nt][0] + b0, acc[mt][nt][1] + b1);
            float2 v1 = make_float2(acc[mt][nt][2] + b0, acc[mt][nt][3] + b1);
            *(float2*)&C[(size_t)r0 * N + bn + col] = v0;
            *(float2*)&C[(size_t)(r0 + 8) * N + bn + col] = v1;
        }
}

/* ------------ fused diffusion step: gate + MLP (+loss) ---------------
   mode 0 = loss path (z_t from v/eps, t from tdiff, loss epilogue)
   mode 1 = first sampling step (z = zsrc raw, t = kk)
   mode 2 = sampling step (apply pending update, write d_z, t = kk)    */
__global__ void __launch_bounds__(256)
fused_step(const float* __restrict__ zsrc, const float* __restrict__ noise,
           const float* __restrict__ eps, const int* __restrict__ tdiff,
           const float* __restrict__ mask, const float* __restrict__ Wf,
           const float* __restrict__ bf, const float* __restrict__ be2,
           ABCoef cf, float c1, float inva, float sbeta, int kk, int mode) {
    extern __shared__ char sm[];
    char* sAh  = sm;
    char* sAl  = sm + 34816;
    char* sW1h = sm + 69632;
    char* sW1l = sm + 104448;
    char* sW2h = sm + 139264;
    char* sW2l = sm + 174080;
    int*   s_t  = (int*)(sm + 208896);
    float* s_m  = (float*)(sm + 209408);
    float* s_wf = (float*)(sm + 209920);
    __shared__ float s_lred[8];

    int tid = threadIdx.x;
    int bm = blockIdx.x * 128;
    int lane = tid & 31, w = tid >> 5;

    /* stage W1 + W2 hi/lo and Wf */
    {
        const float4* w1 = (const float4*)d_we1_img;
        const float4* w2 = (const float4*)d_we2_img;
        float4* d1 = (float4*)sW1h;
        float4* d2 = (float4*)sW2h;
        for (int i = tid; i < 4352; i += 256) { d1[i] = w1[i]; d2[i] = w2[i]; }
        if (tid < 256) { s_wf[tid] = Wf[tid]; s_wf[256 + tid] = Wf[256 + tid]; }
    }
    __syncthreads();

    float bf0 = bf[0], bf1 = bf[1];

    /* phase A: gate per row, store g as hi/lo into A tiles */
    float4 w0q = *(const float4*)&s_wf[lane * 4];
    float4 w1q = *(const float4*)&s_wf[128 + lane * 4];
    float4 w2q = *(const float4*)&s_wf[256 + lane * 4];
    float4 w3q = *(const float4*)&s_wf[384 + lane * 4];
#pragma unroll 1
    for (int i = 0; i < 16; ++i) {
        int r = w * 16 + i;
        int grow = bm + r;
        float m = mask[grow];
        size_t base = (size_t)grow * EE + lane * 4;
        float4 hq = *(const float4*)&d_hp[base];
        float4 zq;
        int t;
        if (mode == 0) {
            t = (m > 0.f) ? tdiff[grow >> 6] : 1;
            float ab = cf.ab[t - 1];
            float sa = sqrtf(ab) * m, sb = sqrtf(1.f - ab) * m;
            float4 vq = *(const float4*)&d_v[base];
            float4 eq = *(const float4*)&eps[base];
            zq.x = sa * vq.x + sb * eq.x;
            zq.y = sa * vq.y + sb * eq.y;
            zq.z = sa * vq.z + sb * eq.z;
            zq.w = sa * vq.w + sb * eq.w;
        } else {
            t = (m > 0.f) ? kk : 1;
            zq = *(const float4*)&zsrc[base];
            if (mode == 2) {
                float4 e = *(const float4*)&d_ep[base];
                float4 nz = *(const float4*)&noise[base];
                zq.x = ((zq.x - c1 * e.x) * inva + sbeta * nz.x) * m;
                zq.y = ((zq.y - c1 * e.y) * inva + sbeta * nz.y) * m;
                zq.z = ((zq.z - c1 * e.z) * inva + sbeta * nz.z) * m;
                zq.w = ((zq.w - c1 * e.w) * inva + sbeta * nz.w) * m;
                *(float4*)&d_z[base] = zq;
            }
        }
        float p0 = zq.x*w0q.x + zq.y*w0q.y + zq.z*w0q.z + zq.w*w0q.w
                 + hq.x*w1q.x + hq.y*w1q.y + hq.z*w1q.z + hq.w*w1q.w;
        float p1 = zq.x*w2q.x + zq.y*w2q.y + zq.z*w2q.z + zq.w*w2q.w
                 + hq.x*w3q.x + hq.y*w3q.y + hq.z*w3q.z + hq.w*w3q.w;
#pragma unroll
        for (int o = 16; o > 0; o >>= 1) {
            p0 += __shfl_xor_sync(0xffffffffu, p0, o);
            p1 += __shfl_xor_sync(0xffffffffu, p1, o);
        }
        float a0 = 1.f / (1.f + expf((p1 + bf1) - (p0 + bf0)));
        float gx = a0 * zq.x + (1.f - a0) * hq.x;
        float gy = a0 * zq.y + (1.f - a0) * hq.y;
        float gz = a0 * zq.z + (1.f - a0) * hq.z;
        float gw = a0 * zq.w + (1.f - a0) * hq.w;
        uint2 s01 = split2(gx, gy), s23 = split2(gz, gw);
        *(u32*)(sAh + r * ROWB + lane * 8)     = s01.x;
        *(u32*)(sAl + r * ROWB + lane * 8)     = s01.y;
        *(u32*)(sAh + r * ROWB + lane * 8 + 4) = s23.x;
        *(u32*)(sAl + r * ROWB + lane * 8 + 4) = s23.y;
        if (lane == 0) { s_t[r] = t; s_m[r] = m; }
    }
    __syncthreads();

    int m0 = (w & 3) * 32, n0 = (w >> 2) * 64;
    int gr = lane >> 2, gc = lane & 3;
    float acc[2][8][4];
#pragma unroll
    for (int i = 0; i < 2; ++i)
#pragma unroll
        for (int j = 0; j < 8; ++j)
#pragma unroll
            for (int q = 0; q < 4; ++q) acc[i][j][q] = 0.f;

    /* gemm1: ff1 = g @ We1a^T */
    mma_block(sAh, sAl, sW1h, sW1l, acc, m0, n0, gr, gc);
    __syncthreads();

    /* epilogue1: relu(acc + TT[t]) restaged into A tiles */
#pragma unroll
    for (int mt = 0; mt < 2; ++mt)
#pragma unroll
        for (int nt = 0; nt < 8; ++nt) {
            int col = n0 + nt * 8 + gc * 2;
            int r0 = m0 + mt * 16 + gr;
            int t0 = s_t[r0], t1 = s_t[r0 + 8];
            float f00 = fmaxf(acc[mt][nt][0] + d_TT[t0 * EE + col], 0.f);
            float f01 = fmaxf(acc[mt][nt][1] + d_TT[t0 * EE + col + 1], 0.f);
            float f10 = fmaxf(acc[mt][nt][2] + d_TT[t1 * EE + col], 0.f);
            float f11 = fmaxf(acc[mt][nt][3] + d_TT[t1 * EE + col + 1], 0.f);
            uint2 u0 = split2(f00, f01), u1 = split2(f10, f11);
            *(u32*)(sAh + r0 * ROWB + col * 2) = u0.x;
            *(u32*)(sAl + r0 * ROWB + col * 2) = u0.y;
            *(u32*)(sAh + (r0 + 8) * ROWB + col * 2) = u1.x;
            *(u32*)(sAl + (r0 + 8) * ROWB + col * 2) = u1.y;
            acc[mt][nt][0] = acc[mt][nt][1] = acc[mt][nt][2] = acc[mt][nt][3] = 0.f;
        }
    __syncthreads();

    /* gemm2: ep = ff1 @ We2^T + be2 */
    mma_block(sAh, sAl, sW2h, sW2l, acc, m0, n0, gr, gc);

    float lsum = 0.f;
#pragma unroll
    for (int mt = 0; mt < 2; ++mt)
#pragma unroll
        for (int nt = 0; nt < 8; ++nt) {
            int col = n0 + nt * 8 + gc * 2;
            int r0 = m0 + mt * 16 + gr;
            float b0 = be2[col], b1 = be2[col + 1];
            float o00 = acc[mt][nt][0] + b0, o01 = acc[mt][nt][1] + b1;
            float o10 = acc[mt][nt][2] + b0, o11 = acc[mt][nt][3] + b1;
            if (mode == 0) {
                float2 e0 = *(const float2*)&eps[(size_t)(bm + r0) * EE + col];
                float2 e1 = *(const float2*)&eps[(size_t)(bm + r0 + 8) * EE + col];
                float dx = o00 - e0.x, dy = o01 - e0.y;
                float dz = o10 - e1.x, dw = o11 - e1.y;
                lsum += (dx * dx + dy * dy) * s_m[r0] + (dz * dz + dw * dw) * s_m[r0 + 8];
            } else {
                *(float2*)&d_ep[(size_t)(bm + r0) * EE + col] = make_float2(o00, o01);
                *(float2*)&d_ep[(size_t)(bm + r0 + 8) * EE + col] = make_float2(o10, o11);
            }
        }
    if (mode == 0) {
#pragma unroll
        for (int o = 16; o > 0; o >>= 1) lsum += __shfl_xor_sync(0xffffffffu, lsum, o);
        if (lane == 0) s_lred[w] = lsum;
        __syncthreads();
        if (tid == 0) {
            float s = 0.f;
            for (int i = 0; i < 8; ++i) s += s_lred[i];
            atomicAdd(&d_scal[1], s);
        }
    }
}

/* ------------------------------ LSTM (4 batches/block) --------------- */
__global__ void __launch_bounds__(512)
lstm_kernel(const float* __restrict__ xg, const float* __restrict__ mask,
            float* __restrict__ hout) {
    int j = threadIdx.x;
    int b0 = blockIdx.x * 4;
    __shared__ __align__(16) float h_sh[4][HH];
    __shared__ float c_sh[4][HH];
    __shared__ float g_sh[4][G4];
    {
        int bb = j >> 7, ii = j & 127;
        h_sh[bb][ii] = 0.f; c_sh[bb][ii] = 0.f;
    }
    __syncthreads();
    const float4* wq4 = (const float4*)d_Wq;   /* [e4*512 + j] */

    for (int l = 0; l < LL; ++l) {
        ull g2[4] = {0ull, 0ull, 0ull, 0ull};
#pragma unroll 8
        for (int e4 = 0; e4 < 32; ++e4) {
            F4U wv; wv.f = wq4[e4 * G4 + j];
#pragma unroll
            for (int bb = 0; bb < 4; ++bb) {
                fma2(g2[bb], wv.u[0], *(const ull*)&h_sh[bb][e4 * 4]);
                fma2(g2[bb], wv.u[1], *(const ull*)&h_sh[bb][e4 * 4 + 2]);
            }
        }
#pragma unroll
        for (int bb = 0; bb < 4; ++bb) {
            F2U u; u.u = g2[bb];
            g_sh[bb][j] = u.f.x + u.f.y + xg[((size_t)(b0 + bb) * LL + l) * G4 + j];
        }
        __syncthreads();
        {
            int bb = j >> 7, idx = j & 127;
            float gi = g_sh[bb][idx];
            float gf = g_sh[bb][128 + idx];
            float gg = g_sh[bb][256 + idx];
            float go = g_sh[bb][384 + idx];
            float c = sigm(gf) * c_sh[bb][idx] + sigm(gi) * tanhf(gg);
            float h = sigm(go) * tanhf(c);
            c_sh[bb][idx] = c;
            h_sh[bb][idx] = h;
            int row = (b0 + bb) * LL + l;
            hout[(size_t)row * HH + idx] = h * mask[row];
        }
        __syncthreads();
    }
}

/* ------------------------------ logits ------------------------------- */
__global__ void __launch_bounds__(128)
logits_kernel(const float* __restrict__ h, const float* __restrict__ Wcls,
              const float* __restrict__ bcls, float* __restrict__ out) {
    int b = blockIdx.x, tid = threadIdx.x;
    int l = d_len[b] - 1;
    float p = h[((size_t)b * LL + l) * HH + tid] * Wcls[tid];
    __shared__ float red[128];
    red[tid] = p;
    __syncthreads();
    for (int o = 64; o > 0; o >>= 1) { if (tid < o) red[tid] += red[tid + o]; __syncthreads(); }
    if (tid == 0) out[b] = red[0] + bcls[0];
}

/* ----------------------- final sampling update ----------------------- */
__global__ void __launch_bounds__(256)
finalupd_kernel(const float* __restrict__ mask, float c1, float inva) {
    int i4 = blockIdx.x * 256 + threadIdx.x;
    int row = i4 >> 5;
    float m = mask[row];
    size_t base = (size_t)i4 * 4;
    float4 z = *(const float4*)&d_z[base];
    float4 e = *(const float4*)&d_ep[base];
    z.x = (z.x - c1 * e.x) * inva * m;
    z.y = (z.y - c1 * e.y) * inva * m;
    z.z = (z.z - c1 * e.z) * inva * m;
    z.w = (z.w - c1 * e.w) * inva * m;
    *(float4*)&d_z[base] = z;
}

__global__ void __launch_bounds__(1)
final_kernel(float* __restrict__ out) {
    out[256] = d_scal[1] / d_scal[0];
}

/* ============================== host ================================= */
extern "C" void kernel_launch(void* const* d_in, const int* in_sizes, int n_in,
                              void* d_out, int out_size) {
    const float* padded_x   = (const float*)d_in[0];
    const float* visit_mask = (const float*)d_in[1];
    const int*   padded_bins= (const int*)  d_in[2];
    const int*   t_diff     = (const int*)  d_in[3];
    const float* eps        = (const float*)d_in[4];
    const float* z0         = (const float*)d_in[5];
    const float* noise      = (const float*)d_in[6];
    const float* W_visit    = (const float*)d_in[7];
    const float* bin_embed  = (const float*)d_in[8];
    const float* W_ih       = (const float*)d_in[9];
    const float* W_hh       = (const float*)d_in[10];
    const float* b_ih       = (const float*)d_in[11];
    const float* b_hh       = (const float*)d_in[12];
    const float* W_cls      = (const float*)d_in[13];
    const float* b_cls      = (const float*)d_in[14];
    const float* W_proj     = (const float*)d_in[15];
    const float* time_embed = (const float*)d_in[16];
    const float* W_fuse     = (const float*)d_in[17];
    const float* b_fuse     = (const float*)d_in[18];
    const float* W_e1       = (const float*)d_in[19];
    const float* b_e1       = (const float*)d_in[20];
    const float* W_e2       = (const float*)d_in[21];
    const float* b_e2       = (const float*)d_in[22];
    float* out = (float*)d_out;
    (void)in_sizes; (void)n_in; (void)out_size;

    float *v, *xg, *h, *hp, *z, *hsyn, *bias;
    __nv_bfloat16 *wih_img, *wproj_img;
    cudaGetSymbolAddress((void**)&v,    d_v);
    cudaGetSymbolAddress((void**)&xg,   d_xg);
    cudaGetSymbolAddress((void**)&h,    d_h);
    cudaGetSymbolAddress((void**)&hp,   d_hp);
    cudaGetSymbolAddress((void**)&z,    d_z);
    cudaGetSymbolAddress((void**)&hsyn, d_hsyn);
    cudaGetSymbolAddress((void**)&bias, d_bias);
    cudaGetSymbolAddress((void**)&wih_img,   d_wih_img);
    cudaGetSymbolAddress((void**)&wproj_img, d_wproj_img);

    static int attr_done = 0;
    if (!attr_done) {
        cudaFuncSetAttribute(hmma_gemm,  cudaFuncAttributeMaxDynamicSharedMemorySize, 139264);
        cudaFuncSetAttribute(fused_step, cudaFuncAttributeMaxDynamicSharedMemorySize, 211968);
        attr_done = 1;
    }

    /* diffusion schedule (host, fp64) */
    double betas[NSTEPS], alphas[NSTEPS], abars[NSTEPS];
    double prod = 1.0;
    for (int i = 0; i < NSTEPS; ++i) {
        betas[i] = 1e-4 + (double)i * (2e-2 - 1e-4) / (double)(NSTEPS - 1);
        alphas[i] = 1.0 - betas[i];
        prod *= alphas[i];
        abars[i] = prod;
    }
    ABCoef cf;
    for (int i = 0; i < NSTEPS; ++i) cf.ab[i] = (float)abars[i];

    /* ---- pipeline ---- */
    transpose_kernel<<<dim3(VV / 32, EE / 32), dim3(32, 8)>>>(W_visit);
    wqprep_kernel<<<64, 256>>>(W_hh);
    wconv_kernel<<<896, 128>>>(W_ih, W_proj, W_e1, W_e2);
    biastt_kernel<<<1, 512>>>(b_ih, b_hh, time_embed, W_e1, b_e1);
    compute_v_kernel<<<RR, 128>>>(padded_x, padded_bins, visit_mask, bin_embed);

    /* encoder LSTM on real data */
    hmma_gemm<<<dim3(RR / 128, 4), 256, 139264>>>(v, wih_img, 512 * KP, bias, xg, G4, 0);
    lstm_kernel<<<BB / 4, 512>>>(xg, visit_mask, h);
    prep_kernel<<<1, 128>>>(visit_mask);
    logits_kernel<<<BB, 128>>>(h, W_cls, b_cls, out);

    /* hp = shift(h) @ W_proj^T */
    hmma_gemm<<<dim3(RR / 128, 1), 256, 139264>>>(h, wproj_img, 128 * KP,
                                                  (const float*)0, hp, EE, 1);

    /* diffusion loss path (mode 0) */
    fused_step<<<RR / 128, 256, 211968>>>(z0, noise, eps, t_diff, visit_mask,
                                          W_fuse, b_fuse, b_e2, cf,
                                          0.f, 1.f, 0.f, 0, 0);

    /* reverse diffusion sampling */
    for (int kk = NSTEPS; kk >= 1; --kk) {
        int s = kk + 1;   /* pending update from the previous iteration's step */
        float c1 = 0.f, inva = 1.f, sb = 0.f;
        const float* zsrc = z0;
        const float* np = noise;
        int mode = 1;
        if (kk < NSTEPS) {
            mode = 2;
            c1   = (float)(betas[s - 1] / sqrt(1.0 - abars[s - 1]));
            inva = (float)(1.0 / sqrt(alphas[s - 1]));
            sb   = (float)sqrt(betas[s - 1]);
            np   = noise + (size_t)(NSTEPS - s) * RR * EE;
            zsrc = (s == NSTEPS) ? z0 : z;
        }
        fused_step<<<RR / 128, 256, 211968>>>(zsrc, np, eps, t_diff, visit_mask,
                                              W_fuse, b_fuse, b_e2, cf,
                                              c1, inva, sb, kk, mode);
    }
    {
        float c1   = (float)(betas[0] / sqrt(1.0 - abars[0]));
        float inva = (float)(1.0 / sqrt(alphas[0]));
        finalupd_kernel<<<RR * EE / 1024, 256>>>(visit_mask, c1, inva);
    }

    /* encoder LSTM on synthetic data */
    hmma_gemm<<<dim3(RR / 128, 4), 256, 139264>>>(z, wih_img, 512 * KP, bias, xg, G4, 0);
    lstm_kernel<<<BB / 4, 512>>>(xg, visit_mask, hsyn);
    logits_kernel<<<BB, 128>>>(hsyn, W_cls, b_cls, out + 128);

    final_kernel<<<1, 1>>>(out);
}

// round 6
// speedup vs baseline: 1.9436x; 1.2143x over previous
#include <cuda_runtime.h>
#include <cuda_bf16.h>
#include <math.h>
#include <stdint.h>

#define BB 128
#define LL 64
#define VV 8192
#define EE 128
#define HH 128
#define RR (BB*LL)     /* 8192 rows */
#define G4 512
#define NSTEPS 10
#define MAXBIN 512
#define KP 136         /* padded K stride in bf16 elems */
#define ROWB 272       /* KP*2 bytes per tile row */

typedef unsigned long long ull;
typedef unsigned int u32;

/* ------------------------------ scratch ------------------------------ */
__device__ float d_Wt[VV*EE];          /* W_visit transposed [V][E] */
__device__ float d_Wq[G4*HH];          /* W_hh packed: [e4][j] float4 */
__device__ float d_v[RR*EE];
__device__ float d_xg[RR*G4];
__device__ float d_h[RR*HH];
__device__ float d_hp[RR*EE];
__device__ float d_z[RR*EE];
__device__ float d_ep[RR*EE];
__device__ float d_hsyn[RR*HH];
__device__ float d_bias[G4];
__device__ float d_TT[(NSTEPS+1)*EE];  /* temb@W_e1b^T + b_e1 per t */
__device__ int   d_len[BB];
__device__ float d_scal[2];            /* [0]=denom, [1]=loss accum */

/* bf16 hi/lo padded weight images: [hi plane Nrows*KP][lo plane Nrows*KP] */
__device__ __nv_bfloat16 d_wih_img[2*512*KP];
__device__ __nv_bfloat16 d_wproj_img[2*128*KP];
__device__ __nv_bfloat16 d_we1_img[2*128*KP];
__device__ __nv_bfloat16 d_we2_img[2*128*KP];

struct ABCoef { float ab[NSTEPS]; };

__device__ __forceinline__ float sigm(float x) { return 1.f / (1.f + expf(-x)); }
__device__ __forceinline__ void fma2(ull& c, ull a, ull b) {
    asm("fma.rn.f32x2 %0, %1, %2, %0;" : "+l"(c) : "l"(a), "l"(b));
}
union F2U { ull u; float2 f; };
union F4U { float4 f; ull u[2]; };

/* split pair of fp32 into (hi bf16x2, lo bf16x2) register images */
__device__ __forceinline__ uint2 split2(float x, float y) {
    __nv_bfloat162 h = __floats2bfloat162_rn(x, y);
    float2 hf = __bfloat1622float2(h);
    __nv_bfloat162 l = __floats2bfloat162_rn(x - hf.x, y - hf.y);
    uint2 r;
    r.x = *(u32*)&h;
    r.y = *(u32*)&l;
    return r;
}

#define MMA(c, a, b) \
    asm volatile("mma.sync.aligned.m16n8k16.row.col.f32.bf16.bf16.f32 " \
        "{%0,%1,%2,%3},{%4,%5,%6,%7},{%8,%9},{%0,%1,%2,%3};" \
        : "+f"((c)[0]), "+f"((c)[1]), "+f"((c)[2]), "+f"((c)[3]) \
        : "r"((a)[0]), "r"((a)[1]), "r"((a)[2]), "r"((a)[3]), "r"((b)[0]), "r"((b)[1]))

/* ------------------------- W_visit transpose ------------------------- */
__global__ void __launch_bounds__(256)
transpose_kernel(const float* __restrict__ W) {
    __shared__ float t[32][33];
    int j0 = blockIdx.x * 32, e0 = blockIdx.y * 32;
    for (int i = threadIdx.y; i < 32; i += 8)
        t[i][threadIdx.x] = W[(size_t)(e0 + i) * VV + j0 + threadIdx.x];
    __syncthreads();
    for (int i = threadIdx.y; i < 32; i += 8)
        d_Wt[(size_t)(j0 + i) * EE + e0 + threadIdx.x] = t[threadIdx.x][i];
}

/* --------------------- W_hh pack: [e4][j] float4 --------------------- */
__global__ void __launch_bounds__(256)
wqprep_kernel(const float* __restrict__ Whh) {
    int idx = blockIdx.x * 256 + threadIdx.x;     /* 32*512 quads */
    if (idx < 32 * G4) {
        int e4 = idx >> 9, j = idx & 511;
#pragma unroll
        for (int c = 0; c < 4; ++c)
            d_Wq[(e4 * G4 + j) * 4 + c] = Whh[(size_t)j * HH + e4 * 4 + c];
    }
}

/* ---------- weight rows -> bf16 hi/lo padded row-major images -------- */
__global__ void __launch_bounds__(128)
wconv_kernel(const float* __restrict__ Wih, const float* __restrict__ Wproj,
             const float* __restrict__ We1, const float* __restrict__ We2) {
    int rb = blockIdx.x, k = threadIdx.x;
    const float* src; int nrow, nrows; __nv_bfloat16* img; int ld = 128;
    if (rb < 512)      { src = Wih;  nrow = rb;       nrows = 512; img = d_wih_img; }
    else if (rb < 640) { src = Wproj; nrow = rb - 512; nrows = 128; img = d_wproj_img; }
    else if (rb < 768) { src = We1;  nrow = rb - 640; nrows = 128; img = d_we1_img; ld = 256; }
    else               { src = We2;  nrow = rb - 768; nrows = 128; img = d_we2_img; }
    float a = src[(size_t)nrow * ld + k];
    __nv_bfloat16 hi = __float2bfloat16(a);
    __nv_bfloat16 lo = __float2bfloat16(a - __bfloat162float(hi));
    img[(size_t)nrow * KP + k] = hi;
    img[(size_t)nrows * KP + (size_t)nrow * KP + k] = lo;
}

/* -------------------------- bias sum --------------------------------- */
__global__ void __launch_bounds__(512)
bias_kernel(const float* __restrict__ bih, const float* __restrict__ bhh) {
    int j = threadIdx.x;
    d_bias[j] = bih[j] + bhh[j];
}

/* ------------------ TT table precompute (parallel) ------------------- */
__global__ void __launch_bounds__(128)
tt_kernel(const float* __restrict__ temb, const float* __restrict__ We1,
          const float* __restrict__ be1) {
    int t = blockIdx.x, j = threadIdx.x;
    const float* tr = temb + t * EE;
    const float* wr = We1 + (size_t)j * (2 * EE) + EE;
    float s = be1[j];
#pragma unroll 16
    for (int k = 0; k < EE; ++k) s += tr[k] * wr[k];
    d_TT[t * EE + j] = s;
}

/* ------------------- lengths, denom, loss reset ---------------------- */
__global__ void __launch_bounds__(128)
prep_kernel(const float* __restrict__ mask) {
    int b = threadIdx.x;
    float s = 0.f;
    for (int l = 0; l < LL; ++l) s += mask[b * LL + l];
    int len = (int)(s + 0.5f);
    if (len < 1) len = 1;
    d_len[b] = len;
    __shared__ float red[128];
    red[b] = s;
    __syncthreads();
    for (int o = 64; o > 0; o >>= 1) { if (b < o) red[b] += red[b + o]; __syncthreads(); }
    if (b == 0) {
        float dn = red[0];
        if (dn < 1.f) dn = 1.f;
        d_scal[0] = dn;
        d_scal[1] = 0.f;
    }
}

/* --------------------- sparse visit embedding ------------------------ */
__global__ void __launch_bounds__(128)
compute_v_kernel(const float* __restrict__ x,
                 const int* __restrict__ bins,
                 const float* __restrict__ mask,
                 const float* __restrict__ bin_embed) {
    int row = blockIdx.x;
    int tid = threadIdx.x;
    int lane = tid & 31;
    int l = row & (LL - 1);
    float m = mask[row];
    if (m == 0.f) { d_v[(size_t)row * EE + tid] = 0.f; return; }

    int dlt = 0;
    if (l > 0) {
        dlt = bins[row] - bins[row - 1];
        if (dlt < 0) dlt = 0;
        if (dlt > MAXBIN + 1) dlt = MAXBIN + 1;
    }
    float acc = bin_embed[dlt * EE + tid];

    __shared__ int s_idx[VV];
    __shared__ int s_cnt;
    if (tid == 0) s_cnt = 0;
    __syncthreads();

    /* preload whole row: 16 float4 per thread (MLP=16) */
    const float4* xr4 = reinterpret_cast<const float4*>(x + (size_t)row * VV);
    float4 xr[16];
#pragma unroll
    for (int i = 0; i < 16; ++i) xr[i] = xr4[i * 128 + tid];

    u32 lmask = (1u << lane) - 1u;
#pragma unroll
    for (int i = 0; i < 16; ++i) {
        float vals[4] = {xr[i].x, xr[i].y, xr[i].z, xr[i].w};
#pragma unroll
        for (int c = 0; c < 4; ++c) {
            bool nz = vals[c] != 0.f;
            u32 msk = __ballot_sync(0xffffffffu, nz);
            if (msk) {
                int leader = __ffs(msk) - 1;
                int wbase = 0;
                if (lane == leader) wbase = atomicAdd(&s_cnt, __popc(msk));
                wbase = __shfl_sync(0xffffffffu, wbase, leader);
                if (nz) s_idx[wbase + __popc(msk & lmask)] = (i * 128 + tid) * 4 + c;
            }
        }
    }
    __syncthreads();
    int n = s_cnt;
    int p = 0;
    for (; p + 4 <= n; p += 4) {
        int i0 = s_idx[p], i1 = s_idx[p+1], i2 = s_idx[p+2], i3 = s_idx[p+3];
        float a0 = d_Wt[(size_t)i0 * EE + tid];
        float a1 = d_Wt[(size_t)i1 * EE + tid];
        float a2 = d_Wt[(size_t)i2 * EE + tid];
        float a3 = d_Wt[(size_t)i3 * EE + tid];
        acc += a0 + a1 + a2 + a3;
    }
    for (; p < n; ++p) acc += d_Wt[(size_t)s_idx[p] * EE + tid];
    d_v[(size_t)row * EE + tid] = acc * m;
}

/* ------------------- generic split-bf16 HMMA GEMM --------------------
   64-row tiles: C[bm:+64, bn:+128] = A @ Wimg[bn:+128]^T (+bias)       */
__global__ void __launch_bounds__(256)
hmma_gemm(const float* __restrict__ A, const __nv_bfloat16* __restrict__ Wimg,
          int wlo, const float* __restrict__ bias, float* __restrict__ C,
          int N, int shift) {
    extern __shared__ char sm[];
    char* sAh = sm;                 /* 64*272 = 17408 */
    char* sAl = sm + 17408;
    char* sWh = sm + 34816;         /* 128*272 = 34816 */
    char* sWl = sm + 69632;
    int tid = threadIdx.x;
    int bm = blockIdx.x * 64, bn = blockIdx.y * 128;

    /* stage W tile (128 rows hi+lo) */
    {
        const float4* srcH = (const float4*)(Wimg + (size_t)bn * KP);
        const float4* srcL = (const float4*)(Wimg + (size_t)wlo + (size_t)bn * KP);
        float4* dh = (float4*)sWh; float4* dl = (float4*)sWl;
        for (int i = tid; i < 2176; i += 256) { dh[i] = srcH[i]; dl[i] = srcL[i]; }
    }
    /* stage A tile 64 rows (fp32 -> hi/lo bf16) */
    {
        int r = tid >> 2, seg = tid & 3;
        int g = bm + r;
        bool zr = shift && ((g & (LL - 1)) == 0);
        const float4* row = (const float4*)(A + (size_t)(shift ? (g > 0 ? g - 1 : 0) : g) * EE);
#pragma unroll
        for (int k4 = 0; k4 < 8; ++k4) {
            int c = seg * 32 + k4 * 4;
            float4 f = zr ? make_float4(0.f, 0.f, 0.f, 0.f) : row[c >> 2];
            uint2 s01 = split2(f.x, f.y), s23 = split2(f.z, f.w);
            *(u32*)(sAh + r * ROWB + c * 2)     = s01.x;
            *(u32*)(sAl + r * ROWB + c * 2)     = s01.y;
            *(u32*)(sAh + r * ROWB + c * 2 + 4) = s23.x;
            *(u32*)(sAl + r * ROWB + c * 2 + 4) = s23.y;
        }
    }
    __syncthreads();

    int lane = tid & 31, w = tid >> 5;
    int m0 = (w & 3) * 16, n0 = (w >> 2) * 64;
    int gr = lane >> 2, gc = lane & 3;
    float acc[8][4];
#pragma unroll
    for (int j = 0; j < 8; ++j)
#pragma unroll
        for (int q = 0; q < 4; ++q) acc[j][q] = 0.f;

#pragma unroll 2
    for (int k0 = 0; k0 < 128; k0 += 16) {
        int cA = (k0 + gc * 2) * 2;
        u32 ah[4], al[4];
        int r = m0 + gr;
        ah[0] = *(const u32*)(sAh + r * ROWB + cA);
        ah[1] = *(const u32*)(sAh + (r + 8) * ROWB + cA);
        ah[2] = *(const u32*)(sAh + r * ROWB + cA + 16);
        ah[3] = *(const u32*)(sAh + (r + 8) * ROWB + cA + 16);
        al[0] = *(const u32*)(sAl + r * ROWB + cA);
        al[1] = *(const u32*)(sAl + (r + 8) * ROWB + cA);
        al[2] = *(const u32*)(sAl + r * ROWB + cA + 16);
        al[3] = *(const u32*)(sAl + (r + 8) * ROWB + cA + 16);
#pragma unroll
        for (int nt = 0; nt < 8; ++nt) {
            int n = n0 + nt * 8 + gr;
            u32 bh[2], bl[2];
            bh[0] = *(const u32*)(sWh + n * ROWB + cA);
            bh[1] = *(const u32*)(sWh + n * ROWB + cA + 16);
            bl[0] = *(const u32*)(sWl + n * ROWB + cA);
            bl[1] = *(const u32*)(sWl + n * ROWB + cA + 16);
            MMA(acc[nt], ah, bh);
            MMA(acc[nt], ah, bl);
            MMA(acc[nt], al, bh);
        }
    }

#pragma unroll
    for (int nt = 0; nt < 8; ++nt) {
        int col = n0 + nt * 8 + gc * 2;
        float b0 = 0.f, b1 = 0.f;
        if (bias) { b0 = bias[bn + col]; b1 = bias[bn + col + 1]; }
        int r0 = bm + m0 + gr;
        *(float2*)&C[(size_t)r0 * N + bn + col] = make_float2(acc[nt][0] + b0, acc[nt][1] + b1);
        *(float2*)&C[(size_t)(r0 + 8) * N + bn + col] = make_float2(acc[nt][2] + b0, acc[nt][3] + b1);
    }
}

/* ------------ fused diffusion step: gate + MLP (+loss) ---------------
   32-row tiles, grid RR/32=256, 2 CTAs/SM.
   mode 0 = loss path;  1 = first sampling step;  2 = sampling step     */
__global__ void __launch_bounds__(256, 2)
fused_step(const float* __restrict__ zsrc, const float* __restrict__ noise,
           const float* __restrict__ eps, const int* __restrict__ tdiff,
           const float* __restrict__ mask, const float* __restrict__ Wf,
           const float* __restrict__ bf, const float* __restrict__ be2,
           ABCoef cf, float c1, float inva, float sbeta, int kk, int mode) {
    extern __shared__ char sm[];
    char* sAh = sm;                  /* 32*272 = 8704 */
    char* sAl = sm + 8704;
    char* sWh = sm + 17408;          /* 128*272 = 34816, reused W1 then W2 */
    char* sWl = sm + 52224;
    int*   s_t  = (int*)(sm + 87040);    /* 32 */
    float* s_m  = (float*)(sm + 87168);  /* 32 */
    float* s_wf = (float*)(sm + 87296);  /* 512 */
    __shared__ float s_lred[8];

    int tid = threadIdx.x;
    int bm = blockIdx.x * 32;
    int lane = tid & 31, w = tid >> 5;

    /* stage W1 hi/lo and Wf */
    {
        const float4* w1h = (const float4*)d_we1_img;
        const float4* w1l = (const float4*)(d_we1_img + 128 * KP);
        float4* dh = (float4*)sWh; float4* dl = (float4*)sWl;
        for (int i = tid; i < 2176; i += 256) { dh[i] = w1h[i]; dl[i] = w1l[i]; }
        if (tid < 256) { s_wf[tid] = Wf[tid]; s_wf[256 + tid] = Wf[256 + tid]; }
    }

    float bf0 = bf[0], bf1 = bf[1];

    /* phase A: gate per row (4 rows/warp), store g hi/lo into A tiles */
    float4 w0q = *(const float4*)&s_wf[lane * 4];       /* note: s_wf filled above by
                                                           this thread's own writes may
                                                           not be visible w/o sync — use
                                                           Wf directly to be safe */
    w0q = *(const float4*)&Wf[lane * 4];
    float4 w1q = *(const float4*)&Wf[128 + lane * 4];
    float4 w2q = *(const float4*)&Wf[256 + lane * 4];
    float4 w3q = *(const float4*)&Wf[384 + lane * 4];
#pragma unroll 2
    for (int i = 0; i < 4; ++i) {
        int r = w * 4 + i;
        int grow = bm + r;
        float m = mask[grow];
        size_t base = (size_t)grow * EE + lane * 4;
        float4 hq = *(const float4*)&d_hp[base];
        float4 zq;
        int t;
        if (mode == 0) {
            t = (m > 0.f) ? tdiff[grow >> 6] : 1;
            float ab = cf.ab[t - 1];
            float sa = sqrtf(ab) * m, sb = sqrtf(1.f - ab) * m;
            float4 vq = *(const float4*)&d_v[base];
            float4 eq = *(const float4*)&eps[base];
            zq.x = sa * vq.x + sb * eq.x;
            zq.y = sa * vq.y + sb * eq.y;
            zq.z = sa * vq.z + sb * eq.z;
            zq.w = sa * vq.w + sb * eq.w;
        } else {
            t = (m > 0.f) ? kk : 1;
            zq = *(const float4*)&zsrc[base];
            if (mode == 2) {
                float4 e = *(const float4*)&d_ep[base];
                float4 nz = *(const float4*)&noise[base];
                zq.x = ((zq.x - c1 * e.x) * inva + sbeta * nz.x) * m;
                zq.y = ((zq.y - c1 * e.y) * inva + sbeta * nz.y) * m;
                zq.z = ((zq.z - c1 * e.z) * inva + sbeta * nz.z) * m;
                zq.w = ((zq.w - c1 * e.w) * inva + sbeta * nz.w) * m;
                *(float4*)&d_z[base] = zq;
            }
        }
        float p0 = zq.x*w0q.x + zq.y*w0q.y + zq.z*w0q.z + zq.w*w0q.w
                 + hq.x*w1q.x + hq.y*w1q.y + hq.z*w1q.z + hq.w*w1q.w;
        float p1 = zq.x*w2q.x + zq.y*w2q.y + zq.z*w2q.z + zq.w*w2q.w
                 + hq.x*w3q.x + hq.y*w3q.y + hq.z*w3q.z + hq.w*w3q.w;
#pragma unroll
        for (int o = 16; o > 0; o >>= 1) {
            p0 += __shfl_xor_sync(0xffffffffu, p0, o);
            p1 += __shfl_xor_sync(0xffffffffu, p1, o);
        }
        float a0 = 1.f / (1.f + expf((p1 + bf1) - (p0 + bf0)));
        float gx = a0 * zq.x + (1.f - a0) * hq.x;
        float gy = a0 * zq.y + (1.f - a0) * hq.y;
        float gz = a0 * zq.z + (1.f - a0) * hq.z;
        float gw = a0 * zq.w + (1.f - a0) * hq.w;
        uint2 s01 = split2(gx, gy), s23 = split2(gz, gw);
        *(u32*)(sAh + r * ROWB + lane * 8)     = s01.x;
        *(u32*)(sAl + r * ROWB + lane * 8)     = s01.y;
        *(u32*)(sAh + r * ROWB + lane * 8 + 4) = s23.x;
        *(u32*)(sAl + r * ROWB + lane * 8 + 4) = s23.y;
        if (lane == 0) { s_t[r] = t; s_m[r] = m; }
    }
    __syncthreads();

    int m0 = (w & 1) * 16, n0 = (w >> 1) * 32;
    int gr = lane >> 2, gc = lane & 3;
    float acc[4][4];
#pragma unroll
    for (int j = 0; j < 4; ++j)
#pragma unroll
        for (int q = 0; q < 4; ++q) acc[j][q] = 0.f;

    /* gemm1: ff1 = g @ We1a^T */
#pragma unroll 2
    for (int k0 = 0; k0 < 128; k0 += 16) {
        int cA = (k0 + gc * 2) * 2;
        u32 ah[4], al[4];
        int r = m0 + gr;
        ah[0] = *(const u32*)(sAh + r * ROWB + cA);
        ah[1] = *(const u32*)(sAh + (r + 8) * ROWB + cA);
        ah[2] = *(const u32*)(sAh + r * ROWB + cA + 16);
        ah[3] = *(const u32*)(sAh + (r + 8) * ROWB + cA + 16);
        al[0] = *(const u32*)(sAl + r * ROWB + cA);
        al[1] = *(const u32*)(sAl + (r + 8) * ROWB + cA);
        al[2] = *(const u32*)(sAl + r * ROWB + cA + 16);
        al[3] = *(const u32*)(sAl + (r + 8) * ROWB + cA + 16);
#pragma unroll
        for (int nt = 0; nt < 4; ++nt) {
            int n = n0 + nt * 8 + gr;
            u32 bh[2], bl[2];
            bh[0] = *(const u32*)(sWh + n * ROWB + cA);
            bh[1] = *(const u32*)(sWh + n * ROWB + cA + 16);
            bl[0] = *(const u32*)(sWl + n * ROWB + cA);
            bl[1] = *(const u32*)(sWl + n * ROWB + cA + 16);
            MMA(acc[nt], ah, bh);
            MMA(acc[nt], ah, bl);
            MMA(acc[nt], al, bh);
        }
    }
    __syncthreads();

    /* epilogue1: relu(acc + TT[t]) restaged into A tiles; stage W2 */
#pragma unroll
    for (int nt = 0; nt < 4; ++nt) {
        int col = n0 + nt * 8 + gc * 2;
        int r0 = m0 + gr, r1 = m0 + 8 + gr;
        int t0 = s_t[r0], t1 = s_t[r1];
        float f00 = fmaxf(acc[nt][0] + d_TT[t0 * EE + col], 0.f);
        float f01 = fmaxf(acc[nt][1] + d_TT[t0 * EE + col + 1], 0.f);
        float f10 = fmaxf(acc[nt][2] + d_TT[t1 * EE + col], 0.f);
        float f11 = fmaxf(acc[nt][3] + d_TT[t1 * EE + col + 1], 0.f);
        uint2 u0 = split2(f00, f01), u1 = split2(f10, f11);
        *(u32*)(sAh + r0 * ROWB + col * 2) = u0.x;
        *(u32*)(sAl + r0 * ROWB + col * 2) = u0.y;
        *(u32*)(sAh + r1 * ROWB + col * 2) = u1.x;
        *(u32*)(sAl + r1 * ROWB + col * 2) = u1.y;
        acc[nt][0] = acc[nt][1] = acc[nt][2] = acc[nt][3] = 0.f;
    }
    {
        const float4* w2h = (const float4*)d_we2_img;
        const float4* w2l = (const float4*)(d_we2_img + 128 * KP);
        float4* dh = (float4*)sWh; float4* dl = (float4*)sWl;
        for (int i = tid; i < 2176; i += 256) { dh[i] = w2h[i]; dl[i] = w2l[i]; }
    }
    __syncthreads();

    /* gemm2: ep = ff1 @ We2^T + be2 */
#pragma unroll 2
    for (int k0 = 0; k0 < 128; k0 += 16) {
        int cA = (k0 + gc * 2) * 2;
        u32 ah[4], al[4];
        int r = m0 + gr;
        ah[0] = *(const u32*)(sAh + r * ROWB + cA);
        ah[1] = *(const u32*)(sAh + (r + 8) * ROWB + cA);
        ah[2] = *(const u32*)(sAh + r * ROWB + cA + 16);
        ah[3] = *(const u32*)(sAh + (r + 8) * ROWB + cA + 16);
        al[0] = *(const u32*)(sAl + r * ROWB + cA);
        al[1] = *(const u32*)(sAl + (r + 8) * ROWB + cA);
        al[2] = *(const u32*)(sAl + r * ROWB + cA + 16);
        al[3] = *(const u32*)(sAl + (r + 8) * ROWB + cA + 16);
#pragma unroll
        for (int nt = 0; nt < 4; ++nt) {
            int n = n0 + nt * 8 + gr;
            u32 bh[2], bl[2];
            bh[0] = *(const u32*)(sWh + n * ROWB + cA);
            bh[1] = *(const u32*)(sWh + n * ROWB + cA + 16);
            bl[0] = *(const u32*)(sWl + n * ROWB + cA);
            bl[1] = *(const u32*)(sWl + n * ROWB + cA + 16);
            MMA(acc[nt], ah, bh);
            MMA(acc[nt], ah, bl);
            MMA(acc[nt], al, bh);
        }
    }

    float lsum = 0.f;
#pragma unroll
    for (int nt = 0; nt < 4; ++nt) {
        int col = n0 + nt * 8 + gc * 2;
        int r0 = m0 + gr, r1 = m0 + 8 + gr;
        float b0 = be2[col], b1 = be2[col + 1];
        float o00 = acc[nt][0] + b0, o01 = acc[nt][1] + b1;
        float o10 = acc[nt][2] + b0, o11 = acc[nt][3] + b1;
        if (mode == 0) {
            float2 e0 = *(const float2*)&eps[(size_t)(bm + r0) * EE + col];
            float2 e1 = *(const float2*)&eps[(size_t)(bm + r1) * EE + col];
            float dx = o00 - e0.x, dy = o01 - e0.y;
            float dz = o10 - e1.x, dw = o11 - e1.y;
            lsum += (dx * dx + dy * dy) * s_m[r0] + (dz * dz + dw * dw) * s_m[r1];
        } else {
            *(float2*)&d_ep[(size_t)(bm + r0) * EE + col] = make_float2(o00, o01);
            *(float2*)&d_ep[(size_t)(bm + r1) * EE + col] = make_float2(o10, o11);
        }
    }
    if (mode == 0) {
#pragma unroll
        for (int o = 16; o > 0; o >>= 1) lsum += __shfl_xor_sync(0xffffffffu, lsum, o);
        if (lane == 0) s_lred[w] = lsum;
        __syncthreads();
        if (tid == 0) {
            float s = 0.f;
            for (int i = 0; i < 8; ++i) s += s_lred[i];
            atomicAdd(&d_scal[1], s);
        }
    }
}

/* ------------------------------ LSTM (4 batches/block) --------------- */
__global__ void __launch_bounds__(512)
lstm_kernel(const float* __restrict__ xg, const float* __restrict__ mask,
            float* __restrict__ hout) {
    int j = threadIdx.x;
    int b0 = blockIdx.x * 4;
    __shared__ __align__(16) float h_sh[4][HH];
    __shared__ float c_sh[4][HH];
    __shared__ float g_sh[4][G4];
    {
        int bb = j >> 7, ii = j & 127;
        h_sh[bb][ii] = 0.f; c_sh[bb][ii] = 0.f;
    }
    __syncthreads();
    const float4* wq4 = (const float4*)d_Wq;   /* [e4*512 + j] */

    for (int l = 0; l < LL; ++l) {
        ull g2[4] = {0ull, 0ull, 0ull, 0ull};
#pragma unroll 8
        for (int e4 = 0; e4 < 32; ++e4) {
            F4U wv; wv.f = wq4[e4 * G4 + j];
#pragma unroll
            for (int bb = 0; bb < 4; ++bb) {
                fma2(g2[bb], wv.u[0], *(const ull*)&h_sh[bb][e4 * 4]);
                fma2(g2[bb], wv.u[1], *(const ull*)&h_sh[bb][e4 * 4 + 2]);
            }
        }
#pragma unroll
        for (int bb = 0; bb < 4; ++bb) {
            F2U u; u.u = g2[bb];
            g_sh[bb][j] = u.f.x + u.f.y + xg[((size_t)(b0 + bb) * LL + l) * G4 + j];
        }
        __syncthreads();
        {
            int bb = j >> 7, idx = j & 127;
            float gi = g_sh[bb][idx];
            float gf = g_sh[bb][128 + idx];
            float gg = g_sh[bb][256 + idx];
            float go = g_sh[bb][384 + idx];
            float c = sigm(gf) * c_sh[bb][idx] + sigm(gi) * tanhf(gg);
            float h = sigm(go) * tanhf(c);
            c_sh[bb][idx] = c;
            h_sh[bb][idx] = h;
            int row = (b0 + bb) * LL + l;
            hout[(size_t)row * HH + idx] = h * mask[row];
        }
        __syncthreads();
    }
}

/* ------------------------------ logits ------------------------------- */
__global__ void __launch_bounds__(128)
logits_kernel(const float* __restrict__ h, const float* __restrict__ Wcls,
              const float* __restrict__ bcls, float* __restrict__ out) {
    int b = blockIdx.x, tid = threadIdx.x;
    int l = d_len[b] - 1;
    float p = h[((size_t)b * LL + l) * HH + tid] * Wcls[tid];
    __shared__ float red[128];
    red[tid] = p;
    __syncthreads();
    for (int o = 64; o > 0; o >>= 1) { if (tid < o) red[tid] += red[tid + o]; __syncthreads(); }
    if (tid == 0) out[b] = red[0] + bcls[0];
}

/* ----------------------- final sampling update ----------------------- */
__global__ void __launch_bounds__(256)
finalupd_kernel(const float* __restrict__ mask, float c1, float inva) {
    int i4 = blockIdx.x * 256 + threadIdx.x;
    int row = i4 >> 5;
    float m = mask[row];
    size_t base = (size_t)i4 * 4;
    float4 z = *(const float4*)&d_z[base];
    float4 e = *(const float4*)&d_ep[base];
    z.x = (z.x - c1 * e.x) * inva * m;
    z.y = (z.y - c1 * e.y) * inva * m;
    z.z = (z.z - c1 * e.z) * inva * m;
    z.w = (z.w - c1 * e.w) * inva * m;
    *(float4*)&d_z[base] = z;
}

__global__ void __launch_bounds__(1)
final_kernel(float* __restrict__ out) {
    out[256] = d_scal[1] / d_scal[0];
}

/* ============================== host ================================= */
extern "C" void kernel_launch(void* const* d_in, const int* in_sizes, int n_in,
                              void* d_out, int out_size) {
    const float* padded_x   = (const float*)d_in[0];
    const float* visit_mask = (const float*)d_in[1];
    const int*   padded_bins= (const int*)  d_in[2];
    const int*   t_diff     = (const int*)  d_in[3];
    const float* eps        = (const float*)d_in[4];
    const float* z0         = (const float*)d_in[5];
    const float* noise      = (const float*)d_in[6];
    const float* W_visit    = (const float*)d_in[7];
    const float* bin_embed  = (const float*)d_in[8];
    const float* W_ih       = (const float*)d_in[9];
    const float* W_hh       = (const float*)d_in[10];
    const float* b_ih       = (const float*)d_in[11];
    const float* b_hh       = (const float*)d_in[12];
    const float* W_cls      = (const float*)d_in[13];
    const float* b_cls      = (const float*)d_in[14];
    const float* W_proj     = (const float*)d_in[15];
    const float* time_embed = (const float*)d_in[16];
    const float* W_fuse     = (const float*)d_in[17];
    const float* b_fuse     = (const float*)d_in[18];
    const float* W_e1       = (const float*)d_in[19];
    const float* b_e1       = (const float*)d_in[20];
    const float* W_e2       = (const float*)d_in[21];
    const float* b_e2       = (const float*)d_in[22];
    float* out = (float*)d_out;
    (void)in_sizes; (void)n_in; (void)out_size;

    float *v, *xg, *h, *hp, *z, *hsyn, *bias;
    __nv_bfloat16 *wih_img, *wproj_img;
    cudaGetSymbolAddress((void**)&v,    d_v);
    cudaGetSymbolAddress((void**)&xg,   d_xg);
    cudaGetSymbolAddress((void**)&h,    d_h);
    cudaGetSymbolAddress((void**)&hp,   d_hp);
    cudaGetSymbolAddress((void**)&z,    d_z);
    cudaGetSymbolAddress((void**)&hsyn, d_hsyn);
    cudaGetSymbolAddress((void**)&bias, d_bias);
    cudaGetSymbolAddress((void**)&wih_img,   d_wih_img);
    cudaGetSymbolAddress((void**)&wproj_img, d_wproj_img);

    static int attr_done = 0;
    if (!attr_done) {
        cudaFuncSetAttribute(hmma_gemm,  cudaFuncAttributeMaxDynamicSharedMemorySize, 104448);
        cudaFuncSetAttribute(fused_step, cudaFuncAttributeMaxDynamicSharedMemorySize, 89344);
        attr_done = 1;
    }

    /* diffusion schedule (host, fp64) */
    double betas[NSTEPS], alphas[NSTEPS], abars[NSTEPS];
    double prod = 1.0;
    for (int i = 0; i < NSTEPS; ++i) {
        betas[i] = 1e-4 + (double)i * (2e-2 - 1e-4) / (double)(NSTEPS - 1);
        alphas[i] = 1.0 - betas[i];
        prod *= alphas[i];
        abars[i] = prod;
    }
    ABCoef cf;
    for (int i = 0; i < NSTEPS; ++i) cf.ab[i] = (float)abars[i];

    /* ---- pipeline ---- */
    transpose_kernel<<<dim3(VV / 32, EE / 32), dim3(32, 8)>>>(W_visit);
    wqprep_kernel<<<64, 256>>>(W_hh);
    wconv_kernel<<<896, 128>>>(W_ih, W_proj, W_e1, W_e2);
    bias_kernel<<<1, 512>>>(b_ih, b_hh);
    tt_kernel<<<NSTEPS + 1, 128>>>(time_embed, W_e1, b_e1);
    compute_v_kernel<<<RR, 128>>>(padded_x, padded_bins, visit_mask, bin_embed);

    /* encoder LSTM on real data */
    hmma_gemm<<<dim3(RR / 64, 4), 256, 104448>>>(v, wih_img, 512 * KP, bias, xg, G4, 0);
    lstm_kernel<<<BB / 4, 512>>>(xg, visit_mask, h);
    prep_kernel<<<1, 128>>>(visit_mask);
    logits_kernel<<<BB, 128>>>(h, W_cls, b_cls, out);

    /* hp = shift(h) @ W_proj^T */
    hmma_gemm<<<dim3(RR / 64, 1), 256, 104448>>>(h, wproj_img, 128 * KP,
                                                 (const float*)0, hp, EE, 1);

    /* diffusion loss path (mode 0) */
    fused_step<<<RR / 32, 256, 89344>>>(z0, noise, eps, t_diff, visit_mask,
                                        W_fuse, b_fuse, b_e2, cf,
                                        0.f, 1.f, 0.f, 0, 0);

    /* reverse diffusion sampling */
    for (int kk = NSTEPS; kk >= 1; --kk) {
        int s = kk + 1;   /* pending update from the previous iteration's step */
        float c1 = 0.f, inva = 1.f, sb = 0.f;
        const float* zsrc = z0;
        const float* np = noise;
        int mode = 1;
        if (kk < NSTEPS) {
            mode = 2;
            c1   = (float)(betas[s - 1] / sqrt(1.0 - abars[s - 1]));
            inva = (float)(1.0 / sqrt(alphas[s - 1]));
            sb   = (float)sqrt(betas[s - 1]);
            np   = noise + (size_t)(NSTEPS - s) * RR * EE;
            zsrc = (s == NSTEPS) ? z0 : z;
        }
        fused_step<<<RR / 32, 256, 89344>>>(zsrc, np, eps, t_diff, visit_mask,
                                            W_fuse, b_fuse, b_e2, cf,
                                            c1, inva, sb, kk, mode);
    }
    {
        float c1   = (float)(betas[0] / sqrt(1.0 - abars[0]));
        float inva = (float)(1.0 / sqrt(alphas[0]));
        finalupd_kernel<<<RR * EE / 1024, 256>>>(visit_mask, c1, inva);
    }

    /* encoder LSTM on synthetic data */
    hmma_gemm<<<dim3(RR / 64, 4), 256, 104448>>>(z, wih_img, 512 * KP, bias, xg, G4, 0);
    lstm_kernel<<<BB / 4, 512>>>(xg, visit_mask, hsyn);
    logits_kernel<<<BB, 128>>>(hsyn, W_cls, b_cls, out + 128);

    final_kernel<<<1, 1>>>(out);
}

// round 7
// speedup vs baseline: 2.0769x; 1.0686x over previous
#include <cuda_runtime.h>
#include <cuda_bf16.h>
#include <math.h>
#include <stdint.h>

#define BB 128
#define LL 64
#define VV 8192
#define EE 128
#define HH 128
#define RR (BB*LL)     /* 8192 rows */
#define G4 512
#define NSTEPS 10
#define MAXBIN 512
#define KP 136         /* padded K stride in bf16 elems */
#define ROWB 272       /* KP*2 bytes per tile row */

typedef unsigned long long ull;
typedef unsigned int u32;

/* ------------------------------ scratch ------------------------------ */
__device__ float d_Wt[VV*EE];          /* W_visit transposed [V][E] */
__device__ float d_Wq[G4*HH];          /* W_hh packed: [e4][j] float4 */
__device__ float d_v[RR*EE];
__device__ float d_xg[RR*G4];
__device__ float d_h[RR*HH];
__device__ float d_hp[RR*EE];
__device__ float d_z[RR*EE];
__device__ float d_ep[RR*EE];
__device__ float d_hsyn[RR*HH];
__device__ float d_TT[(NSTEPS+1)*EE];  /* temb@W_e1b^T + b_e1 per t */
__device__ int   d_len[BB];
__device__ float d_scal[2];            /* [0]=denom, [1]=loss accum */

/* bf16 hi/lo padded weight images: [hi plane Nrows*KP][lo plane Nrows*KP] */
__device__ __nv_bfloat16 d_wih_img[2*512*KP];
__device__ __nv_bfloat16 d_wproj_img[2*128*KP];
__device__ __nv_bfloat16 d_we1_img[2*128*KP];
__device__ __nv_bfloat16 d_we2_img[2*128*KP];

struct ABCoef { float ab[NSTEPS]; };

__device__ __forceinline__ float sigm(float x) { return 1.f / (1.f + expf(-x)); }
__device__ __forceinline__ void fma2(ull& c, ull a, ull b) {
    asm("fma.rn.f32x2 %0, %1, %2, %0;" : "+l"(c) : "l"(a), "l"(b));
}
union F2U { ull u; float2 f; };
union F4U { float4 f; ull u[2]; };

/* split pair of fp32 into (hi bf16x2, lo bf16x2) register images */
__device__ __forceinline__ uint2 split2(float x, float y) {
    __nv_bfloat162 h = __floats2bfloat162_rn(x, y);
    float2 hf = __bfloat1622float2(h);
    __nv_bfloat162 l = __floats2bfloat162_rn(x - hf.x, y - hf.y);
    uint2 r;
    r.x = *(u32*)&h;
    r.y = *(u32*)&l;
    return r;
}

#define MMA(c, a, b) \
    asm volatile("mma.sync.aligned.m16n8k16.row.col.f32.bf16.bf16.f32 " \
        "{%0,%1,%2,%3},{%4,%5,%6,%7},{%8,%9},{%0,%1,%2,%3};" \
        : "+f"((c)[0]), "+f"((c)[1]), "+f"((c)[2]), "+f"((c)[3]) \
        : "r"((a)[0]), "r"((a)[1]), "r"((a)[2]), "r"((a)[3]), "r"((b)[0]), "r"((b)[1]))

/* ------------------------- W_visit transpose ------------------------- */
__global__ void __launch_bounds__(256)
transpose_kernel(const float* __restrict__ W) {
    __shared__ float t[32][33];
    int j0 = blockIdx.x * 32, e0 = blockIdx.y * 32;
    for (int i = threadIdx.y; i < 32; i += 8)
        t[i][threadIdx.x] = W[(size_t)(e0 + i) * VV + j0 + threadIdx.x];
    __syncthreads();
    for (int i = threadIdx.y; i < 32; i += 8)
        d_Wt[(size_t)(j0 + i) * EE + e0 + threadIdx.x] = t[threadIdx.x][i];
}

/* --------------------- W_hh pack: [e4][j] float4 --------------------- */
__global__ void __launch_bounds__(256)
wqprep_kernel(const float* __restrict__ Whh) {
    int idx = blockIdx.x * 256 + threadIdx.x;     /* 32*512 quads */
    if (idx < 32 * G4) {
        int e4 = idx >> 9, j = idx & 511;
#pragma unroll
        for (int c = 0; c < 4; ++c)
            d_Wq[(e4 * G4 + j) * 4 + c] = Whh[(size_t)j * HH + e4 * 4 + c];
    }
}

/* ---------- weight rows -> bf16 hi/lo padded row-major images -------- */
__global__ void __launch_bounds__(128)
wconv_kernel(const float* __restrict__ Wih, const float* __restrict__ Wproj,
             const float* __restrict__ We1, const float* __restrict__ We2) {
    int rb = blockIdx.x, k = threadIdx.x;
    const float* src; int nrow, nrows; __nv_bfloat16* img; int ld = 128;
    if (rb < 512)      { src = Wih;  nrow = rb;       nrows = 512; img = d_wih_img; }
    else if (rb < 640) { src = Wproj; nrow = rb - 512; nrows = 128; img = d_wproj_img; }
    else if (rb < 768) { src = We1;  nrow = rb - 640; nrows = 128; img = d_we1_img; ld = 256; }
    else               { src = We2;  nrow = rb - 768; nrows = 128; img = d_we2_img; }
    float a = src[(size_t)nrow * ld + k];
    __nv_bfloat16 hi = __float2bfloat16(a);
    __nv_bfloat16 lo = __float2bfloat16(a - __bfloat162float(hi));
    img[(size_t)nrow * KP + k] = hi;
    img[(size_t)nrows * KP + (size_t)nrow * KP + k] = lo;
}

/* ------------------ TT table precompute (parallel) ------------------- */
__global__ void __launch_bounds__(128)
tt_kernel(const float* __restrict__ temb, const float* __restrict__ We1,
          const float* __restrict__ be1) {
    int t = blockIdx.x, j = threadIdx.x;
    const float* tr = temb + t * EE;
    const float* wr = We1 + (size_t)j * (2 * EE) + EE;
    float s = be1[j];
#pragma unroll 16
    for (int k = 0; k < EE; ++k) s += tr[k] * wr[k];
    d_TT[t * EE + j] = s;
}

/* ------------------- lengths, denom, loss reset ---------------------- */
__global__ void __launch_bounds__(128)
prep_kernel(const float* __restrict__ mask) {
    int b = threadIdx.x;
    float s = 0.f;
    for (int l = 0; l < LL; ++l) s += mask[b * LL + l];
    int len = (int)(s + 0.5f);
    if (len < 1) len = 1;
    d_len[b] = len;
    __shared__ float red[128];
    red[b] = s;
    __syncthreads();
    for (int o = 64; o > 0; o >>= 1) { if (b < o) red[b] += red[b + o]; __syncthreads(); }
    if (b == 0) {
        float dn = red[0];
        if (dn < 1.f) dn = 1.f;
        d_scal[0] = dn;
        d_scal[1] = 0.f;
    }
}

/* --------------------- sparse visit embedding ------------------------ */
__global__ void __launch_bounds__(128)
compute_v_kernel(const float* __restrict__ x,
                 const int* __restrict__ bins,
                 const float* __restrict__ mask,
                 const float* __restrict__ bin_embed) {
    int row = blockIdx.x;
    int tid = threadIdx.x;
    int lane = tid & 31;
    int l = row & (LL - 1);
    float m = mask[row];
    if (m == 0.f) { d_v[(size_t)row * EE + tid] = 0.f; return; }

    int dlt = 0;
    if (l > 0) {
        dlt = bins[row] - bins[row - 1];
        if (dlt < 0) dlt = 0;
        if (dlt > MAXBIN + 1) dlt = MAXBIN + 1;
    }
    float acc = bin_embed[dlt * EE + tid];

    __shared__ int s_idx[VV];
    __shared__ int s_cnt;
    if (tid == 0) s_cnt = 0;
    __syncthreads();

    const float4* xr4 = reinterpret_cast<const float4*>(x + (size_t)row * VV);
    float4 xr[16];
#pragma unroll
    for (int i = 0; i < 16; ++i) xr[i] = xr4[i * 128 + tid];

    u32 lmask = (1u << lane) - 1u;
#pragma unroll
    for (int i = 0; i < 16; ++i) {
        float vals[4] = {xr[i].x, xr[i].y, xr[i].z, xr[i].w};
#pragma unroll
        for (int c = 0; c < 4; ++c) {
            bool nz = vals[c] != 0.f;
            u32 msk = __ballot_sync(0xffffffffu, nz);
            if (msk) {
                int leader = __ffs(msk) - 1;
                int wbase = 0;
                if (lane == leader) wbase = atomicAdd(&s_cnt, __popc(msk));
                wbase = __shfl_sync(0xffffffffu, wbase, leader);
                if (nz) s_idx[wbase + __popc(msk & lmask)] = (i * 128 + tid) * 4 + c;
            }
        }
    }
    __syncthreads();
    int n = s_cnt;
    int p = 0;
    for (; p + 4 <= n; p += 4) {
        int i0 = s_idx[p], i1 = s_idx[p+1], i2 = s_idx[p+2], i3 = s_idx[p+3];
        acc += d_Wt[(size_t)i0 * EE + tid] + d_Wt[(size_t)i1 * EE + tid]
             + d_Wt[(size_t)i2 * EE + tid] + d_Wt[(size_t)i3 * EE + tid];
    }
    for (; p < n; ++p) acc += d_Wt[(size_t)s_idx[p] * EE + tid];
    d_v[(size_t)row * EE + tid] = acc * m;
}

/* ------------------- generic split-bf16 HMMA GEMM --------------------
   512 thr, 64-row tiles: C[bm:+64, bn:+128] = A @ Wimg[bn:+128]^T
   mode: 0 plain, 1 shift A rows within LL, 2 final-z-update while staging */
__global__ void __launch_bounds__(512, 2)
hmma_gemm(const float* __restrict__ A, const __nv_bfloat16* __restrict__ Wimg,
          int wlo, const float* __restrict__ bias1, const float* __restrict__ bias2,
          float* __restrict__ C, int N, int mode,
          const float* __restrict__ ep, const float* __restrict__ mask,
          float c1, float inva) {
    extern __shared__ char sm[];
    char* sAh = sm;                 /* 64*272 = 17408 */
    char* sAl = sm + 17408;
    char* sWh = sm + 34816;         /* 128*272 = 34816 */
    char* sWl = sm + 69632;
    int tid = threadIdx.x;
    int bm = blockIdx.x * 64, bn = blockIdx.y * 128;

    /* stage W tile (128 rows hi+lo) */
    {
        const float4* srcH = (const float4*)(Wimg + (size_t)bn * KP);
        const float4* srcL = (const float4*)(Wimg + (size_t)wlo + (size_t)bn * KP);
        float4* dh = (float4*)sWh; float4* dl = (float4*)sWl;
        for (int i = tid; i < 2176; i += 512) { dh[i] = srcH[i]; dl[i] = srcL[i]; }
    }
    /* stage A tile 64 rows (fp32 -> hi/lo bf16) */
    {
        int r = tid >> 3, seg = tid & 7;
        int g = bm + r;
        bool zr = (mode == 1) && ((g & (LL - 1)) == 0);
        const float* arow = A + (size_t)((mode == 1) ? (g > 0 ? g - 1 : 0) : g) * EE;
        float m = (mode == 2) ? mask[g] : 0.f;
#pragma unroll
        for (int k4 = 0; k4 < 4; ++k4) {
            int c = seg * 16 + k4 * 4;
            float4 f = zr ? make_float4(0.f, 0.f, 0.f, 0.f)
                          : *(const float4*)(arow + c);
            if (mode == 2) {
                float4 e = *(const float4*)(ep + (size_t)g * EE + c);
                f.x = (f.x - c1 * e.x) * inva * m;
                f.y = (f.y - c1 * e.y) * inva * m;
                f.z = (f.z - c1 * e.z) * inva * m;
                f.w = (f.w - c1 * e.w) * inva * m;
            }
            uint2 s01 = split2(f.x, f.y), s23 = split2(f.z, f.w);
            *(u32*)(sAh + r * ROWB + c * 2)     = s01.x;
            *(u32*)(sAl + r * ROWB + c * 2)     = s01.y;
            *(u32*)(sAh + r * ROWB + c * 2 + 4) = s23.x;
            *(u32*)(sAl + r * ROWB + c * 2 + 4) = s23.y;
        }
    }
    __syncthreads();

    int lane = tid & 31, w = tid >> 5;          /* 16 warps */
    int m0 = (w & 3) * 16, n0 = (w >> 2) * 32;  /* m4 x n4 warp grid */
    int gr = lane >> 2, gc = lane & 3;
    float acc[4][4];
#pragma unroll
    for (int j = 0; j < 4; ++j)
#pragma unroll
        for (int q = 0; q < 4; ++q) acc[j][q] = 0.f;

#pragma unroll 2
    for (int k0 = 0; k0 < 128; k0 += 16) {
        int cA = (k0 + gc * 2) * 2;
        u32 ah[4], al[4];
        int r = m0 + gr;
        ah[0] = *(const u32*)(sAh + r * ROWB + cA);
        ah[1] = *(const u32*)(sAh + (r + 8) * ROWB + cA);
        ah[2] = *(const u32*)(sAh + r * ROWB + cA + 16);
        ah[3] = *(const u32*)(sAh + (r + 8) * ROWB + cA + 16);
        al[0] = *(const u32*)(sAl + r * ROWB + cA);
        al[1] = *(const u32*)(sAl + (r + 8) * ROWB + cA);
        al[2] = *(const u32*)(sAl + r * ROWB + cA + 16);
        al[3] = *(const u32*)(sAl + (r + 8) * ROWB + cA + 16);
#pragma unroll
        for (int nt = 0; nt < 4; ++nt) {
            int n = n0 + nt * 8 + gr;
            u32 bh[2], bl[2];
            bh[0] = *(const u32*)(sWh + n * ROWB + cA);
            bh[1] = *(const u32*)(sWh + n * ROWB + cA + 16);
            bl[0] = *(const u32*)(sWl + n * ROWB + cA);
            bl[1] = *(const u32*)(sWl + n * ROWB + cA + 16);
            MMA(acc[nt], ah, bh);
            MMA(acc[nt], ah, bl);
            MMA(acc[nt], al, bh);
        }
    }

#pragma unroll
    for (int nt = 0; nt < 4; ++nt) {
        int col = n0 + nt * 8 + gc * 2;
        float b0 = 0.f, b1 = 0.f;
        if (bias1) {
            b0 = bias1[bn + col] + bias2[bn + col];
            b1 = bias1[bn + col + 1] + bias2[bn + col + 1];
        }
        int r0 = bm + m0 + gr;
        *(float2*)&C[(size_t)r0 * N + bn + col] = make_float2(acc[nt][0] + b0, acc[nt][1] + b1);
        *(float2*)&C[(size_t)(r0 + 8) * N + bn + col] = make_float2(acc[nt][2] + b0, acc[nt][3] + b1);
    }
}

/* ------------ fused diffusion step: gate + MLP (+loss) ---------------
   512 thr, 32-row tiles, grid RR/32=256.
   mode 0 = loss path;  1 = first sampling step;  2 = sampling step     */
__global__ void __launch_bounds__(512, 2)
fused_step(const float* __restrict__ zsrc, const float* __restrict__ noise,
           const float* __restrict__ eps, const int* __restrict__ tdiff,
           const float* __restrict__ mask, const float* __restrict__ Wf,
           const float* __restrict__ bf, const float* __restrict__ be2,
           ABCoef cf, float c1, float inva, float sbeta, int kk, int mode) {
    extern __shared__ char sm[];
    char* sAh = sm;                  /* 32*272 = 8704 */
    char* sAl = sm + 8704;
    char* sWh = sm + 17408;          /* 128*272 = 34816, reused W1 then W2 */
    char* sWl = sm + 52224;
    int*   s_t = (int*)(sm + 87040);     /* 32 */
    float* s_m = (float*)(sm + 87168);   /* 32 */
    __shared__ float s_lred[16];

    int tid = threadIdx.x;
    int bm = blockIdx.x * 32;
    int lane = tid & 31, w = tid >> 5;   /* 16 warps */

    /* stage W1 hi/lo */
    {
        const float4* w1h = (const float4*)d_we1_img;
        const float4* w1l = (const float4*)(d_we1_img + 128 * KP);
        float4* dh = (float4*)sWh; float4* dl = (float4*)sWl;
        for (int i = tid; i < 2176; i += 512) { dh[i] = w1h[i]; dl[i] = w1l[i]; }
    }

    float bf0 = bf[0], bf1 = bf[1];
    float4 w0q = *(const float4*)&Wf[lane * 4];
    float4 w1q = *(const float4*)&Wf[128 + lane * 4];
    float4 w2q = *(const float4*)&Wf[256 + lane * 4];
    float4 w3q = *(const float4*)&Wf[384 + lane * 4];

    /* phase A: gate per row (2 rows/warp), store g hi/lo into A tiles */
#pragma unroll
    for (int i = 0; i < 2; ++i) {
        int r = w * 2 + i;
        int grow = bm + r;
        float m = mask[grow];
        size_t base = (size_t)grow * EE + lane * 4;
        float4 hq = *(const float4*)&d_hp[base];
        float4 zq;
        int t;
        if (mode == 0) {
            t = (m > 0.f) ? tdiff[grow >> 6] : 1;
            float ab = cf.ab[t - 1];
            float sa = sqrtf(ab) * m, sb = sqrtf(1.f - ab) * m;
            float4 vq = *(const float4*)&d_v[base];
            float4 eq = *(const float4*)&eps[base];
            zq.x = sa * vq.x + sb * eq.x;
            zq.y = sa * vq.y + sb * eq.y;
            zq.z = sa * vq.z + sb * eq.z;
            zq.w = sa * vq.w + sb * eq.w;
        } else {
            t = (m > 0.f) ? kk : 1;
            zq = *(const float4*)&zsrc[base];
            if (mode == 2) {
                float4 e = *(const float4*)&d_ep[base];
                float4 nz = *(const float4*)&noise[base];
                zq.x = ((zq.x - c1 * e.x) * inva + sbeta * nz.x) * m;
                zq.y = ((zq.y - c1 * e.y) * inva + sbeta * nz.y) * m;
                zq.z = ((zq.z - c1 * e.z) * inva + sbeta * nz.z) * m;
                zq.w = ((zq.w - c1 * e.w) * inva + sbeta * nz.w) * m;
                *(float4*)&d_z[base] = zq;
            }
        }
        float p0 = zq.x*w0q.x + zq.y*w0q.y + zq.z*w0q.z + zq.w*w0q.w
                 + hq.x*w1q.x + hq.y*w1q.y + hq.z*w1q.z + hq.w*w1q.w;
        float p1 = zq.x*w2q.x + zq.y*w2q.y + zq.z*w2q.z + zq.w*w2q.w
                 + hq.x*w3q.x + hq.y*w3q.y + hq.z*w3q.z + hq.w*w3q.w;
#pragma unroll
        for (int o = 16; o > 0; o >>= 1) {
            p0 += __shfl_xor_sync(0xffffffffu, p0, o);
            p1 += __shfl_xor_sync(0xffffffffu, p1, o);
        }
        float a0 = 1.f / (1.f + expf((p1 + bf1) - (p0 + bf0)));
        float gx = a0 * zq.x + (1.f - a0) * hq.x;
        float gy = a0 * zq.y + (1.f - a0) * hq.y;
        float gz = a0 * zq.z + (1.f - a0) * hq.z;
        float gw = a0 * zq.w + (1.f - a0) * hq.w;
        uint2 s01 = split2(gx, gy), s23 = split2(gz, gw);
        *(u32*)(sAh + r * ROWB + lane * 8)     = s01.x;
        *(u32*)(sAl + r * ROWB + lane * 8)     = s01.y;
        *(u32*)(sAh + r * ROWB + lane * 8 + 4) = s23.x;
        *(u32*)(sAl + r * ROWB + lane * 8 + 4) = s23.y;
        if (lane == 0) { s_t[r] = t; s_m[r] = m; }
    }
    __syncthreads();

    int m0 = (w & 1) * 16, n0 = (w >> 1) * 16;   /* m2 x n8 warp grid */
    int gr = lane >> 2, gc = lane & 3;
    float acc[2][4];
#pragma unroll
    for (int j = 0; j < 2; ++j)
#pragma unroll
        for (int q = 0; q < 4; ++q) acc[j][q] = 0.f;

    /* gemm1: ff1 = g @ We1a^T */
#pragma unroll 2
    for (int k0 = 0; k0 < 128; k0 += 16) {
        int cA = (k0 + gc * 2) * 2;
        u32 ah[4], al[4];
        int r = m0 + gr;
        ah[0] = *(const u32*)(sAh + r * ROWB + cA);
        ah[1] = *(const u32*)(sAh + (r + 8) * ROWB + cA);
        ah[2] = *(const u32*)(sAh + r * ROWB + cA + 16);
        ah[3] = *(const u32*)(sAh + (r + 8) * ROWB + cA + 16);
        al[0] = *(const u32*)(sAl + r * ROWB + cA);
        al[1] = *(const u32*)(sAl + (r + 8) * ROWB + cA);
        al[2] = *(const u32*)(sAl + r * ROWB + cA + 16);
        al[3] = *(const u32*)(sAl + (r + 8) * ROWB + cA + 16);
#pragma unroll
        for (int nt = 0; nt < 2; ++nt) {
            int n = n0 + nt * 8 + gr;
            u32 bh[2], bl[2];
            bh[0] = *(const u32*)(sWh + n * ROWB + cA);
            bh[1] = *(const u32*)(sWh + n * ROWB + cA + 16);
            bl[0] = *(const u32*)(sWl + n * ROWB + cA);
            bl[1] = *(const u32*)(sWl + n * ROWB + cA + 16);
            MMA(acc[nt], ah, bh);
            MMA(acc[nt], ah, bl);
            MMA(acc[nt], al, bh);
        }
    }
    __syncthreads();

    /* epilogue1: relu(acc + TT[t]) restaged into A tiles; stage W2 */
#pragma unroll
    for (int nt = 0; nt < 2; ++nt) {
        int col = n0 + nt * 8 + gc * 2;
        int r0 = m0 + gr, r1 = m0 + 8 + gr;
        int t0 = s_t[r0], t1 = s_t[r1];
        float f00 = fmaxf(acc[nt][0] + d_TT[t0 * EE + col], 0.f);
        float f01 = fmaxf(acc[nt][1] + d_TT[t0 * EE + col + 1], 0.f);
        float f10 = fmaxf(acc[nt][2] + d_TT[t1 * EE + col], 0.f);
        float f11 = fmaxf(acc[nt][3] + d_TT[t1 * EE + col + 1], 0.f);
        uint2 u0 = split2(f00, f01), u1 = split2(f10, f11);
        *(u32*)(sAh + r0 * ROWB + col * 2) = u0.x;
        *(u32*)(sAl + r0 * ROWB + col * 2) = u0.y;
        *(u32*)(sAh + r1 * ROWB + col * 2) = u1.x;
        *(u32*)(sAl + r1 * ROWB + col * 2) = u1.y;
        acc[nt][0] = acc[nt][1] = acc[nt][2] = acc[nt][3] = 0.f;
    }
    {
        const float4* w2h = (const float4*)d_we2_img;
        const float4* w2l = (const float4*)(d_we2_img + 128 * KP);
        float4* dh = (float4*)sWh; float4* dl = (float4*)sWl;
        for (int i = tid; i < 2176; i += 512) { dh[i] = w2h[i]; dl[i] = w2l[i]; }
    }
    __syncthreads();

    /* gemm2: ep = ff1 @ We2^T + be2 */
#pragma unroll 2
    for (int k0 = 0; k0 < 128; k0 += 16) {
        int cA = (k0 + gc * 2) * 2;
        u32 ah[4], al[4];
        int r = m0 + gr;
        ah[0] = *(const u32*)(sAh + r * ROWB + cA);
        ah[1] = *(const u32*)(sAh + (r + 8) * ROWB + cA);
        ah[2] = *(const u32*)(sAh + r * ROWB + cA + 16);
        ah[3] = *(const u32*)(sAh + (r + 8) * ROWB + cA + 16);
        al[0] = *(const u32*)(sAl + r * ROWB + cA);
        al[1] = *(const u32*)(sAl + (r + 8) * ROWB + cA);
        al[2] = *(const u32*)(sAl + r * ROWB + cA + 16);
        al[3] = *(const u32*)(sAl + (r + 8) * ROWB + cA + 16);
#pragma unroll
        for (int nt = 0; nt < 2; ++nt) {
            int n = n0 + nt * 8 + gr;
            u32 bh[2], bl[2];
            bh[0] = *(const u32*)(sWh + n * ROWB + cA);
            bh[1] = *(const u32*)(sWh + n * ROWB + cA + 16);
            bl[0] = *(const u32*)(sWl + n * ROWB + cA);
            bl[1] = *(const u32*)(sWl + n * ROWB + cA + 16);
            MMA(acc[nt], ah, bh);
            MMA(acc[nt], ah, bl);
            MMA(acc[nt], al, bh);
        }
    }

    float lsum = 0.f;
#pragma unroll
    for (int nt = 0; nt < 2; ++nt) {
        int col = n0 + nt * 8 + gc * 2;
        int r0 = m0 + gr, r1 = m0 + 8 + gr;
        float b0 = be2[col], b1 = be2[col + 1];
        float o00 = acc[nt][0] + b0, o01 = acc[nt][1] + b1;
        float o10 = acc[nt][2] + b0, o11 = acc[nt][3] + b1;
        if (mode == 0) {
            float2 e0 = *(const float2*)&eps[(size_t)(bm + r0) * EE + col];
            float2 e1 = *(const float2*)&eps[(size_t)(bm + r1) * EE + col];
            float dx = o00 - e0.x, dy = o01 - e0.y;
            float dz = o10 - e1.x, dw = o11 - e1.y;
            lsum += (dx * dx + dy * dy) * s_m[r0] + (dz * dz + dw * dw) * s_m[r1];
        } else {
            *(float2*)&d_ep[(size_t)(bm + r0) * EE + col] = make_float2(o00, o01);
            *(float2*)&d_ep[(size_t)(bm + r1) * EE + col] = make_float2(o10, o11);
        }
    }
    if (mode == 0) {
#pragma unroll
        for (int o = 16; o > 0; o >>= 1) lsum += __shfl_xor_sync(0xffffffffu, lsum, o);
        if (lane == 0) s_lred[w] = lsum;
        __syncthreads();
        if (tid == 0) {
            float s = 0.f;
            for (int i = 0; i < 16; ++i) s += s_lred[i];
            atomicAdd(&d_scal[1], s);
        }
    }
}

/* ------------------------------ LSTM (4 batches/block) --------------- */
__global__ void __launch_bounds__(512)
lstm_kernel(const float* __restrict__ xg, const float* __restrict__ mask,
            const float* __restrict__ bih, const float* __restrict__ bhh,
            float* __restrict__ hout) {
    int j = threadIdx.x;
    int b0 = blockIdx.x * 4;
    __shared__ __align__(16) float h_sh[4][HH];
    __shared__ float c_sh[4][HH];
    __shared__ float g_sh[4][G4];
    {
        int bb = j >> 7, ii = j & 127;
        h_sh[bb][ii] = 0.f; c_sh[bb][ii] = 0.f;
    }
    __syncthreads();
    const float4* wq4 = (const float4*)d_Wq;   /* [e4*512 + j] */

    for (int l = 0; l < LL; ++l) {
        ull g2[4] = {0ull, 0ull, 0ull, 0ull};
#pragma unroll 8
        for (int e4 = 0; e4 < 32; ++e4) {
            F4U wv; wv.f = wq4[e4 * G4 + j];
#pragma unroll
            for (int bb = 0; bb < 4; ++bb) {
                F4U hv; hv.f = *(const float4*)&h_sh[bb][e4 * 4];
                fma2(g2[bb], wv.u[0], hv.u[0]);
                fma2(g2[bb], wv.u[1], hv.u[1]);
            }
        }
#pragma unroll
        for (int bb = 0; bb < 4; ++bb) {
            F2U u; u.u = g2[bb];
            g_sh[bb][j] = u.f.x + u.f.y + xg[((size_t)(b0 + bb) * LL + l) * G4 + j];
        }
        __syncthreads();
        {
            int bb = j >> 7, idx = j & 127;
            float gi = g_sh[bb][idx];
            float gf = g_sh[bb][128 + idx];
            float gg = g_sh[bb][256 + idx];
            float go = g_sh[bb][384 + idx];
            float c = sigm(gf) * c_sh[bb][idx] + sigm(gi) * tanhf(gg);
            float h = sigm(go) * tanhf(c);
            c_sh[bb][idx] = c;
            h_sh[bb][idx] = h;
            int row = (b0 + bb) * LL + l;
            hout[(size_t)row * HH + idx] = h * mask[row];
        }
        __syncthreads();
    }
}

/* ------------------------------ logits ------------------------------- */
__global__ void __launch_bounds__(128)
logits_kernel(const float* __restrict__ h, const float* __restrict__ Wcls,
              const float* __restrict__ bcls, float* __restrict__ out) {
    int b = blockIdx.x, tid = threadIdx.x;
    int l = d_len[b] - 1;
    float p = h[((size_t)b * LL + l) * HH + tid] * Wcls[tid];
    __shared__ float red[128];
    red[tid] = p;
    __syncthreads();
    for (int o = 64; o > 0; o >>= 1) { if (tid < o) red[tid] += red[tid + o]; __syncthreads(); }
    if (tid == 0) out[b] = red[0] + bcls[0];
}

__global__ void __launch_bounds__(1)
final_kernel(float* __restrict__ out) {
    out[256] = d_scal[1] / d_scal[0];
}

/* ============================== host ================================= */
extern "C" void kernel_launch(void* const* d_in, const int* in_sizes, int n_in,
                              void* d_out, int out_size) {
    const float* padded_x   = (const float*)d_in[0];
    const float* visit_mask = (const float*)d_in[1];
    const int*   padded_bins= (const int*)  d_in[2];
    const int*   t_diff     = (const int*)  d_in[3];
    const float* eps        = (const float*)d_in[4];
    const float* z0         = (const float*)d_in[5];
    const float* noise      = (const float*)d_in[6];
    const float* W_visit    = (const float*)d_in[7];
    const float* bin_embed  = (const float*)d_in[8];
    const float* W_ih       = (const float*)d_in[9];
    const float* W_hh       = (const float*)d_in[10];
    const float* b_ih       = (const float*)d_in[11];
    const float* b_hh       = (const float*)d_in[12];
    const float* W_cls      = (const float*)d_in[13];
    const float* b_cls      = (const float*)d_in[14];
    const float* W_proj     = (const float*)d_in[15];
    const float* time_embed = (const float*)d_in[16];
    const float* W_fuse     = (const float*)d_in[17];
    const float* b_fuse     = (const float*)d_in[18];
    const float* W_e1       = (const float*)d_in[19];
    const float* b_e1       = (const float*)d_in[20];
    const float* W_e2       = (const float*)d_in[21];
    const float* b_e2       = (const float*)d_in[22];
    float* out = (float*)d_out;
    (void)in_sizes; (void)n_in; (void)out_size;

    float *v, *xg, *h, *hp, *z, *ep, *hsyn;
    __nv_bfloat16 *wih_img, *wproj_img;
    cudaGetSymbolAddress((void**)&v,    d_v);
    cudaGetSymbolAddress((void**)&xg,   d_xg);
    cudaGetSymbolAddress((void**)&h,    d_h);
    cudaGetSymbolAddress((void**)&hp,   d_hp);
    cudaGetSymbolAddress((void**)&z,    d_z);
    cudaGetSymbolAddress((void**)&ep,   d_ep);
    cudaGetSymbolAddress((void**)&hsyn, d_hsyn);
    cudaGetSymbolAddress((void**)&wih_img,   d_wih_img);
    cudaGetSymbolAddress((void**)&wproj_img, d_wproj_img);

    static int attr_done = 0;
    if (!attr_done) {
        cudaFuncSetAttribute(hmma_gemm,  cudaFuncAttributeMaxDynamicSharedMemorySize, 104448);
        cudaFuncSetAttribute(fused_step, cudaFuncAttributeMaxDynamicSharedMemorySize, 89344);
        attr_done = 1;
    }

    /* diffusion schedule (host, fp64) */
    double betas[NSTEPS], alphas[NSTEPS], abars[NSTEPS];
    double prod = 1.0;
    for (int i = 0; i < NSTEPS; ++i) {
        betas[i] = 1e-4 + (double)i * (2e-2 - 1e-4) / (double)(NSTEPS - 1);
        alphas[i] = 1.0 - betas[i];
        prod *= alphas[i];
        abars[i] = prod;
    }
    ABCoef cf;
    for (int i = 0; i < NSTEPS; ++i) cf.ab[i] = (float)abars[i];

    /* ---- pipeline (lstm is launch index 5 for ncu -s 5 -c 1) ---- */
    transpose_kernel<<<dim3(VV / 32, EE / 32), dim3(32, 8)>>>(W_visit);            /* 0 */
    wconv_kernel<<<896, 128>>>(W_ih, W_proj, W_e1, W_e2);                          /* 1 */
    wqprep_kernel<<<64, 256>>>(W_hh);                                              /* 2 */
    compute_v_kernel<<<RR, 128>>>(padded_x, padded_bins, visit_mask, bin_embed);   /* 3 */
    hmma_gemm<<<dim3(RR / 64, 4), 512, 104448>>>(v, wih_img, 512 * KP,
                b_ih, b_hh, xg, G4, 0, 0, 0, 0.f, 0.f);                            /* 4 */
    lstm_kernel<<<BB / 4, 512>>>(xg, visit_mask, b_ih, b_hh, h);                   /* 5 */

    tt_kernel<<<NSTEPS + 1, 128>>>(time_embed, W_e1, b_e1);
    prep_kernel<<<1, 128>>>(visit_mask);
    logits_kernel<<<BB, 128>>>(h, W_cls, b_cls, out);

    /* hp = shift(h) @ W_proj^T */
    hmma_gemm<<<dim3(RR / 64, 1), 512, 104448>>>(h, wproj_img, 128 * KP,
                0, 0, hp, EE, 1, 0, 0, 0.f, 0.f);

    /* diffusion loss path (mode 0) */
    fused_step<<<RR / 32, 512, 89344>>>(z0, noise, eps, t_diff, visit_mask,
                                        W_fuse, b_fuse, b_e2, cf,
                                        0.f, 1.f, 0.f, 0, 0);

    /* reverse diffusion sampling */
    for (int kk = NSTEPS; kk >= 1; --kk) {
        int s = kk + 1;   /* pending update from the previous iteration's step */
        float c1 = 0.f, inva = 1.f, sb = 0.f;
        const float* zsrc = z0;
        const float* np = noise;
        int mode = 1;
        if (kk < NSTEPS) {
            mode = 2;
            c1   = (float)(betas[s - 1] / sqrt(1.0 - abars[s - 1]));
            inva = (float)(1.0 / sqrt(alphas[s - 1]));
            sb   = (float)sqrt(betas[s - 1]);
            np   = noise + (size_t)(NSTEPS - s) * RR * EE;
            zsrc = (s == NSTEPS) ? z0 : z;
        }
        fused_step<<<RR / 32, 512, 89344>>>(zsrc, np, eps, t_diff, visit_mask,
                                            W_fuse, b_fuse, b_e2, cf,
                                            c1, inva, sb, kk, mode);
    }

    /* encoder LSTM on synthetic data; final z update fused into staging */
    {
        float c1   = (float)(betas[0] / sqrt(1.0 - abars[0]));
        float inva = (float)(1.0 / sqrt(alphas[0]));
        hmma_gemm<<<dim3(RR / 64, 4), 512, 104448>>>(z, wih_img, 512 * KP,
                    b_ih, b_hh, xg, G4, 2, ep, visit_mask, c1, inva);
    }
    lstm_kernel<<<BB / 4, 512>>>(xg, visit_mask, b_ih, b_hh, hsyn);
    logits_kernel<<<BB, 128>>>(hsyn, W_cls, b_cls, out + 128);

    final_kernel<<<1, 1>>>(out);
}

// round 8
// speedup vs baseline: 2.1325x; 1.0268x over previous
#include <cuda_runtime.h>
#include <cuda_bf16.h>
#include <math.h>
#include <stdint.h>

#define BB 128
#define LL 64
#define VV 8192
#define EE 128
#define HH 128
#define RR (BB*LL)     /* 8192 rows */
#define G4 512
#define NSTEPS 10
#define MAXBIN 512
#define KP 136         /* padded K stride in bf16 elems */
#define ROWB 272       /* KP*2 bytes per tile row */

typedef unsigned long long ull;
typedef unsigned int u32;

/* ------------------------------ scratch ------------------------------ */
__device__ float d_Wt[VV*EE];          /* W_visit transposed [V][E] */
__device__ float d_Wq[G4*HH];          /* W_hh packed: [e4][j] float4 */
__device__ float d_v[RR*EE];
__device__ float d_xg[RR*G4];
__device__ float d_h[RR*HH];
__device__ float d_hp[RR*EE];
__device__ float d_z[RR*EE];
__device__ float d_ep[RR*EE];
__device__ float d_hsyn[RR*HH];
__device__ float d_TT[(NSTEPS+1)*EE];  /* temb@W_e1b^T + b_e1 per t */
__device__ int   d_len[BB];
__device__ float d_scal[2];            /* [0]=denom, [1]=loss accum */

/* bf16 hi/lo padded weight images: [hi plane Nrows*KP][lo plane Nrows*KP] */
__device__ __nv_bfloat16 d_wih_img[2*512*KP];
__device__ __nv_bfloat16 d_wproj_img[2*128*KP];
__device__ __nv_bfloat16 d_we1_img[2*128*KP];
__device__ __nv_bfloat16 d_we2_img[2*128*KP];

struct ABCoef { float ab[NSTEPS]; };

__device__ __forceinline__ float sigm(float x) { return 1.f / (1.f + expf(-x)); }
union F2U { ull u; float2 f; };

__device__ __forceinline__ u32 smem_u32(const void* p) {
    u32 a;
    asm("{ .reg .u64 t; cvta.to.shared.u64 t, %1; cvt.u32.u64 %0, t; }" : "=r"(a) : "l"(p));
    return a;
}

/* split pair of fp32 into (hi bf16x2, lo bf16x2) register images */
__device__ __forceinline__ uint2 split2(float x, float y) {
    __nv_bfloat162 h = __floats2bfloat162_rn(x, y);
    float2 hf = __bfloat1622float2(h);
    __nv_bfloat162 l = __floats2bfloat162_rn(x - hf.x, y - hf.y);
    uint2 r;
    r.x = *(u32*)&h;
    r.y = *(u32*)&l;
    return r;
}

#define MMA(c, a, b) \
    asm volatile("mma.sync.aligned.m16n8k16.row.col.f32.bf16.bf16.f32 " \
        "{%0,%1,%2,%3},{%4,%5,%6,%7},{%8,%9},{%0,%1,%2,%3};" \
        : "+f"((c)[0]), "+f"((c)[1]), "+f"((c)[2]), "+f"((c)[3]) \
        : "r"((a)[0]), "r"((a)[1]), "r"((a)[2]), "r"((a)[3]), "r"((b)[0]), "r"((b)[1]))

#define LDSM_X4(R, ADDR) \
    asm volatile("ldmatrix.sync.aligned.m8n8.x4.shared.b16 {%0,%1,%2,%3}, [%4];" \
        : "=r"((R)[0]), "=r"((R)[1]), "=r"((R)[2]), "=r"((R)[3]) : "r"(ADDR))

/* ------------------------- W_visit transpose ------------------------- */
__global__ void __launch_bounds__(256)
transpose_kernel(const float* __restrict__ W) {
    __shared__ float t[32][33];
    int j0 = blockIdx.x * 32, e0 = blockIdx.y * 32;
    for (int i = threadIdx.y; i < 32; i += 8)
        t[i][threadIdx.x] = W[(size_t)(e0 + i) * VV + j0 + threadIdx.x];
    __syncthreads();
    for (int i = threadIdx.y; i < 32; i += 8)
        d_Wt[(size_t)(j0 + i) * EE + e0 + threadIdx.x] = t[threadIdx.x][i];
}

/* ---- weight prep: bf16 hi/lo images + W_hh pack (merged kernel) ----- */
__global__ void __launch_bounds__(128)
wconv_kernel(const float* __restrict__ Wih, const float* __restrict__ Wproj,
             const float* __restrict__ We1, const float* __restrict__ We2,
             const float* __restrict__ Whh) {
    int rb = blockIdx.x, k = threadIdx.x;
    if (rb >= 896) {
        /* W_hh pack: [e4][j] float4; 128 blocks x 128 thr = 16384 quads */
        int idx = (rb - 896) * 128 + k;
        int e4 = idx >> 9, j = idx & 511;
#pragma unroll
        for (int c = 0; c < 4; ++c)
            d_Wq[(e4 * G4 + j) * 4 + c] = Whh[(size_t)j * HH + e4 * 4 + c];
        return;
    }
    const float* src; int nrow, nrows; __nv_bfloat16* img; int ld = 128;
    if (rb < 512)      { src = Wih;  nrow = rb;       nrows = 512; img = d_wih_img; }
    else if (rb < 640) { src = Wproj; nrow = rb - 512; nrows = 128; img = d_wproj_img; }
    else if (rb < 768) { src = We1;  nrow = rb - 640; nrows = 128; img = d_we1_img; ld = 256; }
    else               { src = We2;  nrow = rb - 768; nrows = 128; img = d_we2_img; }
    float a = src[(size_t)nrow * ld + k];
    __nv_bfloat16 hi = __float2bfloat16(a);
    __nv_bfloat16 lo = __float2bfloat16(a - __bfloat162float(hi));
    img[(size_t)nrow * KP + k] = hi;
    img[(size_t)nrows * KP + (size_t)nrow * KP + k] = lo;
}

/* ------------------ TT table precompute (parallel) ------------------- */
__global__ void __launch_bounds__(128)
tt_kernel(const float* __restrict__ temb, const float* __restrict__ We1,
          const float* __restrict__ be1) {
    int t = blockIdx.x, j = threadIdx.x;
    const float* tr = temb + t * EE;
    const float* wr = We1 + (size_t)j * (2 * EE) + EE;
    float s = be1[j];
#pragma unroll 16
    for (int k = 0; k < EE; ++k) s += tr[k] * wr[k];
    d_TT[t * EE + j] = s;
}

/* ------------------- lengths, denom, loss reset ---------------------- */
__global__ void __launch_bounds__(128)
prep_kernel(const float* __restrict__ mask) {
    int b = threadIdx.x;
    float s = 0.f;
    for (int l = 0; l < LL; ++l) s += mask[b * LL + l];
    int len = (int)(s + 0.5f);
    if (len < 1) len = 1;
    d_len[b] = len;
    __shared__ float red[128];
    red[b] = s;
    __syncthreads();
    for (int o = 64; o > 0; o >>= 1) { if (b < o) red[b] += red[b + o]; __syncthreads(); }
    if (b == 0) {
        float dn = red[0];
        if (dn < 1.f) dn = 1.f;
        d_scal[0] = dn;
        d_scal[1] = 0.f;
    }
}

/* --------------------- sparse visit embedding (R2 form) -------------- */
__global__ void __launch_bounds__(128)
compute_v_kernel(const float* __restrict__ x,
                 const int* __restrict__ bins,
                 const float* __restrict__ mask,
                 const float* __restrict__ bin_embed) {
    int row = blockIdx.x;
    int tid = threadIdx.x;
    int l = row & (LL - 1);
    float m = mask[row];
    if (m == 0.f) { d_v[(size_t)row * EE + tid] = 0.f; return; }

    int dlt = 0;
    if (l > 0) {
        dlt = bins[row] - bins[row - 1];
        if (dlt < 0) dlt = 0;
        if (dlt > MAXBIN + 1) dlt = MAXBIN + 1;
    }
    float acc = bin_embed[dlt * EE + tid];

    __shared__ int   s_idx[2048];
    __shared__ float s_val[2048];
    __shared__ int   s_cnt;
    const float4* xr4 = reinterpret_cast<const float4*>(x + (size_t)row * VV);

    for (int c0 = 0; c0 < VV; c0 += 2048) {
        if (tid == 0) s_cnt = 0;
        __syncthreads();
#pragma unroll
        for (int i = 0; i < 4; ++i) {
            int j4 = (c0 >> 2) + i * 128 + tid;
            float4 xv = xr4[j4];
            if (xv.x != 0.f) { int p = atomicAdd(&s_cnt, 1); s_idx[p] = 4*j4+0; s_val[p] = xv.x; }
            if (xv.y != 0.f) { int p = atomicAdd(&s_cnt, 1); s_idx[p] = 4*j4+1; s_val[p] = xv.y; }
            if (xv.z != 0.f) { int p = atomicAdd(&s_cnt, 1); s_idx[p] = 4*j4+2; s_val[p] = xv.z; }
            if (xv.w != 0.f) { int p = atomicAdd(&s_cnt, 1); s_idx[p] = 4*j4+3; s_val[p] = xv.w; }
        }
        __syncthreads();
        int n = s_cnt;
        for (int p = 0; p < n; ++p)
            acc += s_val[p] * d_Wt[(size_t)s_idx[p] * EE + tid];
        __syncthreads();
    }
    d_v[(size_t)row * EE + tid] = acc * m;
}

/* ------------------- generic split-bf16 HMMA GEMM --------------------
   512 thr, 64-row tiles: C[bm:+64, bn:+128] = A @ Wimg[bn:+128]^T
   mode: 0 plain, 1 shift A rows within LL, 2 final-z-update while staging */
__global__ void __launch_bounds__(512, 2)
hmma_gemm(const float* __restrict__ A, const __nv_bfloat16* __restrict__ Wimg,
          int wlo, const float* __restrict__ bias1, const float* __restrict__ bias2,
          float* __restrict__ C, int N, int mode,
          const float* __restrict__ ep, const float* __restrict__ mask,
          float c1, float inva) {
    extern __shared__ char sm[];
    char* sAh = sm;                 /* 64*272 = 17408 */
    char* sAl = sm + 17408;
    char* sWh = sm + 34816;         /* 128*272 = 34816 */
    char* sWl = sm + 69632;
    int tid = threadIdx.x;
    int bm = blockIdx.x * 64, bn = blockIdx.y * 128;

    /* stage W tile (128 rows hi+lo) */
    {
        const float4* srcH = (const float4*)(Wimg + (size_t)bn * KP);
        const float4* srcL = (const float4*)(Wimg + (size_t)wlo + (size_t)bn * KP);
        float4* dh = (float4*)sWh; float4* dl = (float4*)sWl;
        for (int i = tid; i < 2176; i += 512) { dh[i] = srcH[i]; dl[i] = srcL[i]; }
    }
    /* stage A tile 64 rows (fp32 -> hi/lo bf16) */
    {
        int r = tid >> 3, seg = tid & 7;
        int g = bm + r;
        bool zr = (mode == 1) && ((g & (LL - 1)) == 0);
        const float* arow = A + (size_t)((mode == 1) ? (g > 0 ? g - 1 : 0) : g) * EE;
        float m = (mode == 2) ? mask[g] : 0.f;
#pragma unroll
        for (int k4 = 0; k4 < 4; ++k4) {
            int c = seg * 16 + k4 * 4;
            float4 f = zr ? make_float4(0.f, 0.f, 0.f, 0.f)
                          : *(const float4*)(arow + c);
            if (mode == 2) {
                float4 e = *(const float4*)(ep + (size_t)g * EE + c);
                f.x = (f.x - c1 * e.x) * inva * m;
                f.y = (f.y - c1 * e.y) * inva * m;
                f.z = (f.z - c1 * e.z) * inva * m;
                f.w = (f.w - c1 * e.w) * inva * m;
            }
            uint2 s01 = split2(f.x, f.y), s23 = split2(f.z, f.w);
            *(u32*)(sAh + r * ROWB + c * 2)     = s01.x;
            *(u32*)(sAl + r * ROWB + c * 2)     = s01.y;
            *(u32*)(sAh + r * ROWB + c * 2 + 4) = s23.x;
            *(u32*)(sAl + r * ROWB + c * 2 + 4) = s23.y;
        }
    }
    __syncthreads();

    int lane = tid & 31, w = tid >> 5;          /* 16 warps */
    int m0 = (w & 3) * 16, n0 = (w >> 2) * 32;  /* m4 x n4 warp grid */
    int gr = lane >> 2, gc = lane & 3;
    float acc[4][4];
#pragma unroll
    for (int j = 0; j < 4; ++j)
#pragma unroll
        for (int q = 0; q < 4; ++q) acc[j][q] = 0.f;

    /* ldmatrix lane-address offsets */
    u32 aAh = smem_u32(sAh), aAl = smem_u32(sAl);
    u32 aWh = smem_u32(sWh), aWl = smem_u32(sWl);
    u32 aoffA = (u32)((m0 + (lane & 15)) * ROWB + ((lane >> 4) & 1) * 16);
    u32 boff0 = (u32)((n0 + (lane & 7) + ((lane >> 4) & 1) * 8) * ROWB
                      + ((lane >> 3) & 1) * 16);
    u32 boff1 = boff0 + 16 * ROWB;

#pragma unroll
    for (int k0 = 0; k0 < 128; k0 += 16) {
        u32 kb = (u32)(k0 * 2);
        u32 ah[4], al[4], bh0[4], bl0[4], bh1[4], bl1[4];
        LDSM_X4(ah, aAh + aoffA + kb);
        LDSM_X4(al, aAl + aoffA + kb);
        LDSM_X4(bh0, aWh + boff0 + kb);
        LDSM_X4(bl0, aWl + boff0 + kb);
        LDSM_X4(bh1, aWh + boff1 + kb);
        LDSM_X4(bl1, aWl + boff1 + kb);
        MMA(acc[0], ah, bh0 + 0); MMA(acc[0], ah, bl0 + 0); MMA(acc[0], al, bh0 + 0);
        MMA(acc[1], ah, bh0 + 2); MMA(acc[1], ah, bl0 + 2); MMA(acc[1], al, bh0 + 2);
        MMA(acc[2], ah, bh1 + 0); MMA(acc[2], ah, bl1 + 0); MMA(acc[2], al, bh1 + 0);
        MMA(acc[3], ah, bh1 + 2); MMA(acc[3], ah, bl1 + 2); MMA(acc[3], al, bh1 + 2);
    }

#pragma unroll
    for (int nt = 0; nt < 4; ++nt) {
        int col = n0 + nt * 8 + gc * 2;
        float b0 = 0.f, b1 = 0.f;
        if (bias1) {
            b0 = bias1[bn + col] + bias2[bn + col];
            b1 = bias1[bn + col + 1] + bias2[bn + col + 1];
        }
        int r0 = bm + m0 + gr;
        *(float2*)&C[(size_t)r0 * N + bn + col] = make_float2(acc[nt][0] + b0, acc[nt][1] + b1);
        *(float2*)&C[(size_t)(r0 + 8) * N + bn + col] = make_float2(acc[nt][2] + b0, acc[nt][3] + b1);
    }
}

/* ------------ fused diffusion step: gate + MLP (+loss) ---------------
   512 thr, 32-row tiles, grid RR/32=256.
   mode 0 = loss path;  1 = first sampling step;  2 = sampling step     */
__global__ void __launch_bounds__(512, 2)
fused_step(const float* __restrict__ zsrc, const float* __restrict__ noise,
           const float* __restrict__ eps, const int* __restrict__ tdiff,
           const float* __restrict__ mask, const float* __restrict__ Wf,
           const float* __restrict__ bf, const float* __restrict__ be2,
           ABCoef cf, float c1, float inva, float sbeta, int kk, int mode) {
    extern __shared__ char sm[];
    char* sAh = sm;                  /* 32*272 = 8704 */
    char* sAl = sm + 8704;
    char* sWh = sm + 17408;          /* 128*272 = 34816, reused W1 then W2 */
    char* sWl = sm + 52224;
    int*   s_t = (int*)(sm + 87040);     /* 32 */
    float* s_m = (float*)(sm + 87168);   /* 32 */
    __shared__ float s_lred[16];

    int tid = threadIdx.x;
    int bm = blockIdx.x * 32;
    int lane = tid & 31, w = tid >> 5;   /* 16 warps */

    /* stage W1 hi/lo */
    {
        const float4* w1h = (const float4*)d_we1_img;
        const float4* w1l = (const float4*)(d_we1_img + 128 * KP);
        float4* dh = (float4*)sWh; float4* dl = (float4*)sWl;
        for (int i = tid; i < 2176; i += 512) { dh[i] = w1h[i]; dl[i] = w1l[i]; }
    }

    float bf0 = bf[0], bf1 = bf[1];
    float4 w0q = *(const float4*)&Wf[lane * 4];
    float4 w1q = *(const float4*)&Wf[128 + lane * 4];
    float4 w2q = *(const float4*)&Wf[256 + lane * 4];
    float4 w3q = *(const float4*)&Wf[384 + lane * 4];

    /* phase A: gate per row (2 rows/warp), store g hi/lo into A tiles */
#pragma unroll
    for (int i = 0; i < 2; ++i) {
        int r = w * 2 + i;
        int grow = bm + r;
        float m = mask[grow];
        size_t base = (size_t)grow * EE + lane * 4;
        float4 hq = *(const float4*)&d_hp[base];
        float4 zq;
        int t;
        if (mode == 0) {
            t = (m > 0.f) ? tdiff[grow >> 6] : 1;
            float ab = cf.ab[t - 1];
            float sa = sqrtf(ab) * m, sb = sqrtf(1.f - ab) * m;
            float4 vq = *(const float4*)&d_v[base];
            float4 eq = *(const float4*)&eps[base];
            zq.x = sa * vq.x + sb * eq.x;
            zq.y = sa * vq.y + sb * eq.y;
            zq.z = sa * vq.z + sb * eq.z;
            zq.w = sa * vq.w + sb * eq.w;
        } else {
            t = (m > 0.f) ? kk : 1;
            zq = *(const float4*)&zsrc[base];
            if (mode == 2) {
                float4 e = *(const float4*)&d_ep[base];
                float4 nz = *(const float4*)&noise[base];
                zq.x = ((zq.x - c1 * e.x) * inva + sbeta * nz.x) * m;
                zq.y = ((zq.y - c1 * e.y) * inva + sbeta * nz.y) * m;
                zq.z = ((zq.z - c1 * e.z) * inva + sbeta * nz.z) * m;
                zq.w = ((zq.w - c1 * e.w) * inva + sbeta * nz.w) * m;
                *(float4*)&d_z[base] = zq;
            }
        }
        float p0 = zq.x*w0q.x + zq.y*w0q.y + zq.z*w0q.z + zq.w*w0q.w
                 + hq.x*w1q.x + hq.y*w1q.y + hq.z*w1q.z + hq.w*w1q.w;
        float p1 = zq.x*w2q.x + zq.y*w2q.y + zq.z*w2q.z + zq.w*w2q.w
                 + hq.x*w3q.x + hq.y*w3q.y + hq.z*w3q.z + hq.w*w3q.w;
#pragma unroll
        for (int o = 16; o > 0; o >>= 1) {
            p0 += __shfl_xor_sync(0xffffffffu, p0, o);
            p1 += __shfl_xor_sync(0xffffffffu, p1, o);
        }
        float a0 = 1.f / (1.f + expf((p1 + bf1) - (p0 + bf0)));
        float gx = a0 * zq.x + (1.f - a0) * hq.x;
        float gy = a0 * zq.y + (1.f - a0) * hq.y;
        float gz = a0 * zq.z + (1.f - a0) * hq.z;
        float gw = a0 * zq.w + (1.f - a0) * hq.w;
        uint2 s01 = split2(gx, gy), s23 = split2(gz, gw);
        *(u32*)(sAh + r * ROWB + lane * 8)     = s01.x;
        *(u32*)(sAl + r * ROWB + lane * 8)     = s01.y;
        *(u32*)(sAh + r * ROWB + lane * 8 + 4) = s23.x;
        *(u32*)(sAl + r * ROWB + lane * 8 + 4) = s23.y;
        if (lane == 0) { s_t[r] = t; s_m[r] = m; }
    }
    __syncthreads();

    int m0 = (w & 1) * 16, n0 = (w >> 1) * 16;   /* m2 x n8 warp grid */
    int gr = lane >> 2, gc = lane & 3;
    float acc[2][4];
#pragma unroll
    for (int j = 0; j < 2; ++j)
#pragma unroll
        for (int q = 0; q < 4; ++q) acc[j][q] = 0.f;

    u32 aAh = smem_u32(sAh), aAl = smem_u32(sAl);
    u32 aWh = smem_u32(sWh), aWl = smem_u32(sWl);
    u32 aoffA = (u32)((m0 + (lane & 15)) * ROWB + ((lane >> 4) & 1) * 16);
    u32 boff = (u32)((n0 + (lane & 7) + ((lane >> 4) & 1) * 8) * ROWB
                     + ((lane >> 3) & 1) * 16);

    /* gemm1: ff1 = g @ We1a^T */
#pragma unroll
    for (int k0 = 0; k0 < 128; k0 += 16) {
        u32 kb = (u32)(k0 * 2);
        u32 ah[4], al[4], bh[4], bl[4];
        LDSM_X4(ah, aAh + aoffA + kb);
        LDSM_X4(al, aAl + aoffA + kb);
        LDSM_X4(bh, aWh + boff + kb);
        LDSM_X4(bl, aWl + boff + kb);
        MMA(acc[0], ah, bh + 0); MMA(acc[0], ah, bl + 0); MMA(acc[0], al, bh + 0);
        MMA(acc[1], ah, bh + 2); MMA(acc[1], ah, bl + 2); MMA(acc[1], al, bh + 2);
    }
    __syncthreads();

    /* epilogue1: relu(acc + TT[t]) restaged into A tiles; stage W2 */
#pragma unroll
    for (int nt = 0; nt < 2; ++nt) {
        int col = n0 + nt * 8 + gc * 2;
        int r0 = m0 + gr, r1 = m0 + 8 + gr;
        int t0 = s_t[r0], t1 = s_t[r1];
        float f00 = fmaxf(acc[nt][0] + d_TT[t0 * EE + col], 0.f);
        float f01 = fmaxf(acc[nt][1] + d_TT[t0 * EE + col + 1], 0.f);
        float f10 = fmaxf(acc[nt][2] + d_TT[t1 * EE + col], 0.f);
        float f11 = fmaxf(acc[nt][3] + d_TT[t1 * EE + col + 1], 0.f);
        uint2 u0 = split2(f00, f01), u1 = split2(f10, f11);
        *(u32*)(sAh + r0 * ROWB + col * 2) = u0.x;
        *(u32*)(sAl + r0 * ROWB + col * 2) = u0.y;
        *(u32*)(sAh + r1 * ROWB + col * 2) = u1.x;
        *(u32*)(sAl + r1 * ROWB + col * 2) = u1.y;
        acc[nt][0] = acc[nt][1] = acc[nt][2] = acc[nt][3] = 0.f;
    }
    {
        const float4* w2h = (const float4*)d_we2_img;
        const float4* w2l = (const float4*)(d_we2_img + 128 * KP);
        float4* dh = (float4*)sWh; float4* dl = (float4*)sWl;
        for (int i = tid; i < 2176; i += 512) { dh[i] = w2h[i]; dl[i] = w2l[i]; }
    }
    __syncthreads();

    /* gemm2: ep = ff1 @ We2^T + be2 */
#pragma unroll
    for (int k0 = 0; k0 < 128; k0 += 16) {
        u32 kb = (u32)(k0 * 2);
        u32 ah[4], al[4], bh[4], bl[4];
        LDSM_X4(ah, aAh + aoffA + kb);
        LDSM_X4(al, aAl + aoffA + kb);
        LDSM_X4(bh, aWh + boff + kb);
        LDSM_X4(bl, aWl + boff + kb);
        MMA(acc[0], ah, bh + 0); MMA(acc[0], ah, bl + 0); MMA(acc[0], al, bh + 0);
        MMA(acc[1], ah, bh + 2); MMA(acc[1], ah, bl + 2); MMA(acc[1], al, bh + 2);
    }

    float lsum = 0.f;
#pragma unroll
    for (int nt = 0; nt < 2; ++nt) {
        int col = n0 + nt * 8 + gc * 2;
        int r0 = m0 + gr, r1 = m0 + 8 + gr;
        float b0 = be2[col], b1 = be2[col + 1];
        float o00 = acc[nt][0] + b0, o01 = acc[nt][1] + b1;
        float o10 = acc[nt][2] + b0, o11 = acc[nt][3] + b1;
        if (mode == 0) {
            float2 e0 = *(const float2*)&eps[(size_t)(bm + r0) * EE + col];
            float2 e1 = *(const float2*)&eps[(size_t)(bm + r1) * EE + col];
            float dx = o00 - e0.x, dy = o01 - e0.y;
            float dz = o10 - e1.x, dw = o11 - e1.y;
            lsum += (dx * dx + dy * dy) * s_m[r0] + (dz * dz + dw * dw) * s_m[r1];
        } else {
            *(float2*)&d_ep[(size_t)(bm + r0) * EE + col] = make_float2(o00, o01);
            *(float2*)&d_ep[(size_t)(bm + r1) * EE + col] = make_float2(o10, o11);
        }
    }
    if (mode == 0) {
#pragma unroll
        for (int o = 16; o > 0; o >>= 1) lsum += __shfl_xor_sync(0xffffffffu, lsum, o);
        if (lane == 0) s_lred[w] = lsum;
        __syncthreads();
        if (tid == 0) {
            float s = 0.f;
            for (int i = 0; i < 16; ++i) s += s_lred[i];
            atomicAdd(&d_scal[1], s);
        }
    }
}

/* ------------------------------ LSTM (4 batches/block) --------------- */
__device__ __forceinline__ void fma2(ull& c, ull a, ull b) {
    asm("fma.rn.f32x2 %0, %1, %2, %0;" : "+l"(c) : "l"(a), "l"(b));
}
union F4U { float4 f; ull u[2]; };

__global__ void __launch_bounds__(512)
lstm_kernel(const float* __restrict__ xg, const float* __restrict__ mask,
            float* __restrict__ hout) {
    int j = threadIdx.x;
    int b0 = blockIdx.x * 4;
    __shared__ __align__(16) float h_sh[4][HH];
    __shared__ float c_sh[4][HH];
    __shared__ float g_sh[4][G4];
    {
        int bb = j >> 7, ii = j & 127;
        h_sh[bb][ii] = 0.f; c_sh[bb][ii] = 0.f;
    }
    __syncthreads();
    const float4* wq4 = (const float4*)d_Wq;   /* [e4*512 + j] */

    for (int l = 0; l < LL; ++l) {
        ull g2[4] = {0ull, 0ull, 0ull, 0ull};
#pragma unroll 8
        for (int e4 = 0; e4 < 32; ++e4) {
            F4U wv; wv.f = wq4[e4 * G4 + j];
#pragma unroll
            for (int bb = 0; bb < 4; ++bb) {
                F4U hv; hv.f = *(const float4*)&h_sh[bb][e4 * 4];
                fma2(g2[bb], wv.u[0], hv.u[0]);
                fma2(g2[bb], wv.u[1], hv.u[1]);
            }
        }
#pragma unroll
        for (int bb = 0; bb < 4; ++bb) {
            F2U u; u.u = g2[bb];
            g_sh[bb][j] = u.f.x + u.f.y + xg[((size_t)(b0 + bb) * LL + l) * G4 + j];
        }
        __syncthreads();
        {
            int bb = j >> 7, idx = j & 127;
            float gi = g_sh[bb][idx];
            float gf = g_sh[bb][128 + idx];
            float gg = g_sh[bb][256 + idx];
            float go = g_sh[bb][384 + idx];
            float c = sigm(gf) * c_sh[bb][idx] + sigm(gi) * tanhf(gg);
            float h = sigm(go) * tanhf(c);
            c_sh[bb][idx] = c;
            h_sh[bb][idx] = h;
            int row = (b0 + bb) * LL + l;
            hout[(size_t)row * HH + idx] = h * mask[row];
        }
        __syncthreads();
    }
}

/* ------------------------------ logits ------------------------------- */
__global__ void __launch_bounds__(128)
logits_kernel(const float* __restrict__ h, const float* __restrict__ Wcls,
              const float* __restrict__ bcls, float* __restrict__ out) {
    int b = blockIdx.x, tid = threadIdx.x;
    int l = d_len[b] - 1;
    float p = h[((size_t)b * LL + l) * HH + tid] * Wcls[tid];
    __shared__ float red[128];
    red[tid] = p;
    __syncthreads();
    for (int o = 64; o > 0; o >>= 1) { if (tid < o) red[tid] += red[tid + o]; __syncthreads(); }
    if (tid == 0) out[b] = red[0] + bcls[0];
}

__global__ void __launch_bounds__(1)
final_kernel(float* __restrict__ out) {
    out[256] = d_scal[1] / d_scal[0];
}

/* ============================== host ================================= */
extern "C" void kernel_launch(void* const* d_in, const int* in_sizes, int n_in,
                              void* d_out, int out_size) {
    const float* padded_x   = (const float*)d_in[0];
    const float* visit_mask = (const float*)d_in[1];
    const int*   padded_bins= (const int*)  d_in[2];
    const int*   t_diff     = (const int*)  d_in[3];
    const float* eps        = (const float*)d_in[4];
    const float* z0         = (const float*)d_in[5];
    const float* noise      = (const float*)d_in[6];
    const float* W_visit    = (const float*)d_in[7];
    const float* bin_embed  = (const float*)d_in[8];
    const float* W_ih       = (const float*)d_in[9];
    const float* W_hh       = (const float*)d_in[10];
    const float* b_ih       = (const float*)d_in[11];
    const float* b_hh       = (const float*)d_in[12];
    const float* W_cls      = (const float*)d_in[13];
    const float* b_cls      = (const float*)d_in[14];
    const float* W_proj     = (const float*)d_in[15];
    const float* time_embed = (const float*)d_in[16];
    const float* W_fuse     = (const float*)d_in[17];
    const float* b_fuse     = (const float*)d_in[18];
    const float* W_e1       = (const float*)d_in[19];
    const float* b_e1       = (const float*)d_in[20];
    const float* W_e2       = (const float*)d_in[21];
    const float* b_e2       = (const float*)d_in[22];
    float* out = (float*)d_out;
    (void)in_sizes; (void)n_in; (void)out_size;

    float *v, *xg, *h, *hp, *z, *ep, *hsyn;
    __nv_bfloat16 *wih_img, *wproj_img;
    cudaGetSymbolAddress((void**)&v,    d_v);
    cudaGetSymbolAddress((void**)&xg,   d_xg);
    cudaGetSymbolAddress((void**)&h,    d_h);
    cudaGetSymbolAddress((void**)&hp,   d_hp);
    cudaGetSymbolAddress((void**)&z,    d_z);
    cudaGetSymbolAddress((void**)&ep,   d_ep);
    cudaGetSymbolAddress((void**)&hsyn, d_hsyn);
    cudaGetSymbolAddress((void**)&wih_img,   d_wih_img);
    cudaGetSymbolAddress((void**)&wproj_img, d_wproj_img);

    static int attr_done = 0;
    if (!attr_done) {
        cudaFuncSetAttribute(hmma_gemm,  cudaFuncAttributeMaxDynamicSharedMemorySize, 104448);
        cudaFuncSetAttribute(fused_step, cudaFuncAttributeMaxDynamicSharedMemorySize, 89344);
        attr_done = 1;
    }

    /* diffusion schedule (host, fp64) */
    double betas[NSTEPS], alphas[NSTEPS], abars[NSTEPS];
    double prod = 1.0;
    for (int i = 0; i < NSTEPS; ++i) {
        betas[i] = 1e-4 + (double)i * (2e-2 - 1e-4) / (double)(NSTEPS - 1);
        alphas[i] = 1.0 - betas[i];
        prod *= alphas[i];
        abars[i] = prod;
    }
    ABCoef cf;
    for (int i = 0; i < NSTEPS; ++i) cf.ab[i] = (float)abars[i];

    /* bias_sum = b_ih + b_hh folded into gemm epilogue (bias1+bias2) */

    /* ---- pipeline (idx 3 = big hmma_gemm → profiled) ---- */
    transpose_kernel<<<dim3(VV / 32, EE / 32), dim3(32, 8)>>>(W_visit);            /* 0 */
    wconv_kernel<<<1024, 128>>>(W_ih, W_proj, W_e1, W_e2, W_hh);                   /* 1 */
    compute_v_kernel<<<RR, 128>>>(padded_x, padded_bins, visit_mask, bin_embed);   /* 2 */
    hmma_gemm<<<dim3(RR / 64, 4), 512, 104448>>>(v, wih_img, 512 * KP,
                b_ih, b_hh, xg, G4, 0, 0, 0, 0.f, 0.f);                            /* 3 */
    lstm_kernel<<<BB / 4, 512>>>(xg, visit_mask, h);                               /* 4 */

    tt_kernel<<<NSTEPS + 1, 128>>>(time_embed, W_e1, b_e1);
    prep_kernel<<<1, 128>>>(visit_mask);
    logits_kernel<<<BB, 128>>>(h, W_cls, b_cls, out);

    /* hp = shift(h) @ W_proj^T */
    hmma_gemm<<<dim3(RR / 64, 1), 512, 104448>>>(h, wproj_img, 128 * KP,
                0, 0, hp, EE, 1, 0, 0, 0.f, 0.f);

    /* diffusion loss path (mode 0) */
    fused_step<<<RR / 32, 512, 89344>>>(z0, noise, eps, t_diff, visit_mask,
                                        W_fuse, b_fuse, b_e2, cf,
                                        0.f, 1.f, 0.f, 0, 0);

    /* reverse diffusion sampling */
    for (int kk = NSTEPS; kk >= 1; --kk) {
        int s = kk + 1;   /* pending update from the previous iteration's step */
        float c1 = 0.f, inva = 1.f, sb = 0.f;
        const float* zsrc = z0;
        const float* np = noise;
        int mode = 1;
        if (kk < NSTEPS) {
            mode = 2;
            c1   = (float)(betas[s - 1] / sqrt(1.0 - abars[s - 1]));
            inva = (float)(1.0 / sqrt(alphas[s - 1]));
            sb   = (float)sqrt(betas[s - 1]);
            np   = noise + (size_t)(NSTEPS - s) * RR * EE;
            zsrc = (s == NSTEPS) ? z0 : z;
        }
        fused_step<<<RR / 32, 512, 89344>>>(zsrc, np, eps, t_diff, visit_mask,
                                            W_fuse, b_fuse, b_e2, cf,
                                            c1, inva, sb, kk, mode);
    }

    /* encoder LSTM on synthetic data; final z update fused into staging */
    {
        float c1   = (float)(betas[0] / sqrt(1.0 - abars[0]));
        float inva = (float)(1.0 / sqrt(alphas[0]));
        hmma_gemm<<<dim3(RR / 64, 4), 512, 104448>>>(z, wih_img, 512 * KP,
                    b_ih, b_hh, xg, G4, 2, ep, visit_mask, c1, inva);
    }
    lstm_kernel<<<BB / 4, 512>>>(xg, visit_mask, hsyn);
    logits_kernel<<<BB, 128>>>(hsyn, W_cls, b_cls, out + 128);

    final_kernel<<<1, 1>>>(out);
}

// round 9
// speedup vs baseline: 2.1770x; 1.0209x over previous
#include <cuda_runtime.h>
#include <cuda_bf16.h>
#include <math.h>
#include <stdint.h>

#define BB 128
#define LL 64
#define VV 8192
#define EE 128
#define HH 128
#define RR (BB*LL)     /* 8192 rows */
#define G4 512
#define NSTEPS 10
#define MAXBIN 512
#define KP 136         /* padded K stride in bf16 elems */
#define ROWB 272       /* KP*2 bytes per tile row */

typedef unsigned long long ull;
typedef unsigned int u32;

/* ------------------------------ scratch ------------------------------ */
__device__ float d_Wt[VV*EE];          /* W_visit transposed [V][E] */
__device__ float d_Wq[G4*HH];          /* W_hh packed: [e4][j] float4 */
__device__ float d_v[RR*EE];
__device__ float d_xg[RR*G4];
__device__ float d_h[RR*HH];
__device__ float d_hp[RR*EE];
__device__ float d_z[RR*EE];
__device__ float d_ep[RR*EE];
__device__ float d_hsyn[RR*HH];
__device__ float d_TT[(NSTEPS+1)*EE];  /* temb@W_e1b^T + b_e1 per t */
__device__ int   d_len[BB];
__device__ float d_scal[2];            /* [0]=denom, [1]=loss accum */
__device__ unsigned g_arrive;          /* grid barrier counter */

/* bf16 hi/lo padded weight images: [hi plane Nrows*KP][lo plane Nrows*KP] */
__device__ __nv_bfloat16 d_wih_img[2*512*KP];
__device__ __nv_bfloat16 d_wproj_img[2*128*KP];
__device__ __nv_bfloat16 d_we1_img[2*128*KP];
__device__ __nv_bfloat16 d_we2_img[2*128*KP];

struct StepCoef {
    float ab[NSTEPS];
    float c1[NSTEPS + 1];    /* indexed by s (step whose update is pending) */
    float inva[NSTEPS + 1];
    float sb[NSTEPS + 1];
};

__device__ __forceinline__ float sigm(float x) { return 1.f / (1.f + expf(-x)); }
union F2U { ull u; float2 f; };

__device__ __forceinline__ u32 smem_u32(const void* p) {
    u32 a;
    asm("{ .reg .u64 t; cvta.to.shared.u64 t, %1; cvt.u32.u64 %0, t; }" : "=r"(a) : "l"(p));
    return a;
}

/* split pair of fp32 into (hi bf16x2, lo bf16x2) register images */
__device__ __forceinline__ uint2 split2(float x, float y) {
    __nv_bfloat162 h = __floats2bfloat162_rn(x, y);
    float2 hf = __bfloat1622float2(h);
    __nv_bfloat162 l = __floats2bfloat162_rn(x - hf.x, y - hf.y);
    uint2 r;
    r.x = *(u32*)&h;
    r.y = *(u32*)&l;
    return r;
}

#define MMA(c, a, b) \
    asm volatile("mma.sync.aligned.m16n8k16.row.col.f32.bf16.bf16.f32 " \
        "{%0,%1,%2,%3},{%4,%5,%6,%7},{%8,%9},{%0,%1,%2,%3};" \
        : "+f"((c)[0]), "+f"((c)[1]), "+f"((c)[2]), "+f"((c)[3]) \
        : "r"((a)[0]), "r"((a)[1]), "r"((a)[2]), "r"((a)[3]), "r"((b)[0]), "r"((b)[1]))

#define LDSM_X4(R, ADDR) \
    asm volatile("ldmatrix.sync.aligned.m8n8.x4.shared.b16 {%0,%1,%2,%3}, [%4];" \
        : "=r"((R)[0]), "=r"((R)[1]), "=r"((R)[2]), "=r"((R)[3]) : "r"(ADDR))

/* ------------------------- W_visit transpose ------------------------- */
__global__ void __launch_bounds__(256)
transpose_kernel(const float* __restrict__ W) {
    __shared__ float t[32][33];
    int j0 = blockIdx.x * 32, e0 = blockIdx.y * 32;
    for (int i = threadIdx.y; i < 32; i += 8)
        t[i][threadIdx.x] = W[(size_t)(e0 + i) * VV + j0 + threadIdx.x];
    __syncthreads();
    for (int i = threadIdx.y; i < 32; i += 8)
        d_Wt[(size_t)(j0 + i) * EE + e0 + threadIdx.x] = t[threadIdx.x][i];
}

/* ---- weight prep: bf16 hi/lo images + W_hh pack (merged kernel) ----- */
__global__ void __launch_bounds__(128)
wconv_kernel(const float* __restrict__ Wih, const float* __restrict__ Wproj,
             const float* __restrict__ We1, const float* __restrict__ We2,
             const float* __restrict__ Whh) {
    int rb = blockIdx.x, k = threadIdx.x;
    if (rb >= 896) {
        int idx = (rb - 896) * 128 + k;
        int e4 = idx >> 9, j = idx & 511;
#pragma unroll
        for (int c = 0; c < 4; ++c)
            d_Wq[(e4 * G4 + j) * 4 + c] = Whh[(size_t)j * HH + e4 * 4 + c];
        return;
    }
    const float* src; int nrow, nrows; __nv_bfloat16* img; int ld = 128;
    if (rb < 512)      { src = Wih;  nrow = rb;       nrows = 512; img = d_wih_img; }
    else if (rb < 640) { src = Wproj; nrow = rb - 512; nrows = 128; img = d_wproj_img; }
    else if (rb < 768) { src = We1;  nrow = rb - 640; nrows = 128; img = d_we1_img; ld = 256; }
    else               { src = We2;  nrow = rb - 768; nrows = 128; img = d_we2_img; }
    float a = src[(size_t)nrow * ld + k];
    __nv_bfloat16 hi = __float2bfloat16(a);
    __nv_bfloat16 lo = __float2bfloat16(a - __bfloat162float(hi));
    img[(size_t)nrow * KP + k] = hi;
    img[(size_t)nrows * KP + (size_t)nrow * KP + k] = lo;
}

/* ------------------ TT table precompute (parallel) ------------------- */
__global__ void __launch_bounds__(128)
tt_kernel(const float* __restrict__ temb, const float* __restrict__ We1,
          const float* __restrict__ be1) {
    int t = blockIdx.x, j = threadIdx.x;
    const float* tr = temb + t * EE;
    const float* wr = We1 + (size_t)j * (2 * EE) + EE;
    float s = be1[j];
#pragma unroll 16
    for (int k = 0; k < EE; ++k) s += tr[k] * wr[k];
    d_TT[t * EE + j] = s;
}

/* --------- lengths, denom, loss reset, grid-barrier reset ------------ */
__global__ void __launch_bounds__(128)
prep_kernel(const float* __restrict__ mask) {
    int b = threadIdx.x;
    float s = 0.f;
    for (int l = 0; l < LL; ++l) s += mask[b * LL + l];
    int len = (int)(s + 0.5f);
    if (len < 1) len = 1;
    d_len[b] = len;
    __shared__ float red[128];
    red[b] = s;
    __syncthreads();
    for (int o = 64; o > 0; o >>= 1) { if (b < o) red[b] += red[b + o]; __syncthreads(); }
    if (b == 0) {
        float dn = red[0];
        if (dn < 1.f) dn = 1.f;
        d_scal[0] = dn;
        d_scal[1] = 0.f;
        g_arrive = 0u;
    }
}

/* --------------------- sparse visit embedding (R2 form) -------------- */
__global__ void __launch_bounds__(128)
compute_v_kernel(const float* __restrict__ x,
                 const int* __restrict__ bins,
                 const float* __restrict__ mask,
                 const float* __restrict__ bin_embed) {
    int row = blockIdx.x;
    int tid = threadIdx.x;
    int l = row & (LL - 1);
    float m = mask[row];
    if (m == 0.f) { d_v[(size_t)row * EE + tid] = 0.f; return; }

    int dlt = 0;
    if (l > 0) {
        dlt = bins[row] - bins[row - 1];
        if (dlt < 0) dlt = 0;
        if (dlt > MAXBIN + 1) dlt = MAXBIN + 1;
    }
    float acc = bin_embed[dlt * EE + tid];

    __shared__ int   s_idx[2048];
    __shared__ float s_val[2048];
    __shared__ int   s_cnt;
    const float4* xr4 = reinterpret_cast<const float4*>(x + (size_t)row * VV);

    for (int c0 = 0; c0 < VV; c0 += 2048) {
        if (tid == 0) s_cnt = 0;
        __syncthreads();
#pragma unroll
        for (int i = 0; i < 4; ++i) {
            int j4 = (c0 >> 2) + i * 128 + tid;
            float4 xv = xr4[j4];
            if (xv.x != 0.f) { int p = atomicAdd(&s_cnt, 1); s_idx[p] = 4*j4+0; s_val[p] = xv.x; }
            if (xv.y != 0.f) { int p = atomicAdd(&s_cnt, 1); s_idx[p] = 4*j4+1; s_val[p] = xv.y; }
            if (xv.z != 0.f) { int p = atomicAdd(&s_cnt, 1); s_idx[p] = 4*j4+2; s_val[p] = xv.z; }
            if (xv.w != 0.f) { int p = atomicAdd(&s_cnt, 1); s_idx[p] = 4*j4+3; s_val[p] = xv.w; }
        }
        __syncthreads();
        int n = s_cnt;
        for (int p = 0; p < n; ++p)
            acc += s_val[p] * d_Wt[(size_t)s_idx[p] * EE + tid];
        __syncthreads();
    }
    d_v[(size_t)row * EE + tid] = acc * m;
}

/* ------------------- generic split-bf16 HMMA GEMM --------------------
   512 thr, 64-row tiles: C[bm:+64, bn:+128] = A @ Wimg[bn:+128]^T
   mode: 0 plain, 1 shift A rows within LL, 2 final-z-update while staging */
__global__ void __launch_bounds__(512, 2)
hmma_gemm(const float* __restrict__ A, const __nv_bfloat16* __restrict__ Wimg,
          int wlo, const float* __restrict__ bias1, const float* __restrict__ bias2,
          float* __restrict__ C, int N, int mode,
          const float* __restrict__ ep, const float* __restrict__ mask,
          float c1, float inva) {
    extern __shared__ char sm[];
    char* sAh = sm;                 /* 64*272 = 17408 */
    char* sAl = sm + 17408;
    char* sWh = sm + 34816;         /* 128*272 = 34816 */
    char* sWl = sm + 69632;
    int tid = threadIdx.x;
    int bm = blockIdx.x * 64, bn = blockIdx.y * 128;

    {
        const float4* srcH = (const float4*)(Wimg + (size_t)bn * KP);
        const float4* srcL = (const float4*)(Wimg + (size_t)wlo + (size_t)bn * KP);
        float4* dh = (float4*)sWh; float4* dl = (float4*)sWl;
        for (int i = tid; i < 2176; i += 512) { dh[i] = srcH[i]; dl[i] = srcL[i]; }
    }
    {
        int r = tid >> 3, seg = tid & 7;
        int g = bm + r;
        bool zr = (mode == 1) && ((g & (LL - 1)) == 0);
        const float* arow = A + (size_t)((mode == 1) ? (g > 0 ? g - 1 : 0) : g) * EE;
        float m = (mode == 2) ? mask[g] : 0.f;
#pragma unroll
        for (int k4 = 0; k4 < 4; ++k4) {
            int c = seg * 16 + k4 * 4;
            float4 f = zr ? make_float4(0.f, 0.f, 0.f, 0.f)
                          : *(const float4*)(arow + c);
            if (mode == 2) {
                float4 e = *(const float4*)(ep + (size_t)g * EE + c);
                f.x = (f.x - c1 * e.x) * inva * m;
                f.y = (f.y - c1 * e.y) * inva * m;
                f.z = (f.z - c1 * e.z) * inva * m;
                f.w = (f.w - c1 * e.w) * inva * m;
            }
            uint2 s01 = split2(f.x, f.y), s23 = split2(f.z, f.w);
            *(u32*)(sAh + r * ROWB + c * 2)     = s01.x;
            *(u32*)(sAl + r * ROWB + c * 2)     = s01.y;
            *(u32*)(sAh + r * ROWB + c * 2 + 4) = s23.x;
            *(u32*)(sAl + r * ROWB + c * 2 + 4) = s23.y;
        }
    }
    __syncthreads();

    int lane = tid & 31, w = tid >> 5;          /* 16 warps */
    int m0 = (w & 3) * 16, n0 = (w >> 2) * 32;
    int gr = lane >> 2, gc = lane & 3;
    float acc[4][4];
#pragma unroll
    for (int j = 0; j < 4; ++j)
#pragma unroll
        for (int q = 0; q < 4; ++q) acc[j][q] = 0.f;

    u32 aAh = smem_u32(sAh), aAl = smem_u32(sAl);
    u32 aWh = smem_u32(sWh), aWl = smem_u32(sWl);
    u32 aoffA = (u32)((m0 + (lane & 15)) * ROWB + ((lane >> 4) & 1) * 16);
    u32 boff0 = (u32)((n0 + (lane & 7) + ((lane >> 4) & 1) * 8) * ROWB
                      + ((lane >> 3) & 1) * 16);
    u32 boff1 = boff0 + 16 * ROWB;

#pragma unroll
    for (int k0 = 0; k0 < 128; k0 += 16) {
        u32 kb = (u32)(k0 * 2);
        u32 ah[4], al[4], bh0[4], bl0[4], bh1[4], bl1[4];
        LDSM_X4(ah, aAh + aoffA + kb);
        LDSM_X4(al, aAl + aoffA + kb);
        LDSM_X4(bh0, aWh + boff0 + kb);
        LDSM_X4(bl0, aWl + boff0 + kb);
        LDSM_X4(bh1, aWh + boff1 + kb);
        LDSM_X4(bl1, aWl + boff1 + kb);
        MMA(acc[0], ah, bh0 + 0); MMA(acc[0], ah, bl0 + 0); MMA(acc[0], al, bh0 + 0);
        MMA(acc[1], ah, bh0 + 2); MMA(acc[1], ah, bl0 + 2); MMA(acc[1], al, bh0 + 2);
        MMA(acc[2], ah, bh1 + 0); MMA(acc[2], ah, bl1 + 0); MMA(acc[2], al, bh1 + 0);
        MMA(acc[3], ah, bh1 + 2); MMA(acc[3], ah, bl1 + 2); MMA(acc[3], al, bh1 + 2);
    }

#pragma unroll
    for (int nt = 0; nt < 4; ++nt) {
        int col = n0 + nt * 8 + gc * 2;
        float b0 = 0.f, b1 = 0.f;
        if (bias1) {
            b0 = bias1[bn + col] + bias2[bn + col];
            b1 = bias1[bn + col + 1] + bias2[bn + col + 1];
        }
        int r0 = bm + m0 + gr;
        *(float2*)&C[(size_t)r0 * N + bn + col] = make_float2(acc[nt][0] + b0, acc[nt][1] + b1);
        *(float2*)&C[(size_t)(r0 + 8) * N + bn + col] = make_float2(acc[nt][2] + b0, acc[nt][3] + b1);
    }
}

/* -------- persistent diffusion: loss step + 10 sampling steps --------
   grid 128 (co-resident, 1 CTA/SM), 512 thr, 64 rows/CTA.
   W1 & W2 hi/lo staged in smem ONCE; software grid barrier between steps */
__global__ void __launch_bounds__(512, 1)
persist_diff(const float* __restrict__ z0, const float* __restrict__ noise,
             const float* __restrict__ eps, const int* __restrict__ tdiff,
             const float* __restrict__ mask, const float* __restrict__ Wf,
             const float* __restrict__ bf, const float* __restrict__ be2,
             StepCoef sc) {
    extern __shared__ char sm[];
    char* sAh  = sm;                    /* 17408 */
    char* sAl  = sm + 17408;
    char* sW1h = sm + 34816;
    char* sW1l = sm + 69632;
    char* sW2h = sm + 104448;
    char* sW2l = sm + 139264;
    int*   s_t = (int*)(sm + 174080);   /* 64 */
    float* s_m = (float*)(sm + 174336); /* 64 */
    __shared__ float s_lred[16];

    int tid = threadIdx.x, lane = tid & 31, w = tid >> 5;
    int bm = blockIdx.x * 64;

    /* stage all four weight planes once */
    {
        const float4* s1h = (const float4*)d_we1_img;
        const float4* s1l = (const float4*)(d_we1_img + 128 * KP);
        const float4* s2h = (const float4*)d_we2_img;
        const float4* s2l = (const float4*)(d_we2_img + 128 * KP);
        float4* d1h = (float4*)sW1h; float4* d1l = (float4*)sW1l;
        float4* d2h = (float4*)sW2h; float4* d2l = (float4*)sW2l;
        for (int i = tid; i < 2176; i += 512) {
            d1h[i] = s1h[i]; d1l[i] = s1l[i];
            d2h[i] = s2h[i]; d2l[i] = s2l[i];
        }
    }

    float bf0 = bf[0], bf1 = bf[1];
    float4 w0q = *(const float4*)&Wf[lane * 4];
    float4 w1q = *(const float4*)&Wf[128 + lane * 4];
    float4 w2q = *(const float4*)&Wf[256 + lane * 4];
    float4 w3q = *(const float4*)&Wf[384 + lane * 4];

    int m0 = (w & 3) * 16, n0 = (w >> 2) * 32;
    int gr = lane >> 2, gc = lane & 3;
    u32 aAh = smem_u32(sAh), aAl = smem_u32(sAl);
    u32 aW1h = smem_u32(sW1h), aW1l = smem_u32(sW1l);
    u32 aW2h = smem_u32(sW2h), aW2l = smem_u32(sW2l);
    u32 aoffA = (u32)((m0 + (lane & 15)) * ROWB + ((lane >> 4) & 1) * 16);
    u32 boff0 = (u32)((n0 + (lane & 7) + ((lane >> 4) & 1) * 8) * ROWB
                      + ((lane >> 3) & 1) * 16);
    u32 boff1 = boff0 + 16 * ROWB;

    for (int step = 0; step <= NSTEPS; ++step) {
        int kk = NSTEPS - (step - 1);     /* valid for step>=1: 10..1 */

        /* ---- gate phase: 4 rows/warp ---- */
#pragma unroll 1
        for (int i = 0; i < 4; ++i) {
            int r = w * 4 + i;
            int grow = bm + r;
            float m = mask[grow];
            size_t base = (size_t)grow * EE + lane * 4;
            float4 hq = *(const float4*)&d_hp[base];
            float4 zq;
            int t;
            if (step == 0) {
                t = (m > 0.f) ? tdiff[grow >> 6] : 1;
                float ab = sc.ab[t - 1];
                float sa = sqrtf(ab) * m, sb2 = sqrtf(1.f - ab) * m;
                float4 vq = *(const float4*)&d_v[base];
                float4 eq = *(const float4*)&eps[base];
                zq.x = sa * vq.x + sb2 * eq.x;
                zq.y = sa * vq.y + sb2 * eq.y;
                zq.z = sa * vq.z + sb2 * eq.z;
                zq.w = sa * vq.w + sb2 * eq.w;
            } else if (step == 1) {
                t = (m > 0.f) ? kk : 1;
                zq = *(const float4*)&z0[base];
            } else {
                t = (m > 0.f) ? kk : 1;
                int s = kk + 1;                     /* 10..2 */
                const float* zs = (s == NSTEPS) ? z0 : d_z;
                zq = *(const float4*)&zs[base];
                float4 e = *(const float4*)&d_ep[base];
                const float* np = noise + (size_t)(NSTEPS - s) * RR * EE;
                float4 nz = *(const float4*)&np[base];
                float c1 = sc.c1[s], inva = sc.inva[s], sb2 = sc.sb[s];
                zq.x = ((zq.x - c1 * e.x) * inva + sb2 * nz.x) * m;
                zq.y = ((zq.y - c1 * e.y) * inva + sb2 * nz.y) * m;
                zq.z = ((zq.z - c1 * e.z) * inva + sb2 * nz.z) * m;
                zq.w = ((zq.w - c1 * e.w) * inva + sb2 * nz.w) * m;
                *(float4*)&d_z[base] = zq;
            }
            float p0 = zq.x*w0q.x + zq.y*w0q.y + zq.z*w0q.z + zq.w*w0q.w
                     + hq.x*w1q.x + hq.y*w1q.y + hq.z*w1q.z + hq.w*w1q.w;
            float p1 = zq.x*w2q.x + zq.y*w2q.y + zq.z*w2q.z + zq.w*w2q.w
                     + hq.x*w3q.x + hq.y*w3q.y + hq.z*w3q.z + hq.w*w3q.w;
#pragma unroll
            for (int o = 16; o > 0; o >>= 1) {
                p0 += __shfl_xor_sync(0xffffffffu, p0, o);
                p1 += __shfl_xor_sync(0xffffffffu, p1, o);
            }
            float a0 = 1.f / (1.f + expf((p1 + bf1) - (p0 + bf0)));
            float gx = a0 * zq.x + (1.f - a0) * hq.x;
            float gy = a0 * zq.y + (1.f - a0) * hq.y;
            float gz = a0 * zq.z + (1.f - a0) * hq.z;
            float gw = a0 * zq.w + (1.f - a0) * hq.w;
            uint2 s01 = split2(gx, gy), s23 = split2(gz, gw);
            *(u32*)(sAh + r * ROWB + lane * 8)     = s01.x;
            *(u32*)(sAl + r * ROWB + lane * 8)     = s01.y;
            *(u32*)(sAh + r * ROWB + lane * 8 + 4) = s23.x;
            *(u32*)(sAl + r * ROWB + lane * 8 + 4) = s23.y;
            if (lane == 0) { s_t[r] = t; s_m[r] = m; }
        }
        __syncthreads();

        float acc[4][4];
#pragma unroll
        for (int j = 0; j < 4; ++j)
#pragma unroll
            for (int q = 0; q < 4; ++q) acc[j][q] = 0.f;

        /* gemm1: g @ We1a^T */
#pragma unroll
        for (int k0 = 0; k0 < 128; k0 += 16) {
            u32 kb = (u32)(k0 * 2);
            u32 ah[4], al[4], bh0[4], bl0[4], bh1[4], bl1[4];
            LDSM_X4(ah, aAh + aoffA + kb);
            LDSM_X4(al, aAl + aoffA + kb);
            LDSM_X4(bh0, aW1h + boff0 + kb);
            LDSM_X4(bl0, aW1l + boff0 + kb);
            LDSM_X4(bh1, aW1h + boff1 + kb);
            LDSM_X4(bl1, aW1l + boff1 + kb);
            MMA(acc[0], ah, bh0 + 0); MMA(acc[0], ah, bl0 + 0); MMA(acc[0], al, bh0 + 0);
            MMA(acc[1], ah, bh0 + 2); MMA(acc[1], ah, bl0 + 2); MMA(acc[1], al, bh0 + 2);
            MMA(acc[2], ah, bh1 + 0); MMA(acc[2], ah, bl1 + 0); MMA(acc[2], al, bh1 + 0);
            MMA(acc[3], ah, bh1 + 2); MMA(acc[3], ah, bl1 + 2); MMA(acc[3], al, bh1 + 2);
        }
        __syncthreads();

        /* epilogue1: relu(acc + TT[t]) restaged into A tiles */
#pragma unroll
        for (int nt = 0; nt < 4; ++nt) {
            int col = n0 + nt * 8 + gc * 2;
            int r0 = m0 + gr, r1 = m0 + 8 + gr;
            int t0 = s_t[r0], t1 = s_t[r1];
            float f00 = fmaxf(acc[nt][0] + d_TT[t0 * EE + col], 0.f);
            float f01 = fmaxf(acc[nt][1] + d_TT[t0 * EE + col + 1], 0.f);
            float f10 = fmaxf(acc[nt][2] + d_TT[t1 * EE + col], 0.f);
            float f11 = fmaxf(acc[nt][3] + d_TT[t1 * EE + col + 1], 0.f);
            uint2 u0 = split2(f00, f01), u1 = split2(f10, f11);
            *(u32*)(sAh + r0 * ROWB + col * 2) = u0.x;
            *(u32*)(sAl + r0 * ROWB + col * 2) = u0.y;
            *(u32*)(sAh + r1 * ROWB + col * 2) = u1.x;
            *(u32*)(sAl + r1 * ROWB + col * 2) = u1.y;
            acc[nt][0] = acc[nt][1] = acc[nt][2] = acc[nt][3] = 0.f;
        }
        __syncthreads();

        /* gemm2: ff1 @ We2^T */
#pragma unroll
        for (int k0 = 0; k0 < 128; k0 += 16) {
            u32 kb = (u32)(k0 * 2);
            u32 ah[4], al[4], bh0[4], bl0[4], bh1[4], bl1[4];
            LDSM_X4(ah, aAh + aoffA + kb);
            LDSM_X4(al, aAl + aoffA + kb);
            LDSM_X4(bh0, aW2h + boff0 + kb);
            LDSM_X4(bl0, aW2l + boff0 + kb);
            LDSM_X4(bh1, aW2h + boff1 + kb);
            LDSM_X4(bl1, aW2l + boff1 + kb);
            MMA(acc[0], ah, bh0 + 0); MMA(acc[0], ah, bl0 + 0); MMA(acc[0], al, bh0 + 0);
            MMA(acc[1], ah, bh0 + 2); MMA(acc[1], ah, bl0 + 2); MMA(acc[1], al, bh0 + 2);
            MMA(acc[2], ah, bh1 + 0); MMA(acc[2], ah, bl1 + 0); MMA(acc[2], al, bh1 + 0);
            MMA(acc[3], ah, bh1 + 2); MMA(acc[3], ah, bl1 + 2); MMA(acc[3], al, bh1 + 2);
        }

        float lsum = 0.f;
#pragma unroll
        for (int nt = 0; nt < 4; ++nt) {
            int col = n0 + nt * 8 + gc * 2;
            int r0 = m0 + gr, r1 = m0 + 8 + gr;
            float b0 = be2[col], b1 = be2[col + 1];
            float o00 = acc[nt][0] + b0, o01 = acc[nt][1] + b1;
            float o10 = acc[nt][2] + b0, o11 = acc[nt][3] + b1;
            if (step == 0) {
                float2 e0 = *(const float2*)&eps[(size_t)(bm + r0) * EE + col];
                float2 e1 = *(const float2*)&eps[(size_t)(bm + r1) * EE + col];
                float dx = o00 - e0.x, dy = o01 - e0.y;
                float dz = o10 - e1.x, dw = o11 - e1.y;
                lsum += (dx * dx + dy * dy) * s_m[r0] + (dz * dz + dw * dw) * s_m[r1];
            } else {
                *(float2*)&d_ep[(size_t)(bm + r0) * EE + col] = make_float2(o00, o01);
                *(float2*)&d_ep[(size_t)(bm + r1) * EE + col] = make_float2(o10, o11);
            }
        }
        if (step == 0) {
#pragma unroll
            for (int o = 16; o > 0; o >>= 1) lsum += __shfl_xor_sync(0xffffffffu, lsum, o);
            if (lane == 0) s_lred[w] = lsum;
            __syncthreads();
            if (tid == 0) {
                float s = 0.f;
                for (int i = 0; i < 16; ++i) s += s_lred[i];
                atomicAdd(&d_scal[1], s);
            }
        }

        /* ---- grid barrier (not needed after last step) ---- */
        if (step < NSTEPS) {
            __threadfence();
            __syncthreads();
            if (tid == 0) {
                atomicAdd(&g_arrive, 1u);
                unsigned bound = (unsigned)(step + 1) * gridDim.x;
                while (atomicAdd(&g_arrive, 0u) < bound) {}
            }
            __syncthreads();
            __threadfence();
        }
    }
}

/* ------------------------------ LSTM (4 batches/block) --------------- */
__device__ __forceinline__ void fma2(ull& c, ull a, ull b) {
    asm("fma.rn.f32x2 %0, %1, %2, %0;" : "+l"(c) : "l"(a), "l"(b));
}
union F4U { float4 f; ull u[2]; };

__global__ void __launch_bounds__(512)
lstm_kernel(const float* __restrict__ xg, const float* __restrict__ mask,
            float* __restrict__ hout) {
    int j = threadIdx.x;
    int b0 = blockIdx.x * 4;
    __shared__ __align__(16) float h_sh[4][HH];
    __shared__ float c_sh[4][HH];
    __shared__ float g_sh[4][G4];
    {
        int bb = j >> 7, ii = j & 127;
        h_sh[bb][ii] = 0.f; c_sh[bb][ii] = 0.f;
    }
    __syncthreads();
    const float4* wq4 = (const float4*)d_Wq;

    for (int l = 0; l < LL; ++l) {
        ull g2[4] = {0ull, 0ull, 0ull, 0ull};
#pragma unroll 8
        for (int e4 = 0; e4 < 32; ++e4) {
            F4U wv; wv.f = wq4[e4 * G4 + j];
#pragma unroll
            for (int bb = 0; bb < 4; ++bb) {
                F4U hv; hv.f = *(const float4*)&h_sh[bb][e4 * 4];
                fma2(g2[bb], wv.u[0], hv.u[0]);
                fma2(g2[bb], wv.u[1], hv.u[1]);
            }
        }
#pragma unroll
        for (int bb = 0; bb < 4; ++bb) {
            F2U u; u.u = g2[bb];
            g_sh[bb][j] = u.f.x + u.f.y + xg[((size_t)(b0 + bb) * LL + l) * G4 + j];
        }
        __syncthreads();
        {
            int bb = j >> 7, idx = j & 127;
            float gi = g_sh[bb][idx];
            float gf = g_sh[bb][128 + idx];
            float gg = g_sh[bb][256 + idx];
            float go = g_sh[bb][384 + idx];
            float c = sigm(gf) * c_sh[bb][idx] + sigm(gi) * tanhf(gg);
            float h = sigm(go) * tanhf(c);
            c_sh[bb][idx] = c;
            h_sh[bb][idx] = h;
            int row = (b0 + bb) * LL + l;
            hout[(size_t)row * HH + idx] = h * mask[row];
        }
        __syncthreads();
    }
}

/* ------------------------------ logits ------------------------------- */
__global__ void __launch_bounds__(128)
logits_kernel(const float* __restrict__ h, const float* __restrict__ Wcls,
              const float* __restrict__ bcls, float* __restrict__ out) {
    int b = blockIdx.x, tid = threadIdx.x;
    int l = d_len[b] - 1;
    float p = h[((size_t)b * LL + l) * HH + tid] * Wcls[tid];
    __shared__ float red[128];
    red[tid] = p;
    __syncthreads();
    for (int o = 64; o > 0; o >>= 1) { if (tid < o) red[tid] += red[tid + o]; __syncthreads(); }
    if (tid == 0) out[b] = red[0] + bcls[0];
}

__global__ void __launch_bounds__(1)
final_kernel(float* __restrict__ out) {
    out[256] = d_scal[1] / d_scal[0];
}

/* ============================== host ================================= */
extern "C" void kernel_launch(void* const* d_in, const int* in_sizes, int n_in,
                              void* d_out, int out_size) {
    const float* padded_x   = (const float*)d_in[0];
    const float* visit_mask = (const float*)d_in[1];
    const int*   padded_bins= (const int*)  d_in[2];
    const int*   t_diff     = (const int*)  d_in[3];
    const float* eps        = (const float*)d_in[4];
    const float* z0         = (const float*)d_in[5];
    const float* noise      = (const float*)d_in[6];
    const float* W_visit    = (const float*)d_in[7];
    const float* bin_embed  = (const float*)d_in[8];
    const float* W_ih       = (const float*)d_in[9];
    const float* W_hh       = (const float*)d_in[10];
    const float* b_ih       = (const float*)d_in[11];
    const float* b_hh       = (const float*)d_in[12];
    const float* W_cls      = (const float*)d_in[13];
    const float* b_cls      = (const float*)d_in[14];
    const float* W_proj     = (const float*)d_in[15];
    const float* time_embed = (const float*)d_in[16];
    const float* W_fuse     = (const float*)d_in[17];
    const float* b_fuse     = (const float*)d_in[18];
    const float* W_e1       = (const float*)d_in[19];
    const float* b_e1       = (const float*)d_in[20];
    const float* W_e2       = (const float*)d_in[21];
    const float* b_e2       = (const float*)d_in[22];
    float* out = (float*)d_out;
    (void)in_sizes; (void)n_in; (void)out_size;

    float *v, *xg, *h, *hp, *z, *ep, *hsyn;
    __nv_bfloat16 *wih_img, *wproj_img;
    cudaGetSymbolAddress((void**)&v,    d_v);
    cudaGetSymbolAddress((void**)&xg,   d_xg);
    cudaGetSymbolAddress((void**)&h,    d_h);
    cudaGetSymbolAddress((void**)&hp,   d_hp);
    cudaGetSymbolAddress((void**)&z,    d_z);
    cudaGetSymbolAddress((void**)&ep,   d_ep);
    cudaGetSymbolAddress((void**)&hsyn, d_hsyn);
    cudaGetSymbolAddress((void**)&wih_img,   d_wih_img);
    cudaGetSymbolAddress((void**)&wproj_img, d_wproj_img);

    static int attr_done = 0;
    if (!attr_done) {
        cudaFuncSetAttribute(hmma_gemm,    cudaFuncAttributeMaxDynamicSharedMemorySize, 104448);
        cudaFuncSetAttribute(persist_diff, cudaFuncAttributeMaxDynamicSharedMemorySize, 174848);
        attr_done = 1;
    }

    /* diffusion schedule (host, fp64) */
    double betas[NSTEPS], alphas[NSTEPS], abars[NSTEPS];
    double prod = 1.0;
    for (int i = 0; i < NSTEPS; ++i) {
        betas[i] = 1e-4 + (double)i * (2e-2 - 1e-4) / (double)(NSTEPS - 1);
        alphas[i] = 1.0 - betas[i];
        prod *= alphas[i];
        abars[i] = prod;
    }
    StepCoef sc;
    for (int i = 0; i < NSTEPS; ++i) sc.ab[i] = (float)abars[i];
    for (int s = 1; s <= NSTEPS; ++s) {
        sc.c1[s]   = (float)(betas[s - 1] / sqrt(1.0 - abars[s - 1]));
        sc.inva[s] = (float)(1.0 / sqrt(alphas[s - 1]));
        sc.sb[s]   = (float)sqrt(betas[s - 1]);
    }
    sc.c1[0] = sc.inva[0] = sc.sb[0] = 0.f;

    /* ---- pipeline ---- */
    transpose_kernel<<<dim3(VV / 32, EE / 32), dim3(32, 8)>>>(W_visit);            /* 0 */
    wconv_kernel<<<1024, 128>>>(W_ih, W_proj, W_e1, W_e2, W_hh);                   /* 1 */
    compute_v_kernel<<<RR, 128>>>(padded_x, padded_bins, visit_mask, bin_embed);   /* 2 */
    hmma_gemm<<<dim3(RR / 64, 4), 512, 104448>>>(v, wih_img, 512 * KP,
                b_ih, b_hh, xg, G4, 0, 0, 0, 0.f, 0.f);                            /* 3 */
    lstm_kernel<<<BB / 4, 512>>>(xg, visit_mask, h);                               /* 4 */

    tt_kernel<<<NSTEPS + 1, 128>>>(time_embed, W_e1, b_e1);
    prep_kernel<<<1, 128>>>(visit_mask);
    logits_kernel<<<BB, 128>>>(h, W_cls, b_cls, out);

    /* hp = shift(h) @ W_proj^T */
    hmma_gemm<<<dim3(RR / 64, 1), 512, 104448>>>(h, wproj_img, 128 * KP,
                0, 0, hp, EE, 1, 0, 0, 0.f, 0.f);

    /* all 11 diffusion steps in one persistent kernel */
    persist_diff<<<RR / 64, 512, 174848>>>(z0, noise, eps, t_diff, visit_mask,
                                           W_fuse, b_fuse, b_e2, sc);

    /* encoder LSTM on synthetic data; final z update fused into staging */
    {
        float c1   = (float)(betas[0] / sqrt(1.0 - abars[0]));
        float inva = (float)(1.0 / sqrt(alphas[0]));
        hmma_gemm<<<dim3(RR / 64, 4), 512, 104448>>>(z, wih_img, 512 * KP,
                    b_ih, b_hh, xg, G4, 2, ep, visit_mask, c1, inva);
    }
    lstm_kernel<<<BB / 4, 512>>>(xg, visit_mask, hsyn);
    logits_kernel<<<BB, 128>>>(hsyn, W_cls, b_cls, out + 128);

    final_kernel<<<1, 1>>>(out);
}